// round 2
// baseline (speedup 1.0000x reference)
#include <cuda_runtime.h>
#include <cstdint>
#include <cstdio>

#define NN 100000
#define NE 1600000

// ---------------- scratch (static device allocations, sanctioned) ----------
__device__ int   g_is64;
__device__ int   g_esrc[NE];
__device__ int   g_edst[NE];
__device__ int   g_cnt[NN];
__device__ int   g_off[NN];
__device__ int   g_cur[NN];
__device__ int   g_src[NE];
__device__ float g_bufA[(size_t)NN * 256];  // y1 -> y2 -> u
__device__ float g_bufB[(size_t)NN * 256];  // r1 -> r2 -> v
__device__ float g_h[(size_t)NN * 256];
__device__ float g_z[(size_t)NN * 128];

// ---------------- edge index dtype detection + normalization ----------------
// If buffer is int64 (values < 1e5, non-negative), every odd int32 word is 0.
// If buffer is int32, odd words are edge indices (all-zero over 1024 samples
// has negligible probability). Deterministic given the input.
__global__ void k_detect(const int* __restrict__ p) {
    if (threadIdx.x == 0 && blockIdx.x == 0) {
        int odd_nonzero = 0;
        for (int i = 0; i < 1024; i++) {
            if (p[2 * i + 1] != 0) { odd_nonzero = 1; break; }
        }
        g_is64 = odd_nonzero ? 0 : 1;
    }
}

__global__ void k_cvt(const void* __restrict__ ei) {
    int e = blockIdx.x * blockDim.x + threadIdx.x;
    if (e >= NE) return;
    if (g_is64) {
        const long long* p = (const long long*)ei;
        g_esrc[e] = (int)p[e];
        g_edst[e] = (int)p[NE + e];
    } else {
        const int* p = (const int*)ei;
        g_esrc[e] = p[e];
        g_edst[e] = p[NE + e];
    }
}

// ---------------- CSR build ------------------------------------------------
__global__ void k_zero_cnt() {
    int i = blockIdx.x * blockDim.x + threadIdx.x;
    if (i < NN) g_cnt[i] = 0;
}

__global__ void k_hist() {
    int e = blockIdx.x * blockDim.x + threadIdx.x;
    if (e < NE) atomicAdd(&g_cnt[g_edst[e]], 1);
}

// single-block exclusive scan over g_cnt -> g_off, g_cur
__global__ void k_scan() {
    __shared__ int s[1024];
    const int t = threadIdx.x;
    const int CH = (NN + 1023) / 1024;  // 98
    int base = t * CH;
    int sum = 0;
    for (int i = 0; i < CH; i++) {
        int idx = base + i;
        if (idx < NN) sum += g_cnt[idx];
    }
    s[t] = sum;
    __syncthreads();
    for (int off = 1; off < 1024; off <<= 1) {
        int v = 0;
        if (t >= off) v = s[t - off];
        __syncthreads();
        s[t] += v;
        __syncthreads();
    }
    int run = s[t] - sum;  // exclusive base for this thread's chunk
    for (int i = 0; i < CH; i++) {
        int idx = base + i;
        if (idx < NN) {
            g_off[idx] = run;
            g_cur[idx] = run;
            run += g_cnt[idx];
        }
    }
}

__global__ void k_scatter() {
    int e = blockIdx.x * blockDim.x + threadIdx.x;
    if (e < NE) {
        int pos = atomicAdd(&g_cur[g_edst[e]], 1);
        g_src[pos] = g_esrc[e];
    }
}

// ---------------- SGEMM: C[M,Nn] = A[M,K] @ W[Nn,K(ldw)]^T ------------------
// 128x128 tile, 256 threads, 8x8 register tile, BK=16. K % 16 == 0, Nn % 128 == 0.
__global__ void __launch_bounds__(256)
k_gemm_nt(const float* __restrict__ A, const float* __restrict__ W,
          float* __restrict__ C, int M, int Nn, int K, int ldw) {
    __shared__ float As[16][128];
    __shared__ float Ws[16][128];
    const int bm = blockIdx.y * 128;
    const int bn = blockIdx.x * 128;
    const int tid = threadIdx.x;
    const int tm = (tid / 16) * 8;
    const int tn = (tid % 16) * 8;

    float acc[8][8];
#pragma unroll
    for (int i = 0; i < 8; i++)
#pragma unroll
        for (int j = 0; j < 8; j++) acc[i][j] = 0.f;

    for (int k0 = 0; k0 < K; k0 += 16) {
#pragma unroll
        for (int r = 0; r < 2; r++) {
            int idx = tid + r * 256;      // float4 id 0..511
            int row = idx >> 2;           // 0..127
            int kk4 = (idx & 3) << 2;     // 0,4,8,12
            float4 va = make_float4(0.f, 0.f, 0.f, 0.f);
            int grow = bm + row;
            if (grow < M)
                va = *reinterpret_cast<const float4*>(&A[(size_t)grow * K + k0 + kk4]);
            As[kk4 + 0][row] = va.x;
            As[kk4 + 1][row] = va.y;
            As[kk4 + 2][row] = va.z;
            As[kk4 + 3][row] = va.w;

            float4 vw = *reinterpret_cast<const float4*>(&W[(size_t)(bn + row) * ldw + k0 + kk4]);
            Ws[kk4 + 0][row] = vw.x;
            Ws[kk4 + 1][row] = vw.y;
            Ws[kk4 + 2][row] = vw.z;
            Ws[kk4 + 3][row] = vw.w;
        }
        __syncthreads();
#pragma unroll
        for (int kk = 0; kk < 16; kk++) {
            float4 a0 = *reinterpret_cast<const float4*>(&As[kk][tm]);
            float4 a1 = *reinterpret_cast<const float4*>(&As[kk][tm + 4]);
            float4 b0 = *reinterpret_cast<const float4*>(&Ws[kk][tn]);
            float4 b1 = *reinterpret_cast<const float4*>(&Ws[kk][tn + 4]);
            float a[8] = {a0.x, a0.y, a0.z, a0.w, a1.x, a1.y, a1.z, a1.w};
            float b[8] = {b0.x, b0.y, b0.z, b0.w, b1.x, b1.y, b1.z, b1.w};
#pragma unroll
            for (int i = 0; i < 8; i++)
#pragma unroll
                for (int j = 0; j < 8; j++) acc[i][j] = fmaf(a[i], b[j], acc[i][j]);
        }
        __syncthreads();
    }
#pragma unroll
    for (int i = 0; i < 8; i++) {
        int gr = bm + tm + i;
        if (gr < M) {
            float4* cp = reinterpret_cast<float4*>(&C[(size_t)gr * Nn + bn + tn]);
            cp[0] = make_float4(acc[i][0], acc[i][1], acc[i][2], acc[i][3]);
            cp[1] = make_float4(acc[i][4], acc[i][5], acc[i][6], acc[i][7]);
        }
    }
}

// ---------------- aggregation + epilogue ------------------------------------
// out[n] = (sum_{s in nbr(n)} y[s]) / max(cnt,1) + bias + r[n]   (opt relu)
// one warp per node; FV = float4s per lane (F = FV*128)
template <int FV, bool RELU>
__global__ void k_agg(const float* __restrict__ y, const float* __restrict__ r,
                      const float* __restrict__ bias, float* __restrict__ outp) {
    int warp = (blockIdx.x * blockDim.x + threadIdx.x) >> 5;
    int lane = threadIdx.x & 31;
    if (warp >= NN) return;
    const int n = warp;
    const int F = FV * 128;
    int beg = g_off[n];
    int c = g_cnt[n];

    float4 acc[FV];
#pragma unroll
    for (int v = 0; v < FV; v++) acc[v] = make_float4(0.f, 0.f, 0.f, 0.f);

    for (int i = 0; i < c; i++) {
        int s = g_src[beg + i];
        const float4* row = reinterpret_cast<const float4*>(&y[(size_t)s * F]);
#pragma unroll
        for (int v = 0; v < FV; v++) {
            float4 t = row[v * 32 + lane];
            acc[v].x += t.x; acc[v].y += t.y; acc[v].z += t.z; acc[v].w += t.w;
        }
    }
    float inv = 1.f / (float)(c > 0 ? c : 1);
    const float4* rrow = reinterpret_cast<const float4*>(&r[(size_t)n * F]);
    const float4* brow = reinterpret_cast<const float4*>(bias);
    float4* orow = reinterpret_cast<float4*>(&outp[(size_t)n * F]);
#pragma unroll
    for (int v = 0; v < FV; v++) {
        float4 rr = rrow[v * 32 + lane];
        float4 bb = brow[v * 32 + lane];
        float4 o;
        o.x = acc[v].x * inv + bb.x + rr.x;
        o.y = acc[v].y * inv + bb.y + rr.y;
        o.z = acc[v].z * inv + bb.z + rr.z;
        o.w = acc[v].w * inv + bb.w + rr.w;
        if (RELU) {
            o.x = fmaxf(o.x, 0.f); o.y = fmaxf(o.y, 0.f);
            o.z = fmaxf(o.z, 0.f); o.w = fmaxf(o.w, 0.f);
        }
        orow[v * 32 + lane] = o;
    }
}

// ---------------- edge decoder ----------------------------------------------
// out[e] = Wd2 . relu(u[src] + v[dst] + bd1) + bd2 ; one warp per edge (strided)
__global__ void k_edge(const float* __restrict__ u_, const float* __restrict__ v_,
                       const float* __restrict__ bd1, const float* __restrict__ wd2,
                       const float* __restrict__ bd2, float* __restrict__ out) {
    int gw = (blockIdx.x * blockDim.x + threadIdx.x) >> 5;
    int lane = threadIdx.x & 31;
    int nw = (gridDim.x * blockDim.x) >> 5;
    float4 b = reinterpret_cast<const float4*>(bd1)[lane];
    float4 w = reinterpret_cast<const float4*>(wd2)[lane];
    float b2 = *bd2;
    for (int e = gw; e < NE; e += nw) {
        int s = g_esrc[e];
        int d = g_edst[e];
        float4 uu = reinterpret_cast<const float4*>(u_ + (size_t)s * 128)[lane];
        float4 vv = reinterpret_cast<const float4*>(v_ + (size_t)d * 128)[lane];
        float t;
        float sum = 0.f;
        t = fmaxf(uu.x + vv.x + b.x, 0.f); sum = fmaf(t, w.x, sum);
        t = fmaxf(uu.y + vv.y + b.y, 0.f); sum = fmaf(t, w.y, sum);
        t = fmaxf(uu.z + vv.z + b.z, 0.f); sum = fmaf(t, w.z, sum);
        t = fmaxf(uu.w + vv.w + b.w, 0.f); sum = fmaf(t, w.w, sum);
#pragma unroll
        for (int off = 16; off > 0; off >>= 1)
            sum += __shfl_xor_sync(0xFFFFFFFFu, sum, off);
        if (lane == 0) out[e] = sum + b2;
    }
}

// ---------------- launch -----------------------------------------------------
extern "C" void kernel_launch(void* const* d_in, const int* in_sizes, int n_in,
                              void* d_out, int out_size) {
    const float* x       = (const float*)d_in[0];
    const void*  ei      = (const void*)d_in[1];
    const float* W1l     = (const float*)d_in[2];
    const float* b1l     = (const float*)d_in[3];
    const float* W1r     = (const float*)d_in[4];
    const float* W2l     = (const float*)d_in[5];
    const float* b2l     = (const float*)d_in[6];
    const float* W2r     = (const float*)d_in[7];
    const float* Wd1     = (const float*)d_in[8];
    const float* bd1     = (const float*)d_in[9];
    const float* Wd2     = (const float*)d_in[10];
    const float* bd2     = (const float*)d_in[11];
    float* out           = (float*)d_out;

    float *bufA, *bufB, *h, *z;
    cudaGetSymbolAddress((void**)&bufA, g_bufA);
    cudaGetSymbolAddress((void**)&bufB, g_bufB);
    cudaGetSymbolAddress((void**)&h, g_h);
    cudaGetSymbolAddress((void**)&z, g_z);

    // dtype probe + edge normalization
    k_detect<<<1, 32>>>((const int*)ei);
    k_cvt<<<(NE + 255) / 256, 256>>>(ei);

    // CSR build
    k_zero_cnt<<<(NN + 255) / 256, 256>>>();
    k_hist<<<(NE + 255) / 256, 256>>>();
    k_scan<<<1, 1024>>>();
    k_scatter<<<(NE + 255) / 256, 256>>>();

    dim3 g256(256 / 128, (NN + 127) / 128);  // Nn = 256
    dim3 g128(128 / 128, (NN + 127) / 128);  // Nn = 128

    // conv1: y1 = x@W1l^T, r1 = x@W1r^T, h = relu(agg(y1)/cnt + b1l + r1)
    k_gemm_nt<<<g256, 256>>>(x, W1l, bufA, NN, 256, 256, 256);
    k_gemm_nt<<<g256, 256>>>(x, W1r, bufB, NN, 256, 256, 256);
    k_agg<2, true><<<(NN * 32 + 255) / 256, 256>>>(bufA, bufB, b1l, h);

    // conv2: y2 = h@W2l^T, r2 = h@W2r^T, z = agg(y2)/cnt + b2l + r2
    k_gemm_nt<<<g128, 256>>>(h, W2l, bufA, NN, 128, 256, 256);
    k_gemm_nt<<<g128, 256>>>(h, W2r, bufB, NN, 128, 256, 256);
    k_agg<1, false><<<(NN * 32 + 255) / 256, 256>>>(bufA, bufB, b2l, z);

    // decoder precompute: u = z@A^T, v = z@B^T  (Wd1 = [A | B], ldw = 256)
    k_gemm_nt<<<g128, 256>>>(z, Wd1, bufA, NN, 128, 128, 256);
    k_gemm_nt<<<g128, 256>>>(z, Wd1 + 128, bufB, NN, 128, 128, 256);

    // per-edge: out = Wd2 . relu(u[src]+v[dst]+bd1) + bd2
    k_edge<<<16384, 256>>>(bufA, bufB, bd1, Wd2, bd2, out);
}

// round 4
// speedup vs baseline: 1.5997x; 1.5997x over previous
#include <cuda_runtime.h>
#include <cstdint>
#include <cstdio>

#define NN 100000
#define NE 1600000

// ---------------- scratch ----------------------------------------------------
__device__ int   g_is64;
__device__ int   g_esrc[NE];
__device__ int   g_edst[NE];
__device__ int   g_cnt[NN];
__device__ int   g_off[NN];
__device__ int   g_cur[NN];
__device__ int   g_src[NE];
__device__ float g_bufA[(size_t)NN * 256];  // y1 -> y2 -> u
__device__ float g_bufB[(size_t)NN * 256];  // r1 -> r2 -> v
__device__ float g_h[(size_t)NN * 256];
__device__ float g_z[(size_t)NN * 128];

// ---------------- helpers ----------------------------------------------------
__device__ __forceinline__ uint32_t f2tf(float f) {
    uint32_t u;
    asm("cvt.rna.tf32.f32 %0, %1;" : "=r"(u) : "f"(f));
    return u;
}

__device__ __forceinline__ void mma_tf32(float4& c, uint2 a02, uint2 a13, uint2 b) {
    // {a0,a1,a2,a3} = {col kk+tig row r, row r+8 col kk+tig, col kk+tig+4 row r, row r+8 col kk+tig+4}
    asm volatile(
        "mma.sync.aligned.m16n8k8.row.col.f32.tf32.tf32.f32 "
        "{%0,%1,%2,%3}, {%4,%5,%6,%7}, {%8,%9}, {%0,%1,%2,%3};"
        : "+f"(c.x), "+f"(c.y), "+f"(c.z), "+f"(c.w)
        : "r"(a02.x), "r"(a13.x), "r"(a02.y), "r"(a13.y), "r"(b.x), "r"(b.y));
}

// interleave position of column k within its 8-wide group:
// p = (k & ~7) + 2*(k & 3) + ((k >> 2) & 1)  -> pairs (k, k+4) adjacent
__device__ __forceinline__ int ipos(int k) {
    return (k & ~7) + 2 * (k & 3) + ((k >> 2) & 1);
}

// ---------------- edge index dtype detection + normalization ----------------
__global__ void k_detect(const int* __restrict__ p) {
    if (threadIdx.x == 0 && blockIdx.x == 0) {
        int odd_nonzero = 0;
        for (int i = 0; i < 1024; i++) {
            if (p[2 * i + 1] != 0) { odd_nonzero = 1; break; }
        }
        g_is64 = odd_nonzero ? 0 : 1;
    }
}

__global__ void k_cvt(const void* __restrict__ ei) {
    int e = blockIdx.x * blockDim.x + threadIdx.x;
    if (e >= NE) return;
    if (g_is64) {
        const long long* p = (const long long*)ei;
        g_esrc[e] = (int)p[e];
        g_edst[e] = (int)p[NE + e];
    } else {
        const int* p = (const int*)ei;
        g_esrc[e] = p[e];
        g_edst[e] = p[NE + e];
    }
}

// ---------------- CSR build ------------------------------------------------
__global__ void k_zero_cnt() {
    int i = blockIdx.x * blockDim.x + threadIdx.x;
    if (i < NN) g_cnt[i] = 0;
}

__global__ void k_hist() {
    int e = blockIdx.x * blockDim.x + threadIdx.x;
    if (e < NE) atomicAdd(&g_cnt[g_edst[e]], 1);
}

__global__ void k_scan() {
    __shared__ int s[1024];
    const int t = threadIdx.x;
    const int CH = (NN + 1023) / 1024;
    int base = t * CH;
    int sum = 0;
    for (int i = 0; i < CH; i++) {
        int idx = base + i;
        if (idx < NN) sum += g_cnt[idx];
    }
    s[t] = sum;
    __syncthreads();
    for (int off = 1; off < 1024; off <<= 1) {
        int v = 0;
        if (t >= off) v = s[t - off];
        __syncthreads();
        s[t] += v;
        __syncthreads();
    }
    int run = s[t] - sum;
    for (int i = 0; i < CH; i++) {
        int idx = base + i;
        if (idx < NN) {
            g_off[idx] = run;
            g_cur[idx] = run;
            run += g_cnt[idx];
        }
    }
}

__global__ void k_scatter() {
    int e = blockIdx.x * blockDim.x + threadIdx.x;
    if (e < NE) {
        int pos = atomicAdd(&g_cur[g_edst[e]], 1);
        g_src[pos] = g_esrc[e];
    }
}

// ---------------- fused dual-GEMM via mma.sync tf32 ---------------------------
// Cl[M,NHALF] = A[M,K] @ Wl[NHALF,K(ldw)]^T ; Cr likewise. NTOT = NBLK*128.
// One CTA owns 128 M-rows; A (tf32) resident in SMEM; W streamed in 32-col
// chunks with register-prefetch double buffering. 8 warps = 2(m) x 4(n),
// each warp 64x32 via m16n8k8 tf32 mma.
template <int K, int NBLK>
__global__ void __launch_bounds__(256)
k_gemm_mma(const float* __restrict__ A,
           const float* __restrict__ Wl, const float* __restrict__ Wr, int ldw,
           float* __restrict__ Cl, float* __restrict__ Cr, int M, int NHALF) {
    constexpr int SA = K + 8;       // A row stride (floats)
    constexpr int SW = 40;          // W row stride (floats)
    constexpr int NCHK = K / 32;    // K chunks
    extern __shared__ uint32_t smem[];
    uint32_t* Asm = smem;                        // 128 * SA
    uint32_t* Wsm = smem + 128 * SA;             // 2 * 128 * SW

    const int tid = threadIdx.x;
    const int wid = tid >> 5;
    const int lane = tid & 31;
    const int wm = wid >> 2;        // 0..1 -> m offset wm*64
    const int wn = wid & 3;         // 0..3 -> n offset wn*32
    const int qr = lane >> 2;       // 0..7
    const int tig = lane & 3;       // 0..3
    const int bm = blockIdx.x * 128;

    // ---- load A (128 x K) into SMEM as tf32, interleaved pair layout ----
    for (int fid = tid; fid < 128 * (K / 4); fid += 256) {
        int row = fid / (K / 4);
        int c = fid % (K / 4);
        float4 v = make_float4(0.f, 0.f, 0.f, 0.f);
        if (bm + row < M)
            v = *reinterpret_cast<const float4*>(&A[(size_t)(bm + row) * K + 4 * c]);
        uint32_t* dst = &Asm[row * SA];
        dst[ipos(4 * c + 0)] = f2tf(v.x);
        dst[ipos(4 * c + 1)] = f2tf(v.y);
        dst[ipos(4 * c + 2)] = f2tf(v.z);
        dst[ipos(4 * c + 3)] = f2tf(v.w);
    }
    __syncthreads();

    const int lrow = tid >> 3;      // 0..31? no: W chunk loader row per fid
    (void)lrow;

    for (int nb = 0; nb < NBLK; nb++) {
        const float* Wp;
        int colbase;
        if (nb * 128 < NHALF) { Wp = Wl + (size_t)(nb * 128) * ldw; colbase = nb * 128; }
        else                  { Wp = Wr + (size_t)(nb * 128 - NHALF) * ldw; colbase = nb * 128 - NHALF; }
        float* Cp = (nb * 128 < NHALF) ? Cl : Cr;

        float4 acc[4][4];
#pragma unroll
        for (int i = 0; i < 4; i++)
#pragma unroll
            for (int j = 0; j < 4; j++) acc[i][j] = make_float4(0.f, 0.f, 0.f, 0.f);

        // prefetch chunk 0 into regs, store to buf 0
        float4 wv[4];
#pragma unroll
        for (int r = 0; r < 4; r++) {
            int fid = tid + r * 256;            // 0..1023
            int row = fid >> 3, c4 = fid & 7;
            wv[r] = *reinterpret_cast<const float4*>(&Wp[(size_t)row * ldw + 0 + 4 * c4]);
        }
#pragma unroll
        for (int r = 0; r < 4; r++) {
            int fid = tid + r * 256;
            int row = fid >> 3, c4 = fid & 7;
            uint32_t* dst = &Wsm[row * SW];
            dst[ipos(4 * c4 + 0)] = f2tf(wv[r].x);
            dst[ipos(4 * c4 + 1)] = f2tf(wv[r].y);
            dst[ipos(4 * c4 + 2)] = f2tf(wv[r].z);
            dst[ipos(4 * c4 + 3)] = f2tf(wv[r].w);
        }
        __syncthreads();

        for (int c = 0; c < NCHK; c++) {
            // prefetch next chunk to registers (overlaps compute)
            if (c + 1 < NCHK) {
#pragma unroll
                for (int r = 0; r < 4; r++) {
                    int fid = tid + r * 256;
                    int row = fid >> 3, c4 = fid & 7;
                    wv[r] = *reinterpret_cast<const float4*>(
                        &Wp[(size_t)row * ldw + (c + 1) * 32 + 4 * c4]);
                }
            }

            const uint32_t* Wb = &Wsm[(c & 1) * 128 * SW];
#pragma unroll
            for (int kk = 0; kk < 32; kk += 8) {
                int aoff = c * 32 + kk + 2 * tig;
                uint2 a[4][2];
#pragma unroll
                for (int mt = 0; mt < 4; mt++) {
                    int r0 = wm * 64 + mt * 16 + qr;
                    a[mt][0] = *reinterpret_cast<const uint2*>(&Asm[r0 * SA + aoff]);
                    a[mt][1] = *reinterpret_cast<const uint2*>(&Asm[(r0 + 8) * SA + aoff]);
                }
                uint2 b[4];
#pragma unroll
                for (int nt = 0; nt < 4; nt++) {
                    int n0 = wn * 32 + nt * 8 + qr;
                    b[nt] = *reinterpret_cast<const uint2*>(&Wb[n0 * SW + kk + 2 * tig]);
                }
#pragma unroll
                for (int mt = 0; mt < 4; mt++)
#pragma unroll
                    for (int nt = 0; nt < 4; nt++)
                        mma_tf32(acc[mt][nt], a[mt][0], a[mt][1], b[nt]);
            }

            if (c + 1 < NCHK) {
                uint32_t* Wn = &Wsm[((c + 1) & 1) * 128 * SW];
#pragma unroll
                for (int r = 0; r < 4; r++) {
                    int fid = tid + r * 256;
                    int row = fid >> 3, c4 = fid & 7;
                    uint32_t* dst = &Wn[row * SW];
                    dst[ipos(4 * c4 + 0)] = f2tf(wv[r].x);
                    dst[ipos(4 * c4 + 1)] = f2tf(wv[r].y);
                    dst[ipos(4 * c4 + 2)] = f2tf(wv[r].z);
                    dst[ipos(4 * c4 + 3)] = f2tf(wv[r].w);
                }
            }
            __syncthreads();
        }

        // epilogue: write 128x128 block
#pragma unroll
        for (int mt = 0; mt < 4; mt++) {
            int row = bm + wm * 64 + mt * 16 + qr;
#pragma unroll
            for (int nt = 0; nt < 4; nt++) {
                int col = colbase + wn * 32 + nt * 8 + 2 * tig;
                if (row < M)
                    *reinterpret_cast<float2*>(&Cp[(size_t)row * NHALF + col]) =
                        make_float2(acc[mt][nt].x, acc[mt][nt].y);
                if (row + 8 < M)
                    *reinterpret_cast<float2*>(&Cp[(size_t)(row + 8) * NHALF + col]) =
                        make_float2(acc[mt][nt].z, acc[mt][nt].w);
            }
        }
        __syncthreads();
    }
}

// ---------------- aggregation + epilogue ------------------------------------
template <int FV, bool RELU>
__global__ void k_agg(const float* __restrict__ y, const float* __restrict__ r,
                      const float* __restrict__ bias, float* __restrict__ outp) {
    int warp = (blockIdx.x * blockDim.x + threadIdx.x) >> 5;
    int lane = threadIdx.x & 31;
    if (warp >= NN) return;
    const int n = warp;
    const int F = FV * 128;
    int beg = g_off[n];
    int c = g_cnt[n];

    float4 acc[FV];
#pragma unroll
    for (int v = 0; v < FV; v++) acc[v] = make_float4(0.f, 0.f, 0.f, 0.f);

    for (int i = 0; i < c; i++) {
        int s = g_src[beg + i];
        const float4* row = reinterpret_cast<const float4*>(&y[(size_t)s * F]);
#pragma unroll
        for (int v = 0; v < FV; v++) {
            float4 t = row[v * 32 + lane];
            acc[v].x += t.x; acc[v].y += t.y; acc[v].z += t.z; acc[v].w += t.w;
        }
    }
    float inv = 1.f / (float)(c > 0 ? c : 1);
    const float4* rrow = reinterpret_cast<const float4*>(&r[(size_t)n * F]);
    const float4* brow = reinterpret_cast<const float4*>(bias);
    float4* orow = reinterpret_cast<float4*>(&outp[(size_t)n * F]);
#pragma unroll
    for (int v = 0; v < FV; v++) {
        float4 rr = rrow[v * 32 + lane];
        float4 bb = brow[v * 32 + lane];
        float4 o;
        o.x = acc[v].x * inv + bb.x + rr.x;
        o.y = acc[v].y * inv + bb.y + rr.y;
        o.z = acc[v].z * inv + bb.z + rr.z;
        o.w = acc[v].w * inv + bb.w + rr.w;
        if (RELU) {
            o.x = fmaxf(o.x, 0.f); o.y = fmaxf(o.y, 0.f);
            o.z = fmaxf(o.z, 0.f); o.w = fmaxf(o.w, 0.f);
        }
        orow[v * 32 + lane] = o;
    }
}

// ---------------- edge decoder ----------------------------------------------
__global__ void k_edge(const float* __restrict__ u_, const float* __restrict__ v_,
                       const float* __restrict__ bd1, const float* __restrict__ wd2,
                       const float* __restrict__ bd2, float* __restrict__ out) {
    int gw = (blockIdx.x * blockDim.x + threadIdx.x) >> 5;
    int lane = threadIdx.x & 31;
    int nw = (gridDim.x * blockDim.x) >> 5;
    float4 b = reinterpret_cast<const float4*>(bd1)[lane];
    float4 w = reinterpret_cast<const float4*>(wd2)[lane];
    float b2 = *bd2;
    for (int e = gw; e < NE; e += nw) {
        int s = g_esrc[e];
        int d = g_edst[e];
        float4 uu = reinterpret_cast<const float4*>(u_ + (size_t)s * 128)[lane];
        float4 vv = reinterpret_cast<const float4*>(v_ + (size_t)d * 128)[lane];
        float t;
        float sum = 0.f;
        t = fmaxf(uu.x + vv.x + b.x, 0.f); sum = fmaf(t, w.x, sum);
        t = fmaxf(uu.y + vv.y + b.y, 0.f); sum = fmaf(t, w.y, sum);
        t = fmaxf(uu.z + vv.z + b.z, 0.f); sum = fmaf(t, w.z, sum);
        t = fmaxf(uu.w + vv.w + b.w, 0.f); sum = fmaf(t, w.w, sum);
#pragma unroll
        for (int off = 16; off > 0; off >>= 1)
            sum += __shfl_xor_sync(0xFFFFFFFFu, sum, off);
        if (lane == 0) out[e] = sum + b2;
    }
}

// ---------------- launch -----------------------------------------------------
extern "C" void kernel_launch(void* const* d_in, const int* in_sizes, int n_in,
                              void* d_out, int out_size) {
    const float* x       = (const float*)d_in[0];
    const void*  ei      = (const void*)d_in[1];
    const float* W1l     = (const float*)d_in[2];
    const float* b1l     = (const float*)d_in[3];
    const float* W1r     = (const float*)d_in[4];
    const float* W2l     = (const float*)d_in[5];
    const float* b2l     = (const float*)d_in[6];
    const float* W2r     = (const float*)d_in[7];
    const float* Wd1     = (const float*)d_in[8];
    const float* bd1     = (const float*)d_in[9];
    const float* Wd2     = (const float*)d_in[10];
    const float* bd2     = (const float*)d_in[11];
    float* out           = (float*)d_out;

    float *bufA, *bufB, *h, *z;
    cudaGetSymbolAddress((void**)&bufA, g_bufA);
    cudaGetSymbolAddress((void**)&bufB, g_bufB);
    cudaGetSymbolAddress((void**)&h, g_h);
    cudaGetSymbolAddress((void**)&z, g_z);

    const int smemK256 = (128 * (256 + 8) + 2 * 128 * 40) * 4;  // 176128
    const int smemK128 = (128 * (128 + 8) + 2 * 128 * 40) * 4;  // 110592
    cudaFuncSetAttribute(k_gemm_mma<256, 4>, cudaFuncAttributeMaxDynamicSharedMemorySize, smemK256);
    cudaFuncSetAttribute(k_gemm_mma<256, 2>, cudaFuncAttributeMaxDynamicSharedMemorySize, smemK256);
    cudaFuncSetAttribute(k_gemm_mma<128, 2>, cudaFuncAttributeMaxDynamicSharedMemorySize, smemK128);

    // dtype probe + edge normalization
    k_detect<<<1, 32>>>((const int*)ei);
    k_cvt<<<(NE + 255) / 256, 256>>>(ei);

    // CSR build
    k_zero_cnt<<<(NN + 255) / 256, 256>>>();
    k_hist<<<(NE + 255) / 256, 256>>>();
    k_scan<<<1, 1024>>>();
    k_scatter<<<(NE + 255) / 256, 256>>>();

    const int MT = (NN + 127) / 128;  // 782

    // conv1: y1 = x@W1l^T, r1 = x@W1r^T (fused), h = relu(agg(y1)/cnt + b1l + r1)
    k_gemm_mma<256, 4><<<MT, 256, smemK256>>>(x, W1l, W1r, 256, bufA, bufB, NN, 256);
    k_agg<2, true><<<(NN * 32 + 255) / 256, 256>>>(bufA, bufB, b1l, h);

    // conv2: y2 = h@W2l^T, r2 = h@W2r^T (fused), z = agg(y2)/cnt + b2l + r2
    k_gemm_mma<256, 2><<<MT, 256, smemK256>>>(h, W2l, W2r, 256, bufA, bufB, NN, 128);
    k_agg<1, false><<<(NN * 32 + 255) / 256, 256>>>(bufA, bufB, b2l, z);

    // decoder precompute: u = z@A^T, v = z@B^T (Wd1 = [A | B], ldw = 256)
    k_gemm_mma<128, 2><<<MT, 256, smemK128>>>(z, Wd1, Wd1 + 128, 256, bufA, bufB, NN, 128);

    // per-edge: out = Wd2 . relu(u[src]+v[dst]+bd1) + bd2
    k_edge<<<16384, 256>>>(bufA, bufB, bd1, Wd2, bd2, out);
}

// round 5
// speedup vs baseline: 1.7014x; 1.0636x over previous
#include <cuda_runtime.h>
#include <cstdint>
#include <cstdio>

#define NN 100000
#define NE 1600000

// ---------------- scratch ----------------------------------------------------
__device__ int   g_is64;
__device__ int   g_esrc[NE];
__device__ int   g_edst[NE];
__device__ int   g_cnt[NN];
__device__ int   g_off[NN];
__device__ int   g_cur[NN];
__device__ int   g_src[NE];
__device__ int   g_eid[NE];
__device__ float g_bufA[(size_t)NN * 256];  // y1 -> y2 -> u
__device__ float g_bufB[(size_t)NN * 256];  // r1 -> r2 -> v
__device__ float g_h[(size_t)NN * 256];
__device__ float g_z[(size_t)NN * 128];

// ---------------- helpers ----------------------------------------------------
__device__ __forceinline__ uint32_t f2tf(float f) {
    uint32_t u;
    asm("cvt.rna.tf32.f32 %0, %1;" : "=r"(u) : "f"(f));
    return u;
}

__device__ __forceinline__ void mma_tf32(float4& c, uint2 a02, uint2 a13, uint2 b) {
    asm volatile(
        "mma.sync.aligned.m16n8k8.row.col.f32.tf32.tf32.f32 "
        "{%0,%1,%2,%3}, {%4,%5,%6,%7}, {%8,%9}, {%0,%1,%2,%3};"
        : "+f"(c.x), "+f"(c.y), "+f"(c.z), "+f"(c.w)
        : "r"(a02.x), "r"(a13.x), "r"(a02.y), "r"(a13.y), "r"(b.x), "r"(b.y));
}

// interleave position of column k: pairs (k, k+4) adjacent
__device__ __forceinline__ int ipos(int k) {
    return (k & ~7) + 2 * (k & 3) + ((k >> 2) & 1);
}

// ---------------- edge index dtype detection + normalization ----------------
__global__ void k_detect(const int* __restrict__ p) {
    if (threadIdx.x == 0 && blockIdx.x == 0) {
        int odd_nonzero = 0;
        for (int i = 0; i < 1024; i++) {
            if (p[2 * i + 1] != 0) { odd_nonzero = 1; break; }
        }
        g_is64 = odd_nonzero ? 0 : 1;
    }
}

// convert edge list + histogram in one pass (g_cnt must be pre-zeroed)
__global__ void k_cvt_hist(const void* __restrict__ ei) {
    int e = blockIdx.x * blockDim.x + threadIdx.x;
    if (e >= NE) return;
    int s, d;
    if (g_is64) {
        const long long* p = (const long long*)ei;
        s = (int)p[e];
        d = (int)p[NE + e];
    } else {
        const int* p = (const int*)ei;
        s = p[e];
        d = p[NE + e];
    }
    g_esrc[e] = s;
    g_edst[e] = d;
    atomicAdd(&g_cnt[d], 1);
}

// ---------------- CSR build ------------------------------------------------
__global__ void k_zero_cnt() {
    int i = blockIdx.x * blockDim.x + threadIdx.x;
    if (i < NN) g_cnt[i] = 0;
}

__global__ void k_scan() {
    __shared__ int s[1024];
    const int t = threadIdx.x;
    const int CH = (NN + 1023) / 1024;
    int base = t * CH;
    int sum = 0;
    for (int i = 0; i < CH; i++) {
        int idx = base + i;
        if (idx < NN) sum += g_cnt[idx];
    }
    s[t] = sum;
    __syncthreads();
    for (int off = 1; off < 1024; off <<= 1) {
        int v = 0;
        if (t >= off) v = s[t - off];
        __syncthreads();
        s[t] += v;
        __syncthreads();
    }
    int run = s[t] - sum;
    for (int i = 0; i < CH; i++) {
        int idx = base + i;
        if (idx < NN) {
            g_off[idx] = run;
            g_cur[idx] = run;
            run += g_cnt[idx];
        }
    }
}

__global__ void k_scatter() {
    int e = blockIdx.x * blockDim.x + threadIdx.x;
    if (e < NE) {
        int pos = atomicAdd(&g_cur[g_edst[e]], 1);
        g_src[pos] = g_esrc[e];
        g_eid[pos] = e;
    }
}

// ---------------- fused dual-GEMM via mma.sync tf32 ---------------------------
template <int K, int NBLK>
__global__ void __launch_bounds__(256)
k_gemm_mma(const float* __restrict__ A,
           const float* __restrict__ Wl, const float* __restrict__ Wr, int ldw,
           float* __restrict__ Cl, float* __restrict__ Cr, int M, int NHALF) {
    constexpr int SA = K + 8;       // A row stride (floats)
    constexpr int SW = 40;          // W row stride (floats)
    constexpr int NCHK = K / 32;    // K chunks
    extern __shared__ uint32_t smem[];
    uint32_t* Asm = smem;                        // 128 * SA
    uint32_t* Wsm = smem + 128 * SA;             // 2 * 128 * SW

    const int tid = threadIdx.x;
    const int wid = tid >> 5;
    const int lane = tid & 31;
    const int wm = wid >> 2;        // 0..1 -> m offset wm*64
    const int wn = wid & 3;         // 0..3 -> n offset wn*32
    const int qr = lane >> 2;       // 0..7
    const int tig = lane & 3;       // 0..3
    const int bm = blockIdx.x * 128;

    // ---- load A (128 x K) into SMEM as tf32, interleaved pair layout ----
    for (int fid = tid; fid < 128 * (K / 4); fid += 256) {
        int row = fid / (K / 4);
        int c = fid % (K / 4);
        float4 v = make_float4(0.f, 0.f, 0.f, 0.f);
        if (bm + row < M)
            v = *reinterpret_cast<const float4*>(&A[(size_t)(bm + row) * K + 4 * c]);
        uint32_t* dst = &Asm[row * SA];
        dst[ipos(4 * c + 0)] = f2tf(v.x);
        dst[ipos(4 * c + 1)] = f2tf(v.y);
        dst[ipos(4 * c + 2)] = f2tf(v.z);
        dst[ipos(4 * c + 3)] = f2tf(v.w);
    }
    __syncthreads();

    for (int nb = 0; nb < NBLK; nb++) {
        const float* Wp;
        int colbase;
        if (nb * 128 < NHALF) { Wp = Wl + (size_t)(nb * 128) * ldw; colbase = nb * 128; }
        else                  { Wp = Wr + (size_t)(nb * 128 - NHALF) * ldw; colbase = nb * 128 - NHALF; }
        float* Cp = (nb * 128 < NHALF) ? Cl : Cr;

        float4 acc[4][4];
#pragma unroll
        for (int i = 0; i < 4; i++)
#pragma unroll
            for (int j = 0; j < 4; j++) acc[i][j] = make_float4(0.f, 0.f, 0.f, 0.f);

        float4 wv[4];
#pragma unroll
        for (int r = 0; r < 4; r++) {
            int fid = tid + r * 256;
            int row = fid >> 3, c4 = fid & 7;
            wv[r] = *reinterpret_cast<const float4*>(&Wp[(size_t)row * ldw + 0 + 4 * c4]);
        }
#pragma unroll
        for (int r = 0; r < 4; r++) {
            int fid = tid + r * 256;
            int row = fid >> 3, c4 = fid & 7;
            uint32_t* dst = &Wsm[row * SW];
            dst[ipos(4 * c4 + 0)] = f2tf(wv[r].x);
            dst[ipos(4 * c4 + 1)] = f2tf(wv[r].y);
            dst[ipos(4 * c4 + 2)] = f2tf(wv[r].z);
            dst[ipos(4 * c4 + 3)] = f2tf(wv[r].w);
        }
        __syncthreads();

        for (int c = 0; c < NCHK; c++) {
            if (c + 1 < NCHK) {
#pragma unroll
                for (int r = 0; r < 4; r++) {
                    int fid = tid + r * 256;
                    int row = fid >> 3, c4 = fid & 7;
                    wv[r] = *reinterpret_cast<const float4*>(
                        &Wp[(size_t)row * ldw + (c + 1) * 32 + 4 * c4]);
                }
            }

            const uint32_t* Wb = &Wsm[(c & 1) * 128 * SW];
#pragma unroll
            for (int kk = 0; kk < 32; kk += 8) {
                int aoff = c * 32 + kk + 2 * tig;
                uint2 a[4][2];
#pragma unroll
                for (int mt = 0; mt < 4; mt++) {
                    int r0 = wm * 64 + mt * 16 + qr;
                    a[mt][0] = *reinterpret_cast<const uint2*>(&Asm[r0 * SA + aoff]);
                    a[mt][1] = *reinterpret_cast<const uint2*>(&Asm[(r0 + 8) * SA + aoff]);
                }
                uint2 b[4];
#pragma unroll
                for (int nt = 0; nt < 4; nt++) {
                    int n0 = wn * 32 + nt * 8 + qr;
                    b[nt] = *reinterpret_cast<const uint2*>(&Wb[n0 * SW + kk + 2 * tig]);
                }
#pragma unroll
                for (int mt = 0; mt < 4; mt++)
#pragma unroll
                    for (int nt = 0; nt < 4; nt++)
                        mma_tf32(acc[mt][nt], a[mt][0], a[mt][1], b[nt]);
            }

            if (c + 1 < NCHK) {
                uint32_t* Wn = &Wsm[((c + 1) & 1) * 128 * SW];
#pragma unroll
                for (int r = 0; r < 4; r++) {
                    int fid = tid + r * 256;
                    int row = fid >> 3, c4 = fid & 7;
                    uint32_t* dst = &Wn[row * SW];
                    dst[ipos(4 * c4 + 0)] = f2tf(wv[r].x);
                    dst[ipos(4 * c4 + 1)] = f2tf(wv[r].y);
                    dst[ipos(4 * c4 + 2)] = f2tf(wv[r].z);
                    dst[ipos(4 * c4 + 3)] = f2tf(wv[r].w);
                }
            }
            __syncthreads();
        }

#pragma unroll
        for (int mt = 0; mt < 4; mt++) {
            int row = bm + wm * 64 + mt * 16 + qr;
#pragma unroll
            for (int nt = 0; nt < 4; nt++) {
                int col = colbase + wn * 32 + nt * 8 + 2 * tig;
                if (row < M)
                    *reinterpret_cast<float2*>(&Cp[(size_t)row * NHALF + col]) =
                        make_float2(acc[mt][nt].x, acc[mt][nt].y);
                if (row + 8 < M)
                    *reinterpret_cast<float2*>(&Cp[(size_t)(row + 8) * NHALF + col]) =
                        make_float2(acc[mt][nt].z, acc[mt][nt].w);
            }
        }
        __syncthreads();
    }
}

// ---------------- aggregation + epilogue (feature-slice pass) ----------------
// One warp per node. Processes 128 contiguous cols starting at col0 of a
// row-stride `stride` buffer. Gather working set per pass = 50MB -> L2-resident.
template <bool RELU>
__global__ void k_agg_h(const float* __restrict__ y, const float* __restrict__ r,
                        const float* __restrict__ bias, float* __restrict__ outp,
                        int stride, int col0) {
    int warp = (blockIdx.x * blockDim.x + threadIdx.x) >> 5;
    int lane = threadIdx.x & 31;
    if (warp >= NN) return;
    const int n = warp;
    int beg = g_off[n];
    int c = g_cnt[n];
    const int fo = col0 + lane * 4;

    float4 acc = make_float4(0.f, 0.f, 0.f, 0.f);
    for (int i = 0; i < c; i++) {
        int s = g_src[beg + i];
        float4 t = *reinterpret_cast<const float4*>(&y[(size_t)s * stride + fo]);
        acc.x += t.x; acc.y += t.y; acc.z += t.z; acc.w += t.w;
    }
    float inv = 1.f / (float)(c > 0 ? c : 1);
    float4 rr = *reinterpret_cast<const float4*>(&r[(size_t)n * stride + fo]);
    float4 bb = *reinterpret_cast<const float4*>(&bias[fo]);
    float4 o;
    o.x = acc.x * inv + bb.x + rr.x;
    o.y = acc.y * inv + bb.y + rr.y;
    o.z = acc.z * inv + bb.z + rr.z;
    o.w = acc.w * inv + bb.w + rr.w;
    if (RELU) {
        o.x = fmaxf(o.x, 0.f); o.y = fmaxf(o.y, 0.f);
        o.z = fmaxf(o.z, 0.f); o.w = fmaxf(o.w, 0.f);
    }
    *reinterpret_cast<float4*>(&outp[(size_t)n * stride + fo]) = o;
}

// ---------------- edge decoder (CSR-grouped by dst) ---------------------------
// One warp per dst node: load v[dst]+bd1 once, gather u[src] per incoming edge.
__global__ void k_edge_csr(const float* __restrict__ u_, const float* __restrict__ v_,
                           const float* __restrict__ bd1, const float* __restrict__ wd2,
                           const float* __restrict__ bd2, float* __restrict__ out) {
    int warp = (blockIdx.x * blockDim.x + threadIdx.x) >> 5;
    int lane = threadIdx.x & 31;
    if (warp >= NN) return;
    const int n = warp;
    int beg = g_off[n];
    int c = g_cnt[n];
    if (c == 0) return;

    float4 b = reinterpret_cast<const float4*>(bd1)[lane];
    float4 w = reinterpret_cast<const float4*>(wd2)[lane];
    float b2 = *bd2;
    float4 vv = reinterpret_cast<const float4*>(v_ + (size_t)n * 128)[lane];
    // vb = v[dst] + bd1 (loop-invariant)
    float4 vb = make_float4(vv.x + b.x, vv.y + b.y, vv.z + b.z, vv.w + b.w);

    for (int i = 0; i < c; i++) {
        int s = g_src[beg + i];
        int eid = g_eid[beg + i];
        float4 uu = reinterpret_cast<const float4*>(u_ + (size_t)s * 128)[lane];
        float t, sum = 0.f;
        t = fmaxf(uu.x + vb.x, 0.f); sum = fmaf(t, w.x, sum);
        t = fmaxf(uu.y + vb.y, 0.f); sum = fmaf(t, w.y, sum);
        t = fmaxf(uu.z + vb.z, 0.f); sum = fmaf(t, w.z, sum);
        t = fmaxf(uu.w + vb.w, 0.f); sum = fmaf(t, w.w, sum);
#pragma unroll
        for (int off = 16; off > 0; off >>= 1)
            sum += __shfl_xor_sync(0xFFFFFFFFu, sum, off);
        if (lane == 0) out[eid] = sum + b2;
    }
}

// ---------------- launch -----------------------------------------------------
extern "C" void kernel_launch(void* const* d_in, const int* in_sizes, int n_in,
                              void* d_out, int out_size) {
    const float* x       = (const float*)d_in[0];
    const void*  ei      = (const void*)d_in[1];
    const float* W1l     = (const float*)d_in[2];
    const float* b1l     = (const float*)d_in[3];
    const float* W1r     = (const float*)d_in[4];
    const float* W2l     = (const float*)d_in[5];
    const float* b2l     = (const float*)d_in[6];
    const float* W2r     = (const float*)d_in[7];
    const float* Wd1     = (const float*)d_in[8];
    const float* bd1     = (const float*)d_in[9];
    const float* Wd2     = (const float*)d_in[10];
    const float* bd2     = (const float*)d_in[11];
    float* out           = (float*)d_out;

    float *bufA, *bufB, *h, *z;
    cudaGetSymbolAddress((void**)&bufA, g_bufA);
    cudaGetSymbolAddress((void**)&bufB, g_bufB);
    cudaGetSymbolAddress((void**)&h, g_h);
    cudaGetSymbolAddress((void**)&z, g_z);

    const int smemK256 = (128 * (256 + 8) + 2 * 128 * 40) * 4;  // 176128
    const int smemK128 = (128 * (128 + 8) + 2 * 128 * 40) * 4;  // 110592
    cudaFuncSetAttribute(k_gemm_mma<256, 4>, cudaFuncAttributeMaxDynamicSharedMemorySize, smemK256);
    cudaFuncSetAttribute(k_gemm_mma<256, 2>, cudaFuncAttributeMaxDynamicSharedMemorySize, smemK256);
    cudaFuncSetAttribute(k_gemm_mma<128, 2>, cudaFuncAttributeMaxDynamicSharedMemorySize, smemK128);

    // dtype probe + edge normalization (+ fused histogram)
    k_detect<<<1, 32>>>((const int*)ei);
    k_zero_cnt<<<(NN + 255) / 256, 256>>>();
    k_cvt_hist<<<(NE + 255) / 256, 256>>>(ei);
    k_scan<<<1, 1024>>>();
    k_scatter<<<(NE + 255) / 256, 256>>>();

    const int MT = (NN + 127) / 128;              // 782
    const int AGG_GRID = (NN * 32 + 255) / 256;   // warp per node

    // conv1: y1 = x@W1l^T, r1 = x@W1r^T (fused), h = relu(agg(y1)/cnt + b1l + r1)
    k_gemm_mma<256, 4><<<MT, 256, smemK256>>>(x, W1l, W1r, 256, bufA, bufB, NN, 256);
    k_agg_h<true><<<AGG_GRID, 256>>>(bufA, bufB, b1l, h, 256, 0);    // cols 0-127
    k_agg_h<true><<<AGG_GRID, 256>>>(bufA, bufB, b1l, h, 256, 128);  // cols 128-255

    // conv2: y2 = h@W2l^T, r2 = h@W2r^T (fused), z = agg(y2)/cnt + b2l + r2
    k_gemm_mma<256, 2><<<MT, 256, smemK256>>>(h, W2l, W2r, 256, bufA, bufB, NN, 128);
    k_agg_h<false><<<AGG_GRID, 256>>>(bufA, bufB, b2l, z, 128, 0);

    // decoder precompute: u = z@A^T, v = z@B^T (Wd1 = [A | B], ldw = 256)
    k_gemm_mma<128, 2><<<MT, 256, smemK128>>>(z, Wd1, Wd1 + 128, 256, bufA, bufB, NN, 128);

    // per-edge (CSR-grouped): out = Wd2 . relu(u[src]+v[dst]+bd1) + bd2
    k_edge_csr<<<AGG_GRID, 256>>>(bufA, bufB, bd1, Wd2, bd2, out);
}

// round 6
// speedup vs baseline: 2.0082x; 1.1803x over previous
#include <cuda_runtime.h>
#include <cstdint>
#include <cstdio>

#define NN 100000
#define NE 1600000
#define SCAN_B 391          // ceil(NN/256)

// ---------------- scratch ----------------------------------------------------
__device__ int   g_is64;
__device__ int   g_esrc[NE];
__device__ int   g_edst[NE];
__device__ int   g_cnt[NN];
__device__ int   g_off[NN];
__device__ int   g_cur[NN];
__device__ int   g_src[NE];
__device__ int   g_eid[NE];
__device__ int   g_bsum[SCAN_B];
__device__ int   g_bpre[SCAN_B];
__device__ float g_bufA[(size_t)NN * 256];  // y1 -> y2 -> u
__device__ float g_bufB[(size_t)NN * 256];  // r1 -> r2 -> v
__device__ float g_h[(size_t)NN * 256];
__device__ float g_z[(size_t)NN * 128];

// ---------------- helpers ----------------------------------------------------
__device__ __forceinline__ uint32_t f2tf(float f) {
    uint32_t u;
    asm("cvt.rna.tf32.f32 %0, %1;" : "=r"(u) : "f"(f));
    return u;
}

__device__ __forceinline__ void mma_tf32(float4& c, uint2 a02, uint2 a13, uint2 b) {
    asm volatile(
        "mma.sync.aligned.m16n8k8.row.col.f32.tf32.tf32.f32 "
        "{%0,%1,%2,%3}, {%4,%5,%6,%7}, {%8,%9}, {%0,%1,%2,%3};"
        : "+f"(c.x), "+f"(c.y), "+f"(c.z), "+f"(c.w)
        : "r"(a02.x), "r"(a13.x), "r"(a02.y), "r"(a13.y), "r"(b.x), "r"(b.y));
}

// interleave position of column k: pairs (k, k+4) adjacent
__device__ __forceinline__ int ipos(int k) {
    return (k & ~7) + 2 * (k & 3) + ((k >> 2) & 1);
}

// ---------------- edge index dtype detection + normalization ----------------
__global__ void k_detect(const int* __restrict__ p) {
    if (threadIdx.x == 0 && blockIdx.x == 0) {
        int odd_nonzero = 0;
        for (int i = 0; i < 1024; i++) {
            if (p[2 * i + 1] != 0) { odd_nonzero = 1; break; }
        }
        g_is64 = odd_nonzero ? 0 : 1;
    }
}

// convert edge list + histogram in one pass (g_cnt must be pre-zeroed)
__global__ void k_cvt_hist(const void* __restrict__ ei) {
    int e = blockIdx.x * blockDim.x + threadIdx.x;
    if (e >= NE) return;
    int s, d;
    if (g_is64) {
        const long long* p = (const long long*)ei;
        s = (int)p[e];
        d = (int)p[NE + e];
    } else {
        const int* p = (const int*)ei;
        s = p[e];
        d = p[NE + e];
    }
    g_esrc[e] = s;
    g_edst[e] = d;
    atomicAdd(&g_cnt[d], 1);
}

__global__ void k_zero_cnt() {
    int i = blockIdx.x * blockDim.x + threadIdx.x;
    if (i < NN) g_cnt[i] = 0;
}

// ---------------- multi-block exclusive scan (3 phases) ----------------------
// Phase A: per-block sum of 256 counts
__global__ void k_scanA() {
    int i = blockIdx.x * 256 + threadIdx.x;
    int v = (i < NN) ? g_cnt[i] : 0;
    int lane = threadIdx.x & 31;
    int wid = threadIdx.x >> 5;
#pragma unroll
    for (int off = 16; off > 0; off >>= 1)
        v += __shfl_xor_sync(0xFFFFFFFFu, v, off);
    __shared__ int ws[8];
    if (lane == 0) ws[wid] = v;
    __syncthreads();
    if (threadIdx.x == 0) {
        int s = 0;
#pragma unroll
        for (int w = 0; w < 8; w++) s += ws[w];
        g_bsum[blockIdx.x] = s;
    }
}

// Phase B: single block exclusive-scans the SCAN_B block sums
__global__ void k_scanB() {
    __shared__ int ws[16];
    const int t = threadIdx.x;           // 512 threads
    int v = (t < SCAN_B) ? g_bsum[t] : 0;
    int lane = t & 31, wid = t >> 5;
    int x = v;
#pragma unroll
    for (int off = 1; off < 32; off <<= 1) {
        int y = __shfl_up_sync(0xFFFFFFFFu, x, off);
        if (lane >= off) x += y;
    }
    if (lane == 31) ws[wid] = x;
    __syncthreads();
    int base = 0;
    for (int w = 0; w < wid; w++) base += ws[w];
    if (t < SCAN_B) g_bpre[t] = base + x - v;   // exclusive prefix
}

// Phase C: intra-block exclusive scan + block prefix -> g_off, g_cur
__global__ void k_scanC() {
    __shared__ int ws[8];
    int i = blockIdx.x * 256 + threadIdx.x;
    int v = (i < NN) ? g_cnt[i] : 0;
    int lane = threadIdx.x & 31, wid = threadIdx.x >> 5;
    int x = v;
#pragma unroll
    for (int off = 1; off < 32; off <<= 1) {
        int y = __shfl_up_sync(0xFFFFFFFFu, x, off);
        if (lane >= off) x += y;
    }
    if (lane == 31) ws[wid] = x;
    __syncthreads();
    int base = g_bpre[blockIdx.x];
    for (int w = 0; w < wid; w++) base += ws[w];
    if (i < NN) {
        int off = base + x - v;
        g_off[i] = off;
        g_cur[i] = off;
    }
}

__global__ void k_scatter() {
    int e = blockIdx.x * blockDim.x + threadIdx.x;
    if (e < NE) {
        int pos = atomicAdd(&g_cur[g_edst[e]], 1);
        g_src[pos] = g_esrc[e];
        g_eid[pos] = e;
    }
}

// ---------------- fused dual-GEMM via mma.sync tf32 ---------------------------
template <int K, int NBLK>
__global__ void __launch_bounds__(256)
k_gemm_mma(const float* __restrict__ A,
           const float* __restrict__ Wl, const float* __restrict__ Wr, int ldw,
           float* __restrict__ Cl, float* __restrict__ Cr, int M, int NHALF) {
    constexpr int SA = K + 8;       // A row stride (floats)
    constexpr int SW = 40;          // W row stride (floats)
    constexpr int NCHK = K / 32;    // K chunks
    extern __shared__ uint32_t smem[];
    uint32_t* Asm = smem;                        // 128 * SA
    uint32_t* Wsm = smem + 128 * SA;             // 2 * 128 * SW

    const int tid = threadIdx.x;
    const int wid = tid >> 5;
    const int lane = tid & 31;
    const int wm = wid >> 2;        // 0..1 -> m offset wm*64
    const int wn = wid & 3;         // 0..3 -> n offset wn*32
    const int qr = lane >> 2;       // 0..7
    const int tig = lane & 3;       // 0..3
    const int bm = blockIdx.x * 128;

    // ---- load A (128 x K) into SMEM as tf32, interleaved pair layout ----
    for (int fid = tid; fid < 128 * (K / 4); fid += 256) {
        int row = fid / (K / 4);
        int c = fid % (K / 4);
        float4 v = make_float4(0.f, 0.f, 0.f, 0.f);
        if (bm + row < M)
            v = *reinterpret_cast<const float4*>(&A[(size_t)(bm + row) * K + 4 * c]);
        uint32_t* dst = &Asm[row * SA];
        dst[ipos(4 * c + 0)] = f2tf(v.x);
        dst[ipos(4 * c + 1)] = f2tf(v.y);
        dst[ipos(4 * c + 2)] = f2tf(v.z);
        dst[ipos(4 * c + 3)] = f2tf(v.w);
    }
    __syncthreads();

    for (int nb = 0; nb < NBLK; nb++) {
        const float* Wp;
        int colbase;
        if (nb * 128 < NHALF) { Wp = Wl + (size_t)(nb * 128) * ldw; colbase = nb * 128; }
        else                  { Wp = Wr + (size_t)(nb * 128 - NHALF) * ldw; colbase = nb * 128 - NHALF; }
        float* Cp = (nb * 128 < NHALF) ? Cl : Cr;

        float4 acc[4][4];
#pragma unroll
        for (int i = 0; i < 4; i++)
#pragma unroll
            for (int j = 0; j < 4; j++) acc[i][j] = make_float4(0.f, 0.f, 0.f, 0.f);

        float4 wv[4];
#pragma unroll
        for (int r = 0; r < 4; r++) {
            int fid = tid + r * 256;
            int row = fid >> 3, c4 = fid & 7;
            wv[r] = *reinterpret_cast<const float4*>(&Wp[(size_t)row * ldw + 0 + 4 * c4]);
        }
#pragma unroll
        for (int r = 0; r < 4; r++) {
            int fid = tid + r * 256;
            int row = fid >> 3, c4 = fid & 7;
            uint32_t* dst = &Wsm[row * SW];
            dst[ipos(4 * c4 + 0)] = f2tf(wv[r].x);
            dst[ipos(4 * c4 + 1)] = f2tf(wv[r].y);
            dst[ipos(4 * c4 + 2)] = f2tf(wv[r].z);
            dst[ipos(4 * c4 + 3)] = f2tf(wv[r].w);
        }
        __syncthreads();

        for (int c = 0; c < NCHK; c++) {
            if (c + 1 < NCHK) {
#pragma unroll
                for (int r = 0; r < 4; r++) {
                    int fid = tid + r * 256;
                    int row = fid >> 3, c4 = fid & 7;
                    wv[r] = *reinterpret_cast<const float4*>(
                        &Wp[(size_t)row * ldw + (c + 1) * 32 + 4 * c4]);
                }
            }

            const uint32_t* Wb = &Wsm[(c & 1) * 128 * SW];
#pragma unroll
            for (int kk = 0; kk < 32; kk += 8) {
                int aoff = c * 32 + kk + 2 * tig;
                uint2 a[4][2];
#pragma unroll
                for (int mt = 0; mt < 4; mt++) {
                    int r0 = wm * 64 + mt * 16 + qr;
                    a[mt][0] = *reinterpret_cast<const uint2*>(&Asm[r0 * SA + aoff]);
                    a[mt][1] = *reinterpret_cast<const uint2*>(&Asm[(r0 + 8) * SA + aoff]);
                }
                uint2 b[4];
#pragma unroll
                for (int nt = 0; nt < 4; nt++) {
                    int n0 = wn * 32 + nt * 8 + qr;
                    b[nt] = *reinterpret_cast<const uint2*>(&Wb[n0 * SW + kk + 2 * tig]);
                }
#pragma unroll
                for (int mt = 0; mt < 4; mt++)
#pragma unroll
                    for (int nt = 0; nt < 4; nt++)
                        mma_tf32(acc[mt][nt], a[mt][0], a[mt][1], b[nt]);
            }

            if (c + 1 < NCHK) {
                uint32_t* Wn = &Wsm[((c + 1) & 1) * 128 * SW];
#pragma unroll
                for (int r = 0; r < 4; r++) {
                    int fid = tid + r * 256;
                    int row = fid >> 3, c4 = fid & 7;
                    uint32_t* dst = &Wn[row * SW];
                    dst[ipos(4 * c4 + 0)] = f2tf(wv[r].x);
                    dst[ipos(4 * c4 + 1)] = f2tf(wv[r].y);
                    dst[ipos(4 * c4 + 2)] = f2tf(wv[r].z);
                    dst[ipos(4 * c4 + 3)] = f2tf(wv[r].w);
                }
            }
            __syncthreads();
        }

#pragma unroll
        for (int mt = 0; mt < 4; mt++) {
            int row = bm + wm * 64 + mt * 16 + qr;
#pragma unroll
            for (int nt = 0; nt < 4; nt++) {
                int col = colbase + wn * 32 + nt * 8 + 2 * tig;
                if (row < M)
                    *reinterpret_cast<float2*>(&Cp[(size_t)row * NHALF + col]) =
                        make_float2(acc[mt][nt].x, acc[mt][nt].y);
                if (row + 8 < M)
                    *reinterpret_cast<float2*>(&Cp[(size_t)(row + 8) * NHALF + col]) =
                        make_float2(acc[mt][nt].z, acc[mt][nt].w);
            }
        }
        __syncthreads();
    }
}

// ---------------- aggregation + epilogue (feature-slice pass) ----------------
template <bool RELU>
__global__ void k_agg_h(const float* __restrict__ y, const float* __restrict__ r,
                        const float* __restrict__ bias, float* __restrict__ outp,
                        int stride, int col0) {
    int warp = (blockIdx.x * blockDim.x + threadIdx.x) >> 5;
    int lane = threadIdx.x & 31;
    if (warp >= NN) return;
    const int n = warp;
    int beg = g_off[n];
    int c = g_cnt[n];
    const int fo = col0 + lane * 4;

    float4 acc = make_float4(0.f, 0.f, 0.f, 0.f);
    for (int i = 0; i < c; i++) {
        int s = g_src[beg + i];
        float4 t = *reinterpret_cast<const float4*>(&y[(size_t)s * stride + fo]);
        acc.x += t.x; acc.y += t.y; acc.z += t.z; acc.w += t.w;
    }
    float inv = 1.f / (float)(c > 0 ? c : 1);
    float4 rr = *reinterpret_cast<const float4*>(&r[(size_t)n * stride + fo]);
    float4 bb = *reinterpret_cast<const float4*>(&bias[fo]);
    float4 o;
    o.x = acc.x * inv + bb.x + rr.x;
    o.y = acc.y * inv + bb.y + rr.y;
    o.z = acc.z * inv + bb.z + rr.z;
    o.w = acc.w * inv + bb.w + rr.w;
    if (RELU) {
        o.x = fmaxf(o.x, 0.f); o.y = fmaxf(o.y, 0.f);
        o.z = fmaxf(o.z, 0.f); o.w = fmaxf(o.w, 0.f);
    }
    *reinterpret_cast<float4*>(&outp[(size_t)n * stride + fo]) = o;
}

// ---------------- edge decoder (CSR-grouped by dst) ---------------------------
__global__ void k_edge_csr(const float* __restrict__ u_, const float* __restrict__ v_,
                           const float* __restrict__ bd1, const float* __restrict__ wd2,
                           const float* __restrict__ bd2, float* __restrict__ out) {
    int warp = (blockIdx.x * blockDim.x + threadIdx.x) >> 5;
    int lane = threadIdx.x & 31;
    if (warp >= NN) return;
    const int n = warp;
    int beg = g_off[n];
    int c = g_cnt[n];
    if (c == 0) return;

    float4 b = reinterpret_cast<const float4*>(bd1)[lane];
    float4 w = reinterpret_cast<const float4*>(wd2)[lane];
    float b2 = *bd2;
    float4 vv = reinterpret_cast<const float4*>(v_ + (size_t)n * 128)[lane];
    float4 vb = make_float4(vv.x + b.x, vv.y + b.y, vv.z + b.z, vv.w + b.w);

    for (int i = 0; i < c; i++) {
        int s = g_src[beg + i];
        int eid = g_eid[beg + i];
        float4 uu = reinterpret_cast<const float4*>(u_ + (size_t)s * 128)[lane];
        float t, sum = 0.f;
        t = fmaxf(uu.x + vb.x, 0.f); sum = fmaf(t, w.x, sum);
        t = fmaxf(uu.y + vb.y, 0.f); sum = fmaf(t, w.y, sum);
        t = fmaxf(uu.z + vb.z, 0.f); sum = fmaf(t, w.z, sum);
        t = fmaxf(uu.w + vb.w, 0.f); sum = fmaf(t, w.w, sum);
#pragma unroll
        for (int off = 16; off > 0; off >>= 1)
            sum += __shfl_xor_sync(0xFFFFFFFFu, sum, off);
        if (lane == 0) out[eid] = sum + b2;
    }
}

// ---------------- launch -----------------------------------------------------
extern "C" void kernel_launch(void* const* d_in, const int* in_sizes, int n_in,
                              void* d_out, int out_size) {
    const float* x       = (const float*)d_in[0];
    const void*  ei      = (const void*)d_in[1];
    const float* W1l     = (const float*)d_in[2];
    const float* b1l     = (const float*)d_in[3];
    const float* W1r     = (const float*)d_in[4];
    const float* W2l     = (const float*)d_in[5];
    const float* b2l     = (const float*)d_in[6];
    const float* W2r     = (const float*)d_in[7];
    const float* Wd1     = (const float*)d_in[8];
    const float* bd1     = (const float*)d_in[9];
    const float* Wd2     = (const float*)d_in[10];
    const float* bd2     = (const float*)d_in[11];
    float* out           = (float*)d_out;

    float *bufA, *bufB, *h, *z;
    cudaGetSymbolAddress((void**)&bufA, g_bufA);
    cudaGetSymbolAddress((void**)&bufB, g_bufB);
    cudaGetSymbolAddress((void**)&h, g_h);
    cudaGetSymbolAddress((void**)&z, g_z);

    const int smemK256 = (128 * (256 + 8) + 2 * 128 * 40) * 4;  // 176128
    const int smemK128 = (128 * (128 + 8) + 2 * 128 * 40) * 4;  // 110592
    cudaFuncSetAttribute(k_gemm_mma<256, 4>, cudaFuncAttributeMaxDynamicSharedMemorySize, smemK256);
    cudaFuncSetAttribute(k_gemm_mma<256, 2>, cudaFuncAttributeMaxDynamicSharedMemorySize, smemK256);
    cudaFuncSetAttribute(k_gemm_mma<128, 2>, cudaFuncAttributeMaxDynamicSharedMemorySize, smemK128);

    // dtype probe + edge normalization (+ fused histogram)
    k_detect<<<1, 32>>>((const int*)ei);
    k_zero_cnt<<<(NN + 255) / 256, 256>>>();
    k_cvt_hist<<<(NE + 255) / 256, 256>>>(ei);

    // multi-block exclusive scan
    k_scanA<<<SCAN_B, 256>>>();
    k_scanB<<<1, 512>>>();
    k_scanC<<<SCAN_B, 256>>>();
    k_scatter<<<(NE + 255) / 256, 256>>>();

    const int MT = (NN + 127) / 128;              // 782
    const int AGG_GRID = (NN * 32 + 255) / 256;   // warp per node

    // conv1: y1 = x@W1l^T, r1 = x@W1r^T (fused), h = relu(agg(y1)/cnt + b1l + r1)
    k_gemm_mma<256, 4><<<MT, 256, smemK256>>>(x, W1l, W1r, 256, bufA, bufB, NN, 256);
    k_agg_h<true><<<AGG_GRID, 256>>>(bufA, bufB, b1l, h, 256, 0);    // cols 0-127
    k_agg_h<true><<<AGG_GRID, 256>>>(bufA, bufB, b1l, h, 256, 128);  // cols 128-255

    // conv2: y2 = h@W2l^T, r2 = h@W2r^T (fused), z = agg(y2)/cnt + b2l + r2
    k_gemm_mma<256, 2><<<MT, 256, smemK256>>>(h, W2l, W2r, 256, bufA, bufB, NN, 128);
    k_agg_h<false><<<AGG_GRID, 256>>>(bufA, bufB, b2l, z, 128, 0);

    // decoder precompute: u = z@A^T, v = z@B^T (Wd1 = [A | B], ldw = 256)
    k_gemm_mma<128, 2><<<MT, 256, smemK128>>>(z, Wd1, Wd1 + 128, 256, bufA, bufB, NN, 128);

    // per-edge (CSR-grouped): out = Wd2 . relu(u[src]+v[dst]+bd1) + bd2
    k_edge_csr<<<AGG_GRID, 256>>>(bufA, bufB, bd1, Wd2, bd2, out);
}

// round 7
// speedup vs baseline: 2.0794x; 1.0355x over previous
#include <cuda_runtime.h>
#include <cstdint>
#include <cstdio>

#define NN 100000
#define NE 1600000
#define SCAN_B 391          // ceil(NN/256)

// ---------------- scratch ----------------------------------------------------
__device__ int   g_is64;
__device__ int   g_esrc[NE];
__device__ int   g_edst[NE];
__device__ int   g_cnt[NN];
__device__ int   g_off[NN];
__device__ int   g_cur[NN];
__device__ int   g_src[NE];
__device__ int   g_eid[NE];
__device__ int   g_bsum[SCAN_B];
__device__ int   g_bpre[SCAN_B];
__device__ float g_bufA[(size_t)NN * 256];  // y1 -> y2 -> u
__device__ float g_bufB[(size_t)NN * 256];  // r1 -> r2 -> v
__device__ float g_h[(size_t)NN * 256];
__device__ float g_z[(size_t)NN * 128];

// ---------------- side stream for CSR/GEMM overlap ---------------------------
// Created once at program load (global ctor) — no device memory involved.
struct SideStream {
    cudaStream_t s = nullptr;
    cudaEvent_t fork = nullptr, join = nullptr;
    SideStream() {
        cudaStreamCreateWithFlags(&s, cudaStreamNonBlocking);
        cudaEventCreateWithFlags(&fork, cudaEventDisableTiming);
        cudaEventCreateWithFlags(&join, cudaEventDisableTiming);
    }
};
static SideStream g_ss;

// ---------------- helpers ----------------------------------------------------
__device__ __forceinline__ uint32_t f2tf(float f) {
    uint32_t u;
    asm("cvt.rna.tf32.f32 %0, %1;" : "=r"(u) : "f"(f));
    return u;
}

__device__ __forceinline__ void mma_tf32(float4& c, uint2 a02, uint2 a13, uint2 b) {
    asm volatile(
        "mma.sync.aligned.m16n8k8.row.col.f32.tf32.tf32.f32 "
        "{%0,%1,%2,%3}, {%4,%5,%6,%7}, {%8,%9}, {%0,%1,%2,%3};"
        : "+f"(c.x), "+f"(c.y), "+f"(c.z), "+f"(c.w)
        : "r"(a02.x), "r"(a13.x), "r"(a02.y), "r"(a13.y), "r"(b.x), "r"(b.y));
}

// interleave position of column k: pairs (k, k+4) adjacent
__device__ __forceinline__ int ipos(int k) {
    return (k & ~7) + 2 * (k & 3) + ((k >> 2) & 1);
}

// ---------------- edge index dtype detection + normalization ----------------
__global__ void k_detect(const int* __restrict__ p) {
    if (threadIdx.x == 0 && blockIdx.x == 0) {
        int odd_nonzero = 0;
        for (int i = 0; i < 1024; i++) {
            if (p[2 * i + 1] != 0) { odd_nonzero = 1; break; }
        }
        g_is64 = odd_nonzero ? 0 : 1;
    }
}

// convert edge list + histogram in one pass (g_cnt must be pre-zeroed)
__global__ void k_cvt_hist(const void* __restrict__ ei) {
    int e = blockIdx.x * blockDim.x + threadIdx.x;
    if (e >= NE) return;
    int s, d;
    if (g_is64) {
        const long long* p = (const long long*)ei;
        s = (int)p[e];
        d = (int)p[NE + e];
    } else {
        const int* p = (const int*)ei;
        s = p[e];
        d = p[NE + e];
    }
    g_esrc[e] = s;
    g_edst[e] = d;
    atomicAdd(&g_cnt[d], 1);
}

__global__ void k_zero_cnt() {
    int i = blockIdx.x * blockDim.x + threadIdx.x;
    if (i < NN) g_cnt[i] = 0;
}

// ---------------- multi-block exclusive scan (3 phases) ----------------------
__global__ void k_scanA() {
    int i = blockIdx.x * 256 + threadIdx.x;
    int v = (i < NN) ? g_cnt[i] : 0;
    int lane = threadIdx.x & 31;
    int wid = threadIdx.x >> 5;
#pragma unroll
    for (int off = 16; off > 0; off >>= 1)
        v += __shfl_xor_sync(0xFFFFFFFFu, v, off);
    __shared__ int ws[8];
    if (lane == 0) ws[wid] = v;
    __syncthreads();
    if (threadIdx.x == 0) {
        int s = 0;
#pragma unroll
        for (int w = 0; w < 8; w++) s += ws[w];
        g_bsum[blockIdx.x] = s;
    }
}

__global__ void k_scanB() {
    __shared__ int ws[16];
    const int t = threadIdx.x;           // 512 threads
    int v = (t < SCAN_B) ? g_bsum[t] : 0;
    int lane = t & 31, wid = t >> 5;
    int x = v;
#pragma unroll
    for (int off = 1; off < 32; off <<= 1) {
        int y = __shfl_up_sync(0xFFFFFFFFu, x, off);
        if (lane >= off) x += y;
    }
    if (lane == 31) ws[wid] = x;
    __syncthreads();
    int base = 0;
    for (int w = 0; w < wid; w++) base += ws[w];
    if (t < SCAN_B) g_bpre[t] = base + x - v;   // exclusive prefix
}

__global__ void k_scanC() {
    __shared__ int ws[8];
    int i = blockIdx.x * 256 + threadIdx.x;
    int v = (i < NN) ? g_cnt[i] : 0;
    int lane = threadIdx.x & 31, wid = threadIdx.x >> 5;
    int x = v;
#pragma unroll
    for (int off = 1; off < 32; off <<= 1) {
        int y = __shfl_up_sync(0xFFFFFFFFu, x, off);
        if (lane >= off) x += y;
    }
    if (lane == 31) ws[wid] = x;
    __syncthreads();
    int base = g_bpre[blockIdx.x];
    for (int w = 0; w < wid; w++) base += ws[w];
    if (i < NN) {
        int off = base + x - v;
        g_off[i] = off;
        g_cur[i] = off;
    }
}

__global__ void k_scatter() {
    int e = blockIdx.x * blockDim.x + threadIdx.x;
    if (e < NE) {
        int pos = atomicAdd(&g_cur[g_edst[e]], 1);
        g_src[pos] = g_esrc[e];
        g_eid[pos] = e;
    }
}

// ---------------- fused dual-GEMM via mma.sync tf32 ---------------------------
template <int K, int NBLK>
__global__ void __launch_bounds__(256)
k_gemm_mma(const float* __restrict__ A,
           const float* __restrict__ Wl, const float* __restrict__ Wr, int ldw,
           float* __restrict__ Cl, float* __restrict__ Cr, int M, int NHALF) {
    constexpr int SA = K + 8;       // A row stride (floats)
    constexpr int SW = 40;          // W row stride (floats)
    constexpr int NCHK = K / 32;    // K chunks
    extern __shared__ uint32_t smem[];
    uint32_t* Asm = smem;                        // 128 * SA
    uint32_t* Wsm = smem + 128 * SA;             // 2 * 128 * SW

    const int tid = threadIdx.x;
    const int wid = tid >> 5;
    const int lane = tid & 31;
    const int wm = wid >> 2;        // 0..1 -> m offset wm*64
    const int wn = wid & 3;         // 0..3 -> n offset wn*32
    const int qr = lane >> 2;       // 0..7
    const int tig = lane & 3;       // 0..3
    const int bm = blockIdx.x * 128;

    for (int fid = tid; fid < 128 * (K / 4); fid += 256) {
        int row = fid / (K / 4);
        int c = fid % (K / 4);
        float4 v = make_float4(0.f, 0.f, 0.f, 0.f);
        if (bm + row < M)
            v = *reinterpret_cast<const float4*>(&A[(size_t)(bm + row) * K + 4 * c]);
        uint32_t* dst = &Asm[row * SA];
        dst[ipos(4 * c + 0)] = f2tf(v.x);
        dst[ipos(4 * c + 1)] = f2tf(v.y);
        dst[ipos(4 * c + 2)] = f2tf(v.z);
        dst[ipos(4 * c + 3)] = f2tf(v.w);
    }
    __syncthreads();

    for (int nb = 0; nb < NBLK; nb++) {
        const float* Wp;
        int colbase;
        if (nb * 128 < NHALF) { Wp = Wl + (size_t)(nb * 128) * ldw; colbase = nb * 128; }
        else                  { Wp = Wr + (size_t)(nb * 128 - NHALF) * ldw; colbase = nb * 128 - NHALF; }
        float* Cp = (nb * 128 < NHALF) ? Cl : Cr;

        float4 acc[4][4];
#pragma unroll
        for (int i = 0; i < 4; i++)
#pragma unroll
            for (int j = 0; j < 4; j++) acc[i][j] = make_float4(0.f, 0.f, 0.f, 0.f);

        float4 wv[4];
#pragma unroll
        for (int r = 0; r < 4; r++) {
            int fid = tid + r * 256;
            int row = fid >> 3, c4 = fid & 7;
            wv[r] = *reinterpret_cast<const float4*>(&Wp[(size_t)row * ldw + 0 + 4 * c4]);
        }
#pragma unroll
        for (int r = 0; r < 4; r++) {
            int fid = tid + r * 256;
            int row = fid >> 3, c4 = fid & 7;
            uint32_t* dst = &Wsm[row * SW];
            dst[ipos(4 * c4 + 0)] = f2tf(wv[r].x);
            dst[ipos(4 * c4 + 1)] = f2tf(wv[r].y);
            dst[ipos(4 * c4 + 2)] = f2tf(wv[r].z);
            dst[ipos(4 * c4 + 3)] = f2tf(wv[r].w);
        }
        __syncthreads();

        for (int c = 0; c < NCHK; c++) {
            if (c + 1 < NCHK) {
#pragma unroll
                for (int r = 0; r < 4; r++) {
                    int fid = tid + r * 256;
                    int row = fid >> 3, c4 = fid & 7;
                    wv[r] = *reinterpret_cast<const float4*>(
                        &Wp[(size_t)row * ldw + (c + 1) * 32 + 4 * c4]);
                }
            }

            const uint32_t* Wb = &Wsm[(c & 1) * 128 * SW];
#pragma unroll
            for (int kk = 0; kk < 32; kk += 8) {
                int aoff = c * 32 + kk + 2 * tig;
                uint2 a[4][2];
#pragma unroll
                for (int mt = 0; mt < 4; mt++) {
                    int r0 = wm * 64 + mt * 16 + qr;
                    a[mt][0] = *reinterpret_cast<const uint2*>(&Asm[r0 * SA + aoff]);
                    a[mt][1] = *reinterpret_cast<const uint2*>(&Asm[(r0 + 8) * SA + aoff]);
                }
                uint2 b[4];
#pragma unroll
                for (int nt = 0; nt < 4; nt++) {
                    int n0 = wn * 32 + nt * 8 + qr;
                    b[nt] = *reinterpret_cast<const uint2*>(&Wb[n0 * SW + kk + 2 * tig]);
                }
#pragma unroll
                for (int mt = 0; mt < 4; mt++)
#pragma unroll
                    for (int nt = 0; nt < 4; nt++)
                        mma_tf32(acc[mt][nt], a[mt][0], a[mt][1], b[nt]);
            }

            if (c + 1 < NCHK) {
                uint32_t* Wn = &Wsm[((c + 1) & 1) * 128 * SW];
#pragma unroll
                for (int r = 0; r < 4; r++) {
                    int fid = tid + r * 256;
                    int row = fid >> 3, c4 = fid & 7;
                    uint32_t* dst = &Wn[row * SW];
                    dst[ipos(4 * c4 + 0)] = f2tf(wv[r].x);
                    dst[ipos(4 * c4 + 1)] = f2tf(wv[r].y);
                    dst[ipos(4 * c4 + 2)] = f2tf(wv[r].z);
                    dst[ipos(4 * c4 + 3)] = f2tf(wv[r].w);
                }
            }
            __syncthreads();
        }

#pragma unroll
        for (int mt = 0; mt < 4; mt++) {
            int row = bm + wm * 64 + mt * 16 + qr;
#pragma unroll
            for (int nt = 0; nt < 4; nt++) {
                int col = colbase + wn * 32 + nt * 8 + 2 * tig;
                if (row < M)
                    *reinterpret_cast<float2*>(&Cp[(size_t)row * NHALF + col]) =
                        make_float2(acc[mt][nt].x, acc[mt][nt].y);
                if (row + 8 < M)
                    *reinterpret_cast<float2*>(&Cp[(size_t)(row + 8) * NHALF + col]) =
                        make_float2(acc[mt][nt].z, acc[mt][nt].w);
            }
        }
        __syncthreads();
    }
}

// ---------------- aggregation + epilogue (feature-slice pass) ----------------
// Unroll-by-2 with dual accumulators -> >=4 independent gathers in flight.
template <bool RELU>
__global__ void k_agg_h(const float* __restrict__ y, const float* __restrict__ r,
                        const float* __restrict__ bias, float* __restrict__ outp,
                        int stride, int col0) {
    int warp = (blockIdx.x * blockDim.x + threadIdx.x) >> 5;
    int lane = threadIdx.x & 31;
    if (warp >= NN) return;
    const int n = warp;
    int beg = g_off[n];
    int c = g_cnt[n];
    const int fo = col0 + lane * 4;

    float4 a0 = make_float4(0.f, 0.f, 0.f, 0.f);
    float4 a1 = make_float4(0.f, 0.f, 0.f, 0.f);
    int i = 0;
#pragma unroll 2
    for (; i + 2 <= c; i += 2) {
        int s0 = g_src[beg + i];
        int s1 = g_src[beg + i + 1];
        float4 t0 = *reinterpret_cast<const float4*>(&y[(size_t)s0 * stride + fo]);
        float4 t1 = *reinterpret_cast<const float4*>(&y[(size_t)s1 * stride + fo]);
        a0.x += t0.x; a0.y += t0.y; a0.z += t0.z; a0.w += t0.w;
        a1.x += t1.x; a1.y += t1.y; a1.z += t1.z; a1.w += t1.w;
    }
    if (i < c) {
        int s = g_src[beg + i];
        float4 t = *reinterpret_cast<const float4*>(&y[(size_t)s * stride + fo]);
        a0.x += t.x; a0.y += t.y; a0.z += t.z; a0.w += t.w;
    }
    float4 acc = make_float4(a0.x + a1.x, a0.y + a1.y, a0.z + a1.z, a0.w + a1.w);

    float inv = 1.f / (float)(c > 0 ? c : 1);
    float4 rr = *reinterpret_cast<const float4*>(&r[(size_t)n * stride + fo]);
    float4 bb = *reinterpret_cast<const float4*>(&bias[fo]);
    float4 o;
    o.x = acc.x * inv + bb.x + rr.x;
    o.y = acc.y * inv + bb.y + rr.y;
    o.z = acc.z * inv + bb.z + rr.z;
    o.w = acc.w * inv + bb.w + rr.w;
    if (RELU) {
        o.x = fmaxf(o.x, 0.f); o.y = fmaxf(o.y, 0.f);
        o.z = fmaxf(o.z, 0.f); o.w = fmaxf(o.w, 0.f);
    }
    *reinterpret_cast<float4*>(&outp[(size_t)n * stride + fo]) = o;
}

// ---------------- edge decoder (CSR-grouped by dst) ---------------------------
__global__ void k_edge_csr(const float* __restrict__ u_, const float* __restrict__ v_,
                           const float* __restrict__ bd1, const float* __restrict__ wd2,
                           const float* __restrict__ bd2, float* __restrict__ out) {
    int warp = (blockIdx.x * blockDim.x + threadIdx.x) >> 5;
    int lane = threadIdx.x & 31;
    if (warp >= NN) return;
    const int n = warp;
    int beg = g_off[n];
    int c = g_cnt[n];
    if (c == 0) return;

    float4 b = reinterpret_cast<const float4*>(bd1)[lane];
    float4 w = reinterpret_cast<const float4*>(wd2)[lane];
    float b2 = *bd2;
    float4 vv = reinterpret_cast<const float4*>(v_ + (size_t)n * 128)[lane];
    float4 vb = make_float4(vv.x + b.x, vv.y + b.y, vv.z + b.z, vv.w + b.w);

#pragma unroll 2
    for (int i = 0; i < c; i++) {
        int s = g_src[beg + i];
        int eid = g_eid[beg + i];
        float4 uu = reinterpret_cast<const float4*>(u_ + (size_t)s * 128)[lane];
        float t, sum = 0.f;
        t = fmaxf(uu.x + vb.x, 0.f); sum = fmaf(t, w.x, sum);
        t = fmaxf(uu.y + vb.y, 0.f); sum = fmaf(t, w.y, sum);
        t = fmaxf(uu.z + vb.z, 0.f); sum = fmaf(t, w.z, sum);
        t = fmaxf(uu.w + vb.w, 0.f); sum = fmaf(t, w.w, sum);
#pragma unroll
        for (int off = 16; off > 0; off >>= 1)
            sum += __shfl_xor_sync(0xFFFFFFFFu, sum, off);
        if (lane == 0) out[eid] = sum + b2;
    }
}

// ---------------- launch -----------------------------------------------------
extern "C" void kernel_launch(void* const* d_in, const int* in_sizes, int n_in,
                              void* d_out, int out_size) {
    const float* x       = (const float*)d_in[0];
    const void*  ei      = (const void*)d_in[1];
    const float* W1l     = (const float*)d_in[2];
    const float* b1l     = (const float*)d_in[3];
    const float* W1r     = (const float*)d_in[4];
    const float* W2l     = (const float*)d_in[5];
    const float* b2l     = (const float*)d_in[6];
    const float* W2r     = (const float*)d_in[7];
    const float* Wd1     = (const float*)d_in[8];
    const float* bd1     = (const float*)d_in[9];
    const float* Wd2     = (const float*)d_in[10];
    const float* bd2     = (const float*)d_in[11];
    float* out           = (float*)d_out;

    float *bufA, *bufB, *h, *z;
    cudaGetSymbolAddress((void**)&bufA, g_bufA);
    cudaGetSymbolAddress((void**)&bufB, g_bufB);
    cudaGetSymbolAddress((void**)&h, g_h);
    cudaGetSymbolAddress((void**)&z, g_z);

    const int smemK256 = (128 * (256 + 8) + 2 * 128 * 40) * 4;  // 176128
    const int smemK128 = (128 * (128 + 8) + 2 * 128 * 40) * 4;  // 110592
    cudaFuncSetAttribute(k_gemm_mma<256, 4>, cudaFuncAttributeMaxDynamicSharedMemorySize, smemK256);
    cudaFuncSetAttribute(k_gemm_mma<256, 2>, cudaFuncAttributeMaxDynamicSharedMemorySize, smemK256);
    cudaFuncSetAttribute(k_gemm_mma<128, 2>, cudaFuncAttributeMaxDynamicSharedMemorySize, smemK128);

    const int MT = (NN + 127) / 128;              // 782
    const int AGG_GRID = (NN * 32 + 255) / 256;   // warp per node

    // ---- fork: CSR build on side stream, GEMM1 on main stream ----
    cudaStream_t s2 = g_ss.s;
    cudaEventRecord(g_ss.fork, 0);
    cudaStreamWaitEvent(s2, g_ss.fork, 0);

    // side stream: dtype probe + edge normalization + CSR
    k_detect<<<1, 32, 0, s2>>>((const int*)ei);
    k_zero_cnt<<<(NN + 255) / 256, 256, 0, s2>>>();
    k_cvt_hist<<<(NE + 255) / 256, 256, 0, s2>>>(ei);
    k_scanA<<<SCAN_B, 256, 0, s2>>>();
    k_scanB<<<1, 512, 0, s2>>>();
    k_scanC<<<SCAN_B, 256, 0, s2>>>();
    k_scatter<<<(NE + 255) / 256, 256, 0, s2>>>();
    cudaEventRecord(g_ss.join, s2);

    // main stream: conv1 GEMMs (independent of CSR)
    k_gemm_mma<256, 4><<<MT, 256, smemK256>>>(x, W1l, W1r, 256, bufA, bufB, NN, 256);

    // join: agg needs CSR + GEMM1
    cudaStreamWaitEvent(0, g_ss.join, 0);

    // conv1 aggregation (two L2-resident half passes)
    k_agg_h<true><<<AGG_GRID, 256>>>(bufA, bufB, b1l, h, 256, 0);
    k_agg_h<true><<<AGG_GRID, 256>>>(bufA, bufB, b1l, h, 256, 128);

    // conv2
    k_gemm_mma<256, 2><<<MT, 256, smemK256>>>(h, W2l, W2r, 256, bufA, bufB, NN, 128);
    k_agg_h<false><<<AGG_GRID, 256>>>(bufA, bufB, b2l, z, 128, 0);

    // decoder precompute: u = z@A^T, v = z@B^T (Wd1 = [A | B], ldw = 256)
    k_gemm_mma<128, 2><<<MT, 256, smemK128>>>(z, Wd1, Wd1 + 128, 256, bufA, bufB, NN, 128);

    // per-edge (CSR-grouped): out = Wd2 . relu(u[src]+v[dst]+bd1) + bd2
    k_edge_csr<<<AGG_GRID, 256>>>(bufA, bufB, bd1, Wd2, bd2, out);
}

// round 8
// speedup vs baseline: 2.1192x; 1.0191x over previous
#include <cuda_runtime.h>
#include <cuda_fp16.h>
#include <cstdint>
#include <cstdio>

#define NN 100000
#define NE 1600000
#define SCAN_B 391          // ceil(NN/256)

// ---------------- scratch ----------------------------------------------------
__device__ int    g_is64;
__device__ int    g_esrc[NE];
__device__ int    g_edst[NE];
__device__ int    g_cnt[NN];
__device__ int    g_off[NN];
__device__ int    g_cur[NN];
__device__ int    g_src[NE];
__device__ int    g_eid[NE];
__device__ int    g_bsum[SCAN_B];
__device__ int    g_bpre[SCAN_B];
__device__ __half g_yh[(size_t)NN * 256];   // gathered buffers: y1 / y2 / u (fp16)
__device__ float  g_bufB[(size_t)NN * 256]; // streamed: r1 -> r2 -> v (fp32)
__device__ float  g_h[(size_t)NN * 256];
__device__ float  g_z[(size_t)NN * 128];

// ---------------- side stream for CSR/GEMM overlap ---------------------------
struct SideStream {
    cudaStream_t s = nullptr;
    cudaEvent_t fork = nullptr, join = nullptr;
    SideStream() {
        cudaStreamCreateWithFlags(&s, cudaStreamNonBlocking);
        cudaEventCreateWithFlags(&fork, cudaEventDisableTiming);
        cudaEventCreateWithFlags(&join, cudaEventDisableTiming);
    }
};
static SideStream g_ss;

// ---------------- helpers ----------------------------------------------------
__device__ __forceinline__ uint32_t f2tf(float f) {
    uint32_t u;
    asm("cvt.rna.tf32.f32 %0, %1;" : "=r"(u) : "f"(f));
    return u;
}

__device__ __forceinline__ void mma_tf32(float4& c, uint2 a02, uint2 a13, uint2 b) {
    asm volatile(
        "mma.sync.aligned.m16n8k8.row.col.f32.tf32.tf32.f32 "
        "{%0,%1,%2,%3}, {%4,%5,%6,%7}, {%8,%9}, {%0,%1,%2,%3};"
        : "+f"(c.x), "+f"(c.y), "+f"(c.z), "+f"(c.w)
        : "r"(a02.x), "r"(a13.x), "r"(a02.y), "r"(a13.y), "r"(b.x), "r"(b.y));
}

// interleave position of column k: pairs (k, k+4) adjacent
__device__ __forceinline__ int ipos(int k) {
    return (k & ~7) + 2 * (k & 3) + ((k >> 2) & 1);
}

// ---------------- edge index dtype detection + normalization ----------------
__global__ void k_detect(const int* __restrict__ p) {
    if (threadIdx.x == 0 && blockIdx.x == 0) {
        int odd_nonzero = 0;
        for (int i = 0; i < 1024; i++) {
            if (p[2 * i + 1] != 0) { odd_nonzero = 1; break; }
        }
        g_is64 = odd_nonzero ? 0 : 1;
    }
}

__global__ void k_cvt_hist(const void* __restrict__ ei) {
    int e = blockIdx.x * blockDim.x + threadIdx.x;
    if (e >= NE) return;
    int s, d;
    if (g_is64) {
        const long long* p = (const long long*)ei;
        s = (int)p[e];
        d = (int)p[NE + e];
    } else {
        const int* p = (const int*)ei;
        s = p[e];
        d = p[NE + e];
    }
    g_esrc[e] = s;
    g_edst[e] = d;
    atomicAdd(&g_cnt[d], 1);
}

__global__ void k_zero_cnt() {
    int i = blockIdx.x * blockDim.x + threadIdx.x;
    if (i < NN) g_cnt[i] = 0;
}

// ---------------- multi-block exclusive scan (3 phases) ----------------------
__global__ void k_scanA() {
    int i = blockIdx.x * 256 + threadIdx.x;
    int v = (i < NN) ? g_cnt[i] : 0;
    int lane = threadIdx.x & 31;
    int wid = threadIdx.x >> 5;
#pragma unroll
    for (int off = 16; off > 0; off >>= 1)
        v += __shfl_xor_sync(0xFFFFFFFFu, v, off);
    __shared__ int ws[8];
    if (lane == 0) ws[wid] = v;
    __syncthreads();
    if (threadIdx.x == 0) {
        int s = 0;
#pragma unroll
        for (int w = 0; w < 8; w++) s += ws[w];
        g_bsum[blockIdx.x] = s;
    }
}

__global__ void k_scanB() {
    __shared__ int ws[16];
    const int t = threadIdx.x;           // 512 threads
    int v = (t < SCAN_B) ? g_bsum[t] : 0;
    int lane = t & 31, wid = t >> 5;
    int x = v;
#pragma unroll
    for (int off = 1; off < 32; off <<= 1) {
        int y = __shfl_up_sync(0xFFFFFFFFu, x, off);
        if (lane >= off) x += y;
    }
    if (lane == 31) ws[wid] = x;
    __syncthreads();
    int base = 0;
    for (int w = 0; w < wid; w++) base += ws[w];
    if (t < SCAN_B) g_bpre[t] = base + x - v;   // exclusive prefix
}

__global__ void k_scanC() {
    __shared__ int ws[8];
    int i = blockIdx.x * 256 + threadIdx.x;
    int v = (i < NN) ? g_cnt[i] : 0;
    int lane = threadIdx.x & 31, wid = threadIdx.x >> 5;
    int x = v;
#pragma unroll
    for (int off = 1; off < 32; off <<= 1) {
        int y = __shfl_up_sync(0xFFFFFFFFu, x, off);
        if (lane >= off) x += y;
    }
    if (lane == 31) ws[wid] = x;
    __syncthreads();
    int base = g_bpre[blockIdx.x];
    for (int w = 0; w < wid; w++) base += ws[w];
    if (i < NN) {
        int off = base + x - v;
        g_off[i] = off;
        g_cur[i] = off;
    }
}

__global__ void k_scatter() {
    int e = blockIdx.x * blockDim.x + threadIdx.x;
    if (e < NE) {
        int pos = atomicAdd(&g_cur[g_edst[e]], 1);
        g_src[pos] = g_esrc[e];
        g_eid[pos] = e;
    }
}

// ---------------- fused dual-GEMM via mma.sync tf32 ---------------------------
// Cl (gathered later) written as fp16; Cr (streamed later) written fp32.
template <int K, int NBLK>
__global__ void __launch_bounds__(256)
k_gemm_mma(const float* __restrict__ A,
           const float* __restrict__ Wl, const float* __restrict__ Wr, int ldw,
           __half* __restrict__ Cl, float* __restrict__ Cr, int M, int NHALF) {
    constexpr int SA = K + 8;       // A row stride (floats)
    constexpr int SW = 40;          // W row stride (floats)
    constexpr int NCHK = K / 32;    // K chunks
    extern __shared__ uint32_t smem[];
    uint32_t* Asm = smem;                        // 128 * SA
    uint32_t* Wsm = smem + 128 * SA;             // 2 * 128 * SW

    const int tid = threadIdx.x;
    const int wid = tid >> 5;
    const int lane = tid & 31;
    const int wm = wid >> 2;        // 0..1 -> m offset wm*64
    const int wn = wid & 3;         // 0..3 -> n offset wn*32
    const int qr = lane >> 2;       // 0..7
    const int tig = lane & 3;       // 0..3
    const int bm = blockIdx.x * 128;

    for (int fid = tid; fid < 128 * (K / 4); fid += 256) {
        int row = fid / (K / 4);
        int c = fid % (K / 4);
        float4 v = make_float4(0.f, 0.f, 0.f, 0.f);
        if (bm + row < M)
            v = *reinterpret_cast<const float4*>(&A[(size_t)(bm + row) * K + 4 * c]);
        uint32_t* dst = &Asm[row * SA];
        dst[ipos(4 * c + 0)] = f2tf(v.x);
        dst[ipos(4 * c + 1)] = f2tf(v.y);
        dst[ipos(4 * c + 2)] = f2tf(v.z);
        dst[ipos(4 * c + 3)] = f2tf(v.w);
    }
    __syncthreads();

    for (int nb = 0; nb < NBLK; nb++) {
        const float* Wp;
        int colbase;
        const bool isL = (nb * 128 < NHALF);
        if (isL) { Wp = Wl + (size_t)(nb * 128) * ldw; colbase = nb * 128; }
        else     { Wp = Wr + (size_t)(nb * 128 - NHALF) * ldw; colbase = nb * 128 - NHALF; }

        float4 acc[4][4];
#pragma unroll
        for (int i = 0; i < 4; i++)
#pragma unroll
            for (int j = 0; j < 4; j++) acc[i][j] = make_float4(0.f, 0.f, 0.f, 0.f);

        float4 wv[4];
#pragma unroll
        for (int r = 0; r < 4; r++) {
            int fid = tid + r * 256;
            int row = fid >> 3, c4 = fid & 7;
            wv[r] = *reinterpret_cast<const float4*>(&Wp[(size_t)row * ldw + 0 + 4 * c4]);
        }
#pragma unroll
        for (int r = 0; r < 4; r++) {
            int fid = tid + r * 256;
            int row = fid >> 3, c4 = fid & 7;
            uint32_t* dst = &Wsm[row * SW];
            dst[ipos(4 * c4 + 0)] = f2tf(wv[r].x);
            dst[ipos(4 * c4 + 1)] = f2tf(wv[r].y);
            dst[ipos(4 * c4 + 2)] = f2tf(wv[r].z);
            dst[ipos(4 * c4 + 3)] = f2tf(wv[r].w);
        }
        __syncthreads();

        for (int c = 0; c < NCHK; c++) {
            if (c + 1 < NCHK) {
#pragma unroll
                for (int r = 0; r < 4; r++) {
                    int fid = tid + r * 256;
                    int row = fid >> 3, c4 = fid & 7;
                    wv[r] = *reinterpret_cast<const float4*>(
                        &Wp[(size_t)row * ldw + (c + 1) * 32 + 4 * c4]);
                }
            }

            const uint32_t* Wb = &Wsm[(c & 1) * 128 * SW];
#pragma unroll
            for (int kk = 0; kk < 32; kk += 8) {
                int aoff = c * 32 + kk + 2 * tig;
                uint2 a[4][2];
#pragma unroll
                for (int mt = 0; mt < 4; mt++) {
                    int r0 = wm * 64 + mt * 16 + qr;
                    a[mt][0] = *reinterpret_cast<const uint2*>(&Asm[r0 * SA + aoff]);
                    a[mt][1] = *reinterpret_cast<const uint2*>(&Asm[(r0 + 8) * SA + aoff]);
                }
                uint2 b[4];
#pragma unroll
                for (int nt = 0; nt < 4; nt++) {
                    int n0 = wn * 32 + nt * 8 + qr;
                    b[nt] = *reinterpret_cast<const uint2*>(&Wb[n0 * SW + kk + 2 * tig]);
                }
#pragma unroll
                for (int mt = 0; mt < 4; mt++)
#pragma unroll
                    for (int nt = 0; nt < 4; nt++)
                        mma_tf32(acc[mt][nt], a[mt][0], a[mt][1], b[nt]);
            }

            if (c + 1 < NCHK) {
                uint32_t* Wn = &Wsm[((c + 1) & 1) * 128 * SW];
#pragma unroll
                for (int r = 0; r < 4; r++) {
                    int fid = tid + r * 256;
                    int row = fid >> 3, c4 = fid & 7;
                    uint32_t* dst = &Wn[row * SW];
                    dst[ipos(4 * c4 + 0)] = f2tf(wv[r].x);
                    dst[ipos(4 * c4 + 1)] = f2tf(wv[r].y);
                    dst[ipos(4 * c4 + 2)] = f2tf(wv[r].z);
                    dst[ipos(4 * c4 + 3)] = f2tf(wv[r].w);
                }
            }
            __syncthreads();
        }

#pragma unroll
        for (int mt = 0; mt < 4; mt++) {
            int row = bm + wm * 64 + mt * 16 + qr;
#pragma unroll
            for (int nt = 0; nt < 4; nt++) {
                int col = colbase + wn * 32 + nt * 8 + 2 * tig;
                if (isL) {
                    if (row < M)
                        *reinterpret_cast<__half2*>(&Cl[(size_t)row * NHALF + col]) =
                            __floats2half2_rn(acc[mt][nt].x, acc[mt][nt].y);
                    if (row + 8 < M)
                        *reinterpret_cast<__half2*>(&Cl[(size_t)(row + 8) * NHALF + col]) =
                            __floats2half2_rn(acc[mt][nt].z, acc[mt][nt].w);
                } else {
                    if (row < M)
                        *reinterpret_cast<float2*>(&Cr[(size_t)row * NHALF + col]) =
                            make_float2(acc[mt][nt].x, acc[mt][nt].y);
                    if (row + 8 < M)
                        *reinterpret_cast<float2*>(&Cr[(size_t)(row + 8) * NHALF + col]) =
                            make_float2(acc[mt][nt].z, acc[mt][nt].w);
                }
            }
        }
        __syncthreads();
    }
}

// ---------------- aggregation + epilogue (fp16 gather, fp32 accumulate) ------
// One warp per node, F = 32*HL columns. HL = halves per lane (8 for 256, 4 for 128).
template <int HL, bool RELU>
__global__ void k_agg_h(const __half* __restrict__ y, const float* __restrict__ r,
                        const float* __restrict__ bias, float* __restrict__ outp) {
    int warp = (blockIdx.x * blockDim.x + threadIdx.x) >> 5;
    int lane = threadIdx.x & 31;
    if (warp >= NN) return;
    const int n = warp;
    const int F = 32 * HL;
    int beg = g_off[n];
    int c = g_cnt[n];
    const int fo = lane * HL;

    float a0[HL], a1[HL];
#pragma unroll
    for (int q = 0; q < HL; q++) { a0[q] = 0.f; a1[q] = 0.f; }

    int i = 0;
    for (; i + 2 <= c; i += 2) {
        int s0 = g_src[beg + i];
        int s1 = g_src[beg + i + 1];
        __half2 t0[HL / 2], t1[HL / 2];
        *reinterpret_cast<uint4*>(t0) = (HL == 8)
            ? *reinterpret_cast<const uint4*>(&y[(size_t)s0 * F + fo])
            : make_uint4(0, 0, 0, 0);
        if (HL == 4)
            *reinterpret_cast<uint2*>(t0) = *reinterpret_cast<const uint2*>(&y[(size_t)s0 * F + fo]);
        if (HL == 8)
            *reinterpret_cast<uint4*>(t1) = *reinterpret_cast<const uint4*>(&y[(size_t)s1 * F + fo]);
        else
            *reinterpret_cast<uint2*>(t1) = *reinterpret_cast<const uint2*>(&y[(size_t)s1 * F + fo]);
#pragma unroll
        for (int q = 0; q < HL / 2; q++) {
            float2 f0 = __half22float2(t0[q]);
            float2 f1 = __half22float2(t1[q]);
            a0[2 * q] += f0.x; a0[2 * q + 1] += f0.y;
            a1[2 * q] += f1.x; a1[2 * q + 1] += f1.y;
        }
    }
    if (i < c) {
        int s = g_src[beg + i];
        __half2 t[HL / 2];
        if (HL == 8)
            *reinterpret_cast<uint4*>(t) = *reinterpret_cast<const uint4*>(&y[(size_t)s * F + fo]);
        else
            *reinterpret_cast<uint2*>(t) = *reinterpret_cast<const uint2*>(&y[(size_t)s * F + fo]);
#pragma unroll
        for (int q = 0; q < HL / 2; q++) {
            float2 f = __half22float2(t[q]);
            a0[2 * q] += f.x; a0[2 * q + 1] += f.y;
        }
    }

    float inv = 1.f / (float)(c > 0 ? c : 1);
#pragma unroll
    for (int q = 0; q < HL; q += 4) {
        float4 rr = *reinterpret_cast<const float4*>(&r[(size_t)n * F + fo + q]);
        float4 bb = *reinterpret_cast<const float4*>(&bias[fo + q]);
        float4 o;
        o.x = (a0[q + 0] + a1[q + 0]) * inv + bb.x + rr.x;
        o.y = (a0[q + 1] + a1[q + 1]) * inv + bb.y + rr.y;
        o.z = (a0[q + 2] + a1[q + 2]) * inv + bb.z + rr.z;
        o.w = (a0[q + 3] + a1[q + 3]) * inv + bb.w + rr.w;
        if (RELU) {
            o.x = fmaxf(o.x, 0.f); o.y = fmaxf(o.y, 0.f);
            o.z = fmaxf(o.z, 0.f); o.w = fmaxf(o.w, 0.f);
        }
        *reinterpret_cast<float4*>(&outp[(size_t)n * F + fo + q]) = o;
    }
}

// ---------------- edge decoder (CSR-grouped by dst; u fp16) -------------------
__global__ void k_edge_csr(const __half* __restrict__ u_, const float* __restrict__ v_,
                           const float* __restrict__ bd1, const float* __restrict__ wd2,
                           const float* __restrict__ bd2, float* __restrict__ out) {
    int warp = (blockIdx.x * blockDim.x + threadIdx.x) >> 5;
    int lane = threadIdx.x & 31;
    if (warp >= NN) return;
    const int n = warp;
    int beg = g_off[n];
    int c = g_cnt[n];
    if (c == 0) return;

    float4 b = reinterpret_cast<const float4*>(bd1)[lane];
    float4 w = reinterpret_cast<const float4*>(wd2)[lane];
    float b2 = *bd2;
    float4 vv = reinterpret_cast<const float4*>(v_ + (size_t)n * 128)[lane];
    float4 vb = make_float4(vv.x + b.x, vv.y + b.y, vv.z + b.z, vv.w + b.w);

#pragma unroll 2
    for (int i = 0; i < c; i++) {
        int s = g_src[beg + i];
        int eid = g_eid[beg + i];
        __half2 uh[2];
        *reinterpret_cast<uint2*>(uh) =
            *reinterpret_cast<const uint2*>(&u_[(size_t)s * 128 + lane * 4]);
        float2 u01 = __half22float2(uh[0]);
        float2 u23 = __half22float2(uh[1]);
        float t, sum = 0.f;
        t = fmaxf(u01.x + vb.x, 0.f); sum = fmaf(t, w.x, sum);
        t = fmaxf(u01.y + vb.y, 0.f); sum = fmaf(t, w.y, sum);
        t = fmaxf(u23.x + vb.z, 0.f); sum = fmaf(t, w.z, sum);
        t = fmaxf(u23.y + vb.w, 0.f); sum = fmaf(t, w.w, sum);
#pragma unroll
        for (int off = 16; off > 0; off >>= 1)
            sum += __shfl_xor_sync(0xFFFFFFFFu, sum, off);
        if (lane == 0) out[eid] = sum + b2;
    }
}

// ---------------- launch -----------------------------------------------------
extern "C" void kernel_launch(void* const* d_in, const int* in_sizes, int n_in,
                              void* d_out, int out_size) {
    const float* x       = (const float*)d_in[0];
    const void*  ei      = (const void*)d_in[1];
    const float* W1l     = (const float*)d_in[2];
    const float* b1l     = (const float*)d_in[3];
    const float* W1r     = (const float*)d_in[4];
    const float* W2l     = (const float*)d_in[5];
    const float* b2l     = (const float*)d_in[6];
    const float* W2r     = (const float*)d_in[7];
    const float* Wd1     = (const float*)d_in[8];
    const float* bd1     = (const float*)d_in[9];
    const float* Wd2     = (const float*)d_in[10];
    const float* bd2     = (const float*)d_in[11];
    float* out           = (float*)d_out;

    __half* yh;
    float *bufB, *h, *z;
    cudaGetSymbolAddress((void**)&yh, g_yh);
    cudaGetSymbolAddress((void**)&bufB, g_bufB);
    cudaGetSymbolAddress((void**)&h, g_h);
    cudaGetSymbolAddress((void**)&z, g_z);

    const int smemK256 = (128 * (256 + 8) + 2 * 128 * 40) * 4;  // 176128
    const int smemK128 = (128 * (128 + 8) + 2 * 128 * 40) * 4;  // 110592
    cudaFuncSetAttribute(k_gemm_mma<256, 4>, cudaFuncAttributeMaxDynamicSharedMemorySize, smemK256);
    cudaFuncSetAttribute(k_gemm_mma<256, 2>, cudaFuncAttributeMaxDynamicSharedMemorySize, smemK256);
    cudaFuncSetAttribute(k_gemm_mma<128, 2>, cudaFuncAttributeMaxDynamicSharedMemorySize, smemK128);

    const int MT = (NN + 127) / 128;              // 782
    const int AGG_GRID = (NN * 32 + 255) / 256;   // warp per node

    // ---- fork: CSR build on side stream, GEMM1 on main stream ----
    cudaStream_t s2 = g_ss.s;
    cudaEventRecord(g_ss.fork, 0);
    cudaStreamWaitEvent(s2, g_ss.fork, 0);

    k_detect<<<1, 32, 0, s2>>>((const int*)ei);
    k_zero_cnt<<<(NN + 255) / 256, 256, 0, s2>>>();
    k_cvt_hist<<<(NE + 255) / 256, 256, 0, s2>>>(ei);
    k_scanA<<<SCAN_B, 256, 0, s2>>>();
    k_scanB<<<1, 512, 0, s2>>>();
    k_scanC<<<SCAN_B, 256, 0, s2>>>();
    k_scatter<<<(NE + 255) / 256, 256, 0, s2>>>();
    cudaEventRecord(g_ss.join, s2);

    // main stream: conv1 GEMMs (y1 fp16, r1 fp32)
    k_gemm_mma<256, 4><<<MT, 256, smemK256>>>(x, W1l, W1r, 256, yh, bufB, NN, 256);

    // join: agg needs CSR + GEMM1
    cudaStreamWaitEvent(0, g_ss.join, 0);

    // conv1 aggregation: single pass (y1 fp16 = 50MB, L2-resident)
    k_agg_h<8, true><<<AGG_GRID, 256>>>(yh, bufB, b1l, h);

    // conv2 (y2 fp16, r2 fp32)
    k_gemm_mma<256, 2><<<MT, 256, smemK256>>>(h, W2l, W2r, 256, yh, bufB, NN, 128);
    k_agg_h<4, false><<<AGG_GRID, 256>>>(yh, bufB, b2l, z);

    // decoder precompute: u (fp16) = z@A^T, v (fp32) = z@B^T
    k_gemm_mma<128, 2><<<MT, 256, smemK128>>>(z, Wd1, Wd1 + 128, 256, yh, bufB, NN, 128);

    // per-edge (CSR-grouped): out = Wd2 . relu(u[src]+v[dst]+bd1) + bd2
    k_edge_csr<<<AGG_GRID, 256>>>(yh, bufB, bd1, Wd2, bd2, out);
}

// round 9
// speedup vs baseline: 2.8790x; 1.3585x over previous
#include <cuda_runtime.h>
#include <cuda_fp16.h>
#include <cstdint>
#include <cstdio>

#define NN 100000
#define NE 1600000
#define SCAN_B 391          // ceil(NN/256)

// ---------------- scratch ----------------------------------------------------
__device__ int    g_is64;
__device__ int    g_esrc[NE];
__device__ int    g_edst[NE];
__device__ int    g_cnt[NN];
__device__ int    g_off[NN];
__device__ int    g_cur[NN];
__device__ int    g_src[NE];
__device__ int    g_eid[NE];
__device__ int    g_bsum[SCAN_B];
__device__ int    g_bpre[SCAN_B];
__device__ __half g_yh[(size_t)NN * 256];   // gathered: y1 / y2 / u
__device__ __half g_rh[(size_t)NN * 256];   // streamed: r1 / r2 / v
__device__ __half g_hh[(size_t)NN * 256];   // h
__device__ __half g_zh[(size_t)NN * 128];   // z

// ---------------- side stream for CSR/GEMM overlap ---------------------------
struct SideStream {
    cudaStream_t s = nullptr;
    cudaEvent_t fork = nullptr, join = nullptr;
    SideStream() {
        cudaStreamCreateWithFlags(&s, cudaStreamNonBlocking);
        cudaEventCreateWithFlags(&fork, cudaEventDisableTiming);
        cudaEventCreateWithFlags(&join, cudaEventDisableTiming);
    }
};
static SideStream g_ss;

// ---------------- helpers ----------------------------------------------------
__device__ __forceinline__ uint32_t h2u(float x, float y) {
    __half2 h = __floats2half2_rn(x, y);
    return *reinterpret_cast<uint32_t*>(&h);
}
__device__ __forceinline__ float2 u2f(uint32_t u) {
    __half2 h = *reinterpret_cast<__half2*>(&u);
    return __half22float2(h);
}
// interleave position of 32-bit word w (0..7) in a 16-col group: pairs (w, w+4) adjacent
__device__ __forceinline__ int iposl(int w) {
    return 2 * (w & 3) + ((w >> 2) & 1);
}

__device__ __forceinline__ void mma_f16(float4& c, uint2 a02, uint2 a13, uint2 b) {
    asm volatile(
        "mma.sync.aligned.m16n8k16.row.col.f32.f16.f16.f32 "
        "{%0,%1,%2,%3}, {%4,%5,%6,%7}, {%8,%9}, {%0,%1,%2,%3};"
        : "+f"(c.x), "+f"(c.y), "+f"(c.z), "+f"(c.w)
        : "r"(a02.x), "r"(a13.x), "r"(a02.y), "r"(a13.y), "r"(b.x), "r"(b.y));
}

// ---------------- edge index dtype detection + normalization ----------------
__global__ void k_detect(const int* __restrict__ p) {
    if (threadIdx.x == 0 && blockIdx.x == 0) {
        int odd_nonzero = 0;
        for (int i = 0; i < 1024; i++) {
            if (p[2 * i + 1] != 0) { odd_nonzero = 1; break; }
        }
        g_is64 = odd_nonzero ? 0 : 1;
    }
}

__global__ void k_cvt_hist(const void* __restrict__ ei) {
    int e = blockIdx.x * blockDim.x + threadIdx.x;
    if (e >= NE) return;
    int s, d;
    if (g_is64) {
        const long long* p = (const long long*)ei;
        s = (int)p[e];
        d = (int)p[NE + e];
    } else {
        const int* p = (const int*)ei;
        s = p[e];
        d = p[NE + e];
    }
    g_esrc[e] = s;
    g_edst[e] = d;
    atomicAdd(&g_cnt[d], 1);
}

__global__ void k_zero_cnt() {
    int i = blockIdx.x * blockDim.x + threadIdx.x;
    if (i < NN) g_cnt[i] = 0;
}

// ---------------- multi-block exclusive scan (3 phases) ----------------------
__global__ void k_scanA() {
    int i = blockIdx.x * 256 + threadIdx.x;
    int v = (i < NN) ? g_cnt[i] : 0;
    int lane = threadIdx.x & 31;
    int wid = threadIdx.x >> 5;
#pragma unroll
    for (int off = 16; off > 0; off >>= 1)
        v += __shfl_xor_sync(0xFFFFFFFFu, v, off);
    __shared__ int ws[8];
    if (lane == 0) ws[wid] = v;
    __syncthreads();
    if (threadIdx.x == 0) {
        int s = 0;
#pragma unroll
        for (int w = 0; w < 8; w++) s += ws[w];
        g_bsum[blockIdx.x] = s;
    }
}

__global__ void k_scanB() {
    __shared__ int ws[16];
    const int t = threadIdx.x;           // 512 threads
    int v = (t < SCAN_B) ? g_bsum[t] : 0;
    int lane = t & 31, wid = t >> 5;
    int x = v;
#pragma unroll
    for (int off = 1; off < 32; off <<= 1) {
        int y = __shfl_up_sync(0xFFFFFFFFu, x, off);
        if (lane >= off) x += y;
    }
    if (lane == 31) ws[wid] = x;
    __syncthreads();
    int base = 0;
    for (int w = 0; w < wid; w++) base += ws[w];
    if (t < SCAN_B) g_bpre[t] = base + x - v;   // exclusive prefix
}

__global__ void k_scanC() {
    __shared__ int ws[8];
    int i = blockIdx.x * 256 + threadIdx.x;
    int v = (i < NN) ? g_cnt[i] : 0;
    int lane = threadIdx.x & 31, wid = threadIdx.x >> 5;
    int x = v;
#pragma unroll
    for (int off = 1; off < 32; off <<= 1) {
        int y = __shfl_up_sync(0xFFFFFFFFu, x, off);
        if (lane >= off) x += y;
    }
    if (lane == 31) ws[wid] = x;
    __syncthreads();
    int base = g_bpre[blockIdx.x];
    for (int w = 0; w < wid; w++) base += ws[w];
    if (i < NN) {
        int off = base + x - v;
        g_off[i] = off;
        g_cur[i] = off;
    }
}

__global__ void k_scatter() {
    int e = blockIdx.x * blockDim.x + threadIdx.x;
    if (e < NE) {
        int pos = atomicAdd(&g_cur[g_edst[e]], 1);
        g_src[pos] = g_esrc[e];
        g_eid[pos] = e;
    }
}

// ---------------- fused dual-GEMM via mma.sync fp16 (fp32 accum) --------------
// Cl[M,NHALF] = A@Wl^T (fp16 out), Cr = A@Wr^T (fp16 out). NTOT = NBLK*128.
// A resident in SMEM (fp16 words, pair-interleaved); W streamed in 32-col chunks.
// 8 warps = 2(m) x 4(n), each warp 64x32 via m16n8k16.
template <int K, int NBLK, bool AF16>
__global__ void __launch_bounds__(256)
k_gemm_mma(const void* __restrict__ A,
           const float* __restrict__ Wl, const float* __restrict__ Wr, int ldw,
           __half* __restrict__ Cl, __half* __restrict__ Cr, int M, int NHALF) {
    constexpr int SA = K / 2 + 4;   // A row stride (32-bit words)
    constexpr int SW = 20;          // W row stride (words; 16 data + 4 pad)
    constexpr int NCHK = K / 32;    // K chunks (32 cols = 2 groups of 16)
    extern __shared__ uint32_t smem[];
    uint32_t* Asm = smem;                        // 128 * SA
    uint32_t* Wsm = smem + 128 * SA;             // 2 * 128 * SW

    const int tid = threadIdx.x;
    const int wid = tid >> 5;
    const int lane = tid & 31;
    const int wm = wid >> 2;        // 0..1 -> m offset wm*64
    const int wn = wid & 3;         // 0..3 -> n offset wn*32
    const int qr = lane >> 2;       // 0..7
    const int tig = lane & 3;       // 0..3
    const int bm = blockIdx.x * 128;

    // ---- load A (128 x K) into SMEM as fp16 words, group-interleaved ----
    for (int it = tid; it < 128 * (K / 16); it += 256) {
        int row = it / (K / 16);
        int g = it % (K / 16);
        uint32_t w[8];
        if (AF16) {
            const __half* Ah = (const __half*)A;
            uint4 v0 = make_uint4(0, 0, 0, 0), v1 = make_uint4(0, 0, 0, 0);
            if (bm + row < M) {
                v0 = *reinterpret_cast<const uint4*>(&Ah[(size_t)(bm + row) * K + g * 16]);
                v1 = *reinterpret_cast<const uint4*>(&Ah[(size_t)(bm + row) * K + g * 16 + 8]);
            }
            w[0] = v0.x; w[1] = v0.y; w[2] = v0.z; w[3] = v0.w;
            w[4] = v1.x; w[5] = v1.y; w[6] = v1.z; w[7] = v1.w;
        } else {
            const float* Af = (const float*)A;
#pragma unroll
            for (int q = 0; q < 4; q++) {
                float4 f = make_float4(0.f, 0.f, 0.f, 0.f);
                if (bm + row < M)
                    f = *reinterpret_cast<const float4*>(&Af[(size_t)(bm + row) * K + g * 16 + q * 4]);
                w[2 * q]     = h2u(f.x, f.y);
                w[2 * q + 1] = h2u(f.z, f.w);
            }
        }
        uint32_t* dst = &Asm[row * SA + g * 8];
#pragma unroll
        for (int q = 0; q < 8; q++) dst[iposl(q)] = w[q];
    }
    __syncthreads();

    // W chunk loader mapping: thread -> (row, group)
    const int lrow = tid >> 1;      // 0..127
    const int lg = tid & 1;         // 0..1

    for (int nb = 0; nb < NBLK; nb++) {
        const float* Wp;
        int colbase;
        const bool isL = (nb * 128 < NHALF);
        if (isL) { Wp = Wl + (size_t)(nb * 128) * ldw; colbase = nb * 128; }
        else     { Wp = Wr + (size_t)(nb * 128 - NHALF) * ldw; colbase = nb * 128 - NHALF; }
        __half* Cp = isL ? Cl : Cr;

        float4 acc[4][4];
#pragma unroll
        for (int i = 0; i < 4; i++)
#pragma unroll
            for (int j = 0; j < 4; j++) acc[i][j] = make_float4(0.f, 0.f, 0.f, 0.f);

        // prefetch chunk 0 (16 floats per thread), store to buf 0
        float4 wv[4];
#pragma unroll
        for (int q = 0; q < 4; q++)
            wv[q] = *reinterpret_cast<const float4*>(&Wp[(size_t)lrow * ldw + lg * 16 + q * 4]);
        {
            uint32_t* dst = &Wsm[lrow * SW + lg * 8];
#pragma unroll
            for (int q = 0; q < 4; q++) {
                dst[iposl(2 * q)]     = h2u(wv[q].x, wv[q].y);
                dst[iposl(2 * q + 1)] = h2u(wv[q].z, wv[q].w);
            }
        }
        __syncthreads();

        for (int c = 0; c < NCHK; c++) {
            if (c + 1 < NCHK) {
#pragma unroll
                for (int q = 0; q < 4; q++)
                    wv[q] = *reinterpret_cast<const float4*>(
                        &Wp[(size_t)lrow * ldw + (c + 1) * 32 + lg * 16 + q * 4]);
            }

            const uint32_t* Wb = &Wsm[(c & 1) * 128 * SW];
#pragma unroll
            for (int g2 = 0; g2 < 2; g2++) {
                const int gw = c * 16 + g2 * 8 + 2 * tig;
                uint2 a[4][2];
#pragma unroll
                for (int mt = 0; mt < 4; mt++) {
                    int r0 = wm * 64 + mt * 16 + qr;
                    a[mt][0] = *reinterpret_cast<const uint2*>(&Asm[r0 * SA + gw]);
                    a[mt][1] = *reinterpret_cast<const uint2*>(&Asm[(r0 + 8) * SA + gw]);
                }
                uint2 b[4];
#pragma unroll
                for (int nt = 0; nt < 4; nt++) {
                    int n0 = wn * 32 + nt * 8 + qr;
                    b[nt] = *reinterpret_cast<const uint2*>(&Wb[n0 * SW + g2 * 8 + 2 * tig]);
                }
#pragma unroll
                for (int mt = 0; mt < 4; mt++)
#pragma unroll
                    for (int nt = 0; nt < 4; nt++)
                        mma_f16(acc[mt][nt], a[mt][0], a[mt][1], b[nt]);
            }

            if (c + 1 < NCHK) {
                uint32_t* Wn = &Wsm[((c + 1) & 1) * 128 * SW];
                uint32_t* dst = &Wn[lrow * SW + lg * 8];
#pragma unroll
                for (int q = 0; q < 4; q++) {
                    dst[iposl(2 * q)]     = h2u(wv[q].x, wv[q].y);
                    dst[iposl(2 * q + 1)] = h2u(wv[q].z, wv[q].w);
                }
            }
            __syncthreads();
        }

        // epilogue: fp16 outputs
#pragma unroll
        for (int mt = 0; mt < 4; mt++) {
            int row = bm + wm * 64 + mt * 16 + qr;
#pragma unroll
            for (int nt = 0; nt < 4; nt++) {
                int col = colbase + wn * 32 + nt * 8 + 2 * tig;
                if (row < M)
                    *reinterpret_cast<uint32_t*>(&Cp[(size_t)row * NHALF + col]) =
                        h2u(acc[mt][nt].x, acc[mt][nt].y);
                if (row + 8 < M)
                    *reinterpret_cast<uint32_t*>(&Cp[(size_t)(row + 8) * NHALF + col]) =
                        h2u(acc[mt][nt].z, acc[mt][nt].w);
            }
        }
        __syncthreads();
    }
}

// ---------------- aggregation + epilogue (fp16 in/out, fp32 accumulate) ------
// One warp per node, F = 32*HL halves. HL = 8 (F=256) or 4 (F=128).
template <int HL, bool RELU>
__global__ void k_agg_h(const __half* __restrict__ y, const __half* __restrict__ r,
                        const float* __restrict__ bias, __half* __restrict__ outp) {
    int warp = (blockIdx.x * blockDim.x + threadIdx.x) >> 5;
    int lane = threadIdx.x & 31;
    if (warp >= NN) return;
    const int n = warp;
    const int F = 32 * HL;
    int beg = g_off[n];
    int c = g_cnt[n];
    const int fo = lane * HL;

    float a0[HL], a1[HL];
#pragma unroll
    for (int q = 0; q < HL; q++) { a0[q] = 0.f; a1[q] = 0.f; }

    int i = 0;
    for (; i + 2 <= c; i += 2) {
        int s0 = g_src[beg + i];
        int s1 = g_src[beg + i + 1];
        uint32_t t0[HL / 2], t1[HL / 2];
        if (HL == 8) {
            *reinterpret_cast<uint4*>(t0) = *reinterpret_cast<const uint4*>(&y[(size_t)s0 * F + fo]);
            *reinterpret_cast<uint4*>(t1) = *reinterpret_cast<const uint4*>(&y[(size_t)s1 * F + fo]);
        } else {
            *reinterpret_cast<uint2*>(t0) = *reinterpret_cast<const uint2*>(&y[(size_t)s0 * F + fo]);
            *reinterpret_cast<uint2*>(t1) = *reinterpret_cast<const uint2*>(&y[(size_t)s1 * F + fo]);
        }
#pragma unroll
        for (int q = 0; q < HL / 2; q++) {
            float2 f0 = u2f(t0[q]);
            float2 f1 = u2f(t1[q]);
            a0[2 * q] += f0.x; a0[2 * q + 1] += f0.y;
            a1[2 * q] += f1.x; a1[2 * q + 1] += f1.y;
        }
    }
    if (i < c) {
        int s = g_src[beg + i];
        uint32_t t[HL / 2];
        if (HL == 8)
            *reinterpret_cast<uint4*>(t) = *reinterpret_cast<const uint4*>(&y[(size_t)s * F + fo]);
        else
            *reinterpret_cast<uint2*>(t) = *reinterpret_cast<const uint2*>(&y[(size_t)s * F + fo]);
#pragma unroll
        for (int q = 0; q < HL / 2; q++) {
            float2 f = u2f(t[q]);
            a0[2 * q] += f.x; a0[2 * q + 1] += f.y;
        }
    }

    float inv = 1.f / (float)(c > 0 ? c : 1);
    uint32_t rw[HL / 2], ow[HL / 2];
    if (HL == 8)
        *reinterpret_cast<uint4*>(rw) = *reinterpret_cast<const uint4*>(&r[(size_t)n * F + fo]);
    else
        *reinterpret_cast<uint2*>(rw) = *reinterpret_cast<const uint2*>(&r[(size_t)n * F + fo]);
#pragma unroll
    for (int q = 0; q < HL / 2; q++) {
        float2 rr = u2f(rw[q]);
        float bx = bias[fo + 2 * q];
        float by = bias[fo + 2 * q + 1];
        float ox = (a0[2 * q] + a1[2 * q]) * inv + bx + rr.x;
        float oy = (a0[2 * q + 1] + a1[2 * q + 1]) * inv + by + rr.y;
        if (RELU) { ox = fmaxf(ox, 0.f); oy = fmaxf(oy, 0.f); }
        ow[q] = h2u(ox, oy);
    }
    if (HL == 8)
        *reinterpret_cast<uint4*>(&outp[(size_t)n * F + fo]) = *reinterpret_cast<uint4*>(ow);
    else
        *reinterpret_cast<uint2*>(&outp[(size_t)n * F + fo]) = *reinterpret_cast<uint2*>(ow);
}

// ---------------- edge decoder (CSR-grouped by dst; u,v fp16) -----------------
__global__ void k_edge_csr(const __half* __restrict__ u_, const __half* __restrict__ v_,
                           const float* __restrict__ bd1, const float* __restrict__ wd2,
                           const float* __restrict__ bd2, float* __restrict__ out) {
    int warp = (blockIdx.x * blockDim.x + threadIdx.x) >> 5;
    int lane = threadIdx.x & 31;
    if (warp >= NN) return;
    const int n = warp;
    int beg = g_off[n];
    int c = g_cnt[n];
    if (c == 0) return;

    float4 b = reinterpret_cast<const float4*>(bd1)[lane];
    float4 w = reinterpret_cast<const float4*>(wd2)[lane];
    float b2 = *bd2;
    uint32_t vw[2];
    *reinterpret_cast<uint2*>(vw) = *reinterpret_cast<const uint2*>(&v_[(size_t)n * 128 + lane * 4]);
    float2 v01 = u2f(vw[0]);
    float2 v23 = u2f(vw[1]);
    float4 vb = make_float4(v01.x + b.x, v01.y + b.y, v23.x + b.z, v23.y + b.w);

#pragma unroll 2
    for (int i = 0; i < c; i++) {
        int s = g_src[beg + i];
        int eid = g_eid[beg + i];
        uint32_t uw[2];
        *reinterpret_cast<uint2*>(uw) =
            *reinterpret_cast<const uint2*>(&u_[(size_t)s * 128 + lane * 4]);
        float2 u01 = u2f(uw[0]);
        float2 u23 = u2f(uw[1]);
        float t, sum = 0.f;
        t = fmaxf(u01.x + vb.x, 0.f); sum = fmaf(t, w.x, sum);
        t = fmaxf(u01.y + vb.y, 0.f); sum = fmaf(t, w.y, sum);
        t = fmaxf(u23.x + vb.z, 0.f); sum = fmaf(t, w.z, sum);
        t = fmaxf(u23.y + vb.w, 0.f); sum = fmaf(t, w.w, sum);
#pragma unroll
        for (int off = 16; off > 0; off >>= 1)
            sum += __shfl_xor_sync(0xFFFFFFFFu, sum, off);
        if (lane == 0) out[eid] = sum + b2;
    }
}

// ---------------- launch -----------------------------------------------------
extern "C" void kernel_launch(void* const* d_in, const int* in_sizes, int n_in,
                              void* d_out, int out_size) {
    const float* x       = (const float*)d_in[0];
    const void*  ei      = (const void*)d_in[1];
    const float* W1l     = (const float*)d_in[2];
    const float* b1l     = (const float*)d_in[3];
    const float* W1r     = (const float*)d_in[4];
    const float* W2l     = (const float*)d_in[5];
    const float* b2l     = (const float*)d_in[6];
    const float* W2r     = (const float*)d_in[7];
    const float* Wd1     = (const float*)d_in[8];
    const float* bd1     = (const float*)d_in[9];
    const float* Wd2     = (const float*)d_in[10];
    const float* bd2     = (const float*)d_in[11];
    float* out           = (float*)d_out;

    __half *yh, *rh, *hh, *zh;
    cudaGetSymbolAddress((void**)&yh, g_yh);
    cudaGetSymbolAddress((void**)&rh, g_rh);
    cudaGetSymbolAddress((void**)&hh, g_hh);
    cudaGetSymbolAddress((void**)&zh, g_zh);

    const int smemK256 = (128 * (256 / 2 + 4) + 2 * 128 * 20) * 4;  // 88064
    const int smemK128 = (128 * (128 / 2 + 4) + 2 * 128 * 20) * 4;  // 55296
    cudaFuncSetAttribute(k_gemm_mma<256, 4, false>, cudaFuncAttributeMaxDynamicSharedMemorySize, smemK256);
    cudaFuncSetAttribute(k_gemm_mma<256, 2, true>,  cudaFuncAttributeMaxDynamicSharedMemorySize, smemK256);
    cudaFuncSetAttribute(k_gemm_mma<128, 2, true>,  cudaFuncAttributeMaxDynamicSharedMemorySize, smemK128);

    const int MT = (NN + 127) / 128;              // 782
    const int AGG_GRID = (NN * 32 + 255) / 256;   // warp per node

    // ---- fork: CSR build on side stream, GEMM1 on main stream ----
    cudaStream_t s2 = g_ss.s;
    cudaEventRecord(g_ss.fork, 0);
    cudaStreamWaitEvent(s2, g_ss.fork, 0);

    k_detect<<<1, 32, 0, s2>>>((const int*)ei);
    k_zero_cnt<<<(NN + 255) / 256, 256, 0, s2>>>();
    k_cvt_hist<<<(NE + 255) / 256, 256, 0, s2>>>(ei);
    k_scanA<<<SCAN_B, 256, 0, s2>>>();
    k_scanB<<<1, 512, 0, s2>>>();
    k_scanC<<<SCAN_B, 256, 0, s2>>>();
    k_scatter<<<(NE + 255) / 256, 256, 0, s2>>>();
    cudaEventRecord(g_ss.join, s2);

    // main stream: conv1 GEMMs (A = x fp32; outputs y1, r1 fp16)
    k_gemm_mma<256, 4, false><<<MT, 256, smemK256>>>(x, W1l, W1r, 256, yh, rh, NN, 256);

    // join: agg needs CSR + GEMM1
    cudaStreamWaitEvent(0, g_ss.join, 0);

    // conv1 aggregation -> h (fp16)
    k_agg_h<8, true><<<AGG_GRID, 256>>>(yh, rh, b1l, hh);

    // conv2 (A = h fp16; outputs y2, r2 fp16)
    k_gemm_mma<256, 2, true><<<MT, 256, smemK256>>>(hh, W2l, W2r, 256, yh, rh, NN, 128);
    k_agg_h<4, false><<<AGG_GRID, 256>>>(yh, rh, b2l, zh);

    // decoder precompute: u = z@A^T, v = z@B^T (A = z fp16)
    k_gemm_mma<128, 2, true><<<MT, 256, smemK128>>>(zh, Wd1, Wd1 + 128, 256, yh, rh, NN, 128);

    // per-edge (CSR-grouped): out = Wd2 . relu(u[src]+v[dst]+bd1) + bd2
    k_edge_csr<<<AGG_GRID, 256>>>(yh, rh, bd1, Wd2, bd2, out);
}

// round 11
// speedup vs baseline: 2.9888x; 1.0381x over previous
#include <cuda_runtime.h>
#include <cuda_fp16.h>
#include <cstdint>
#include <cstdio>

#define NN 100000
#define NE 1600000
#define SCAN_B 391          // ceil(NN/256)

// ---------------- scratch ----------------------------------------------------
__device__ int    g_is64;
__device__ int    g_esrc[NE];
__device__ int    g_edst[NE];
__device__ int    g_cnt[NN];
__device__ int    g_off[NN];
__device__ int    g_cur[NN];
__device__ int    g_src[NE];
__device__ int    g_eid[NE];
__device__ int    g_bsum[SCAN_B];
__device__ int    g_bpre[SCAN_B];
__device__ __half g_yh[(size_t)NN * 256];   // gathered: y1 / y2 / u
__device__ __half g_rh[(size_t)NN * 256];   // streamed: r1 / r2 / v
__device__ __half g_hh[(size_t)NN * 256];   // h
__device__ __half g_zh[(size_t)NN * 128];   // z

// ---------------- side stream for CSR/GEMM overlap ---------------------------
struct SideStream {
    cudaStream_t s = nullptr;
    cudaEvent_t fork = nullptr, join = nullptr;
    SideStream() {
        cudaStreamCreateWithFlags(&s, cudaStreamNonBlocking);
        cudaEventCreateWithFlags(&fork, cudaEventDisableTiming);
        cudaEventCreateWithFlags(&join, cudaEventDisableTiming);
    }
};
static SideStream g_ss;

// ---------------- helpers ----------------------------------------------------
__device__ __forceinline__ uint32_t h2u(float x, float y) {
    __half2 h = __floats2half2_rn(x, y);
    return *reinterpret_cast<uint32_t*>(&h);
}
__device__ __forceinline__ float2 u2f(uint32_t u) {
    __half2 h = *reinterpret_cast<__half2*>(&u);
    return __half22float2(h);
}

__device__ __forceinline__ void mma_f16(float4& c, uint32_t a0, uint32_t a1,
                                        uint32_t a2, uint32_t a3,
                                        uint32_t b0, uint32_t b1) {
    asm volatile(
        "mma.sync.aligned.m16n8k16.row.col.f32.f16.f16.f32 "
        "{%0,%1,%2,%3}, {%4,%5,%6,%7}, {%8,%9}, {%0,%1,%2,%3};"
        : "+f"(c.x), "+f"(c.y), "+f"(c.z), "+f"(c.w)
        : "r"(a0), "r"(a1), "r"(a2), "r"(a3), "r"(b0), "r"(b1));
}

__device__ __forceinline__ void ldsm_x4(uint32_t& r0, uint32_t& r1,
                                        uint32_t& r2, uint32_t& r3, uint32_t addr) {
    asm volatile("ldmatrix.sync.aligned.m8n8.x4.shared.b16 {%0,%1,%2,%3}, [%4];"
        : "=r"(r0), "=r"(r1), "=r"(r2), "=r"(r3) : "r"(addr));
}

// ---------------- edge index dtype detection + normalization ----------------
__global__ void k_detect(const int* __restrict__ p) {
    if (threadIdx.x == 0 && blockIdx.x == 0) {
        int odd_nonzero = 0;
        for (int i = 0; i < 1024; i++) {
            if (p[2 * i + 1] != 0) { odd_nonzero = 1; break; }
        }
        g_is64 = odd_nonzero ? 0 : 1;
    }
}

__global__ void k_cvt_hist(const void* __restrict__ ei) {
    int e = blockIdx.x * blockDim.x + threadIdx.x;
    if (e >= NE) return;
    int s, d;
    if (g_is64) {
        const long long* p = (const long long*)ei;
        s = (int)p[e];
        d = (int)p[NE + e];
    } else {
        const int* p = (const int*)ei;
        s = p[e];
        d = p[NE + e];
    }
    g_esrc[e] = s;
    g_edst[e] = d;
    atomicAdd(&g_cnt[d], 1);
}

__global__ void k_zero_cnt() {
    int i = blockIdx.x * blockDim.x + threadIdx.x;
    if (i < NN) g_cnt[i] = 0;
}

// ---------------- multi-block exclusive scan (3 phases) ----------------------
__global__ void k_scanA() {
    int i = blockIdx.x * 256 + threadIdx.x;
    int v = (i < NN) ? g_cnt[i] : 0;
    int lane = threadIdx.x & 31;
    int wid = threadIdx.x >> 5;
#pragma unroll
    for (int off = 16; off > 0; off >>= 1)
        v += __shfl_xor_sync(0xFFFFFFFFu, v, off);
    __shared__ int ws[8];
    if (lane == 0) ws[wid] = v;
    __syncthreads();
    if (threadIdx.x == 0) {
        int s = 0;
#pragma unroll
        for (int w = 0; w < 8; w++) s += ws[w];
        g_bsum[blockIdx.x] = s;
    }
}

__global__ void k_scanB() {
    __shared__ int ws[16];
    const int t = threadIdx.x;           // 512 threads
    int v = (t < SCAN_B) ? g_bsum[t] : 0;
    int lane = t & 31, wid = t >> 5;
    int x = v;
#pragma unroll
    for (int off = 1; off < 32; off <<= 1) {
        int y = __shfl_up_sync(0xFFFFFFFFu, x, off);
        if (lane >= off) x += y;
    }
    if (lane == 31) ws[wid] = x;
    __syncthreads();
    int base = 0;
    for (int w = 0; w < wid; w++) base += ws[w];
    if (t < SCAN_B) g_bpre[t] = base + x - v;   // exclusive prefix
}

__global__ void k_scanC() {
    __shared__ int ws[8];
    int i = blockIdx.x * 256 + threadIdx.x;
    int v = (i < NN) ? g_cnt[i] : 0;
    int lane = threadIdx.x & 31, wid = threadIdx.x >> 5;
    int x = v;
#pragma unroll
    for (int off = 1; off < 32; off <<= 1) {
        int y = __shfl_up_sync(0xFFFFFFFFu, x, off);
        if (lane >= off) x += y;
    }
    if (lane == 31) ws[wid] = x;
    __syncthreads();
    int base = g_bpre[blockIdx.x];
    for (int w = 0; w < wid; w++) base += ws[w];
    if (i < NN) {
        int off = base + x - v;
        g_off[i] = off;
        g_cur[i] = off;
    }
}

__global__ void k_scatter() {
    int e = blockIdx.x * blockDim.x + threadIdx.x;
    if (e < NE) {
        int pos = atomicAdd(&g_cur[g_edst[e]], 1);
        g_src[pos] = g_esrc[e];
        g_eid[pos] = e;
    }
}

// ---------------- fused dual-GEMM via mma.sync fp16 + ldmatrix ----------------
// Cl[M,NHALF] = A@Wl^T (fp16 out), Cr = A@Wr^T. NTOT = NBLK*128.
// A resident in SMEM (plain row-major fp16); W streamed in 32-col chunks.
// 8 warps = 2(m) x 4(n), warp tile 64x32 via m16n8k16; ldmatrix.x4 fragments.
template <int K, int NBLK, bool AF16>
__global__ void __launch_bounds__(256, 2)
k_gemm_mma(const void* __restrict__ A,
           const float* __restrict__ Wl, const float* __restrict__ Wr, int ldw,
           __half* __restrict__ Cl, __half* __restrict__ Cr, int M, int NHALF) {
    constexpr int SA = K / 2 + 4;   // A row stride (32-bit words)
    constexpr int SW = 20;          // W row stride (words)
    constexpr int NCHK = K / 32;    // K chunks (32 cols = 2 groups of 16)
    extern __shared__ uint32_t smem[];
    uint32_t* Asm = smem;                        // 128 * SA
    uint32_t* Wsm = smem + 128 * SA;             // 2 * 128 * SW

    const int tid = threadIdx.x;
    const int wid = tid >> 5;
    const int lane = tid & 31;
    const int wm = wid >> 2;        // 0..1 -> m offset wm*64
    const int wn = wid & 3;         // 0..3 -> n offset wn*32
    const int qr = lane >> 2;       // 0..7
    const int tig = lane & 3;       // 0..3
    const int bm = blockIdx.x * 128;

    // ---- load A (128 x K) into SMEM as fp16, plain row-major ----
    for (int it = tid; it < 128 * (K / 16); it += 256) {
        int row = it / (K / 16);
        int g = it % (K / 16);
        uint32_t w[8];
        if (AF16) {
            const __half* Ah = (const __half*)A;
            uint4 v0 = make_uint4(0, 0, 0, 0), v1 = make_uint4(0, 0, 0, 0);
            if (bm + row < M) {
                v0 = *reinterpret_cast<const uint4*>(&Ah[(size_t)(bm + row) * K + g * 16]);
                v1 = *reinterpret_cast<const uint4*>(&Ah[(size_t)(bm + row) * K + g * 16 + 8]);
            }
            w[0] = v0.x; w[1] = v0.y; w[2] = v0.z; w[3] = v0.w;
            w[4] = v1.x; w[5] = v1.y; w[6] = v1.z; w[7] = v1.w;
        } else {
            const float* Af = (const float*)A;
#pragma unroll
            for (int q = 0; q < 4; q++) {
                float4 f = make_float4(0.f, 0.f, 0.f, 0.f);
                if (bm + row < M)
                    f = *reinterpret_cast<const float4*>(&Af[(size_t)(bm + row) * K + g * 16 + q * 4]);
                w[2 * q]     = h2u(f.x, f.y);
                w[2 * q + 1] = h2u(f.z, f.w);
            }
        }
        uint32_t* dst = &Asm[row * SA + g * 8];
        *reinterpret_cast<uint4*>(dst)     = make_uint4(w[0], w[1], w[2], w[3]);
        *reinterpret_cast<uint4*>(dst + 4) = make_uint4(w[4], w[5], w[6], w[7]);
    }
    __syncthreads();

    // ldmatrix per-lane addresses
    const uint32_t asm_base = (uint32_t)__cvta_generic_to_shared(Asm);
    const uint32_t wsm_base = (uint32_t)__cvta_generic_to_shared(Wsm);
    // A: m0=(rows0-7,klo) m1=(rows8-15,klo) m2=(rows0-7,khi) m3=(rows8-15,khi)
    const int rowA = (lane & 7) | (((lane >> 3) & 1) << 3);
    const int kwA = ((lane >> 4) & 1) * 4;
    uint32_t aAddr[4];
#pragma unroll
    for (int mt = 0; mt < 4; mt++)
        aAddr[mt] = asm_base + (((wm * 64 + mt * 16 + rowA) * SA + kwA) << 2);
    // B: m0=(n0-7,klo) m1=(n0-7,khi) m2=(n8-15,klo) m3=(n8-15,khi)
    const int rowB = (lane & 7) + (((lane >> 4) & 1) << 3);
    const int kwB = ((lane >> 3) & 1) * 4;
    uint32_t bAddr[2];
#pragma unroll
    for (int p = 0; p < 2; p++)
        bAddr[p] = wsm_base + (((wn * 32 + p * 16 + rowB) * SW + kwB) << 2);

    // W chunk loader mapping
    const int lrow = tid >> 1;      // 0..127
    const int lg = tid & 1;         // 0..1

    for (int nb = 0; nb < NBLK; nb++) {
        const float* Wp;
        int colbase;
        const bool isL = (nb * 128 < NHALF);
        if (isL) { Wp = Wl + (size_t)(nb * 128) * ldw; colbase = nb * 128; }
        else     { Wp = Wr + (size_t)(nb * 128 - NHALF) * ldw; colbase = nb * 128 - NHALF; }
        __half* Cp = isL ? Cl : Cr;

        float4 acc[4][4];
#pragma unroll
        for (int i = 0; i < 4; i++)
#pragma unroll
            for (int j = 0; j < 4; j++) acc[i][j] = make_float4(0.f, 0.f, 0.f, 0.f);

        // prefetch chunk 0 (16 floats -> 8 half2 words), store to buf 0
        uint32_t wpre[8];
#pragma unroll
        for (int q = 0; q < 4; q++) {
            float4 f = *reinterpret_cast<const float4*>(&Wp[(size_t)lrow * ldw + lg * 16 + q * 4]);
            wpre[2 * q]     = h2u(f.x, f.y);
            wpre[2 * q + 1] = h2u(f.z, f.w);
        }
        {
            uint32_t* dst = &Wsm[lrow * SW + lg * 8];
            *reinterpret_cast<uint4*>(dst)     = make_uint4(wpre[0], wpre[1], wpre[2], wpre[3]);
            *reinterpret_cast<uint4*>(dst + 4) = make_uint4(wpre[4], wpre[5], wpre[6], wpre[7]);
        }
        __syncthreads();

        for (int c = 0; c < NCHK; c++) {
            if (c + 1 < NCHK) {
#pragma unroll
                for (int q = 0; q < 4; q++) {
                    float4 f = *reinterpret_cast<const float4*>(
                        &Wp[(size_t)lrow * ldw + (c + 1) * 32 + lg * 16 + q * 4]);
                    wpre[2 * q]     = h2u(f.x, f.y);
                    wpre[2 * q + 1] = h2u(f.z, f.w);
                }
            }

            const uint32_t wbuf = (uint32_t)((c & 1) * 128 * SW * 4);
#pragma unroll
            for (int g2 = 0; g2 < 2; g2++) {
                const uint32_t koff = (uint32_t)((c * 16 + g2 * 8) << 2);
                uint32_t a[4][4];
#pragma unroll
                for (int mt = 0; mt < 4; mt++)
                    ldsm_x4(a[mt][0], a[mt][1], a[mt][2], a[mt][3], aAddr[mt] + koff);
                uint32_t b[2][4];
#pragma unroll
                for (int p = 0; p < 2; p++)
                    ldsm_x4(b[p][0], b[p][1], b[p][2], b[p][3],
                            bAddr[p] + wbuf + (uint32_t)((g2 * 8) << 2));
#pragma unroll
                for (int mt = 0; mt < 4; mt++) {
#pragma unroll
                    for (int p = 0; p < 2; p++) {
                        mma_f16(acc[mt][2 * p], a[mt][0], a[mt][1], a[mt][2], a[mt][3],
                                b[p][0], b[p][1]);
                        mma_f16(acc[mt][2 * p + 1], a[mt][0], a[mt][1], a[mt][2], a[mt][3],
                                b[p][2], b[p][3]);
                    }
                }
            }

            if (c + 1 < NCHK) {
                uint32_t* dst = &Wsm[((c + 1) & 1) * 128 * SW + lrow * SW + lg * 8];
                *reinterpret_cast<uint4*>(dst)     = make_uint4(wpre[0], wpre[1], wpre[2], wpre[3]);
                *reinterpret_cast<uint4*>(dst + 4) = make_uint4(wpre[4], wpre[5], wpre[6], wpre[7]);
            }
            __syncthreads();
        }

        // epilogue: fp16 outputs
#pragma unroll
        for (int mt = 0; mt < 4; mt++) {
            int row = bm + wm * 64 + mt * 16 + qr;
#pragma unroll
            for (int nt = 0; nt < 4; nt++) {
                int col = colbase + wn * 32 + nt * 8 + 2 * tig;
                if (row < M)
                    *reinterpret_cast<uint32_t*>(&Cp[(size_t)row * NHALF + col]) =
                        h2u(acc[mt][nt].x, acc[mt][nt].y);
                if (row + 8 < M)
                    *reinterpret_cast<uint32_t*>(&Cp[(size_t)(row + 8) * NHALF + col]) =
                        h2u(acc[mt][nt].z, acc[mt][nt].w);
            }
        }
        __syncthreads();
    }
}

// ---------------- aggregation + epilogue (fp16 in/out, fp32 accumulate) ------
template <int HL, bool RELU>
__global__ void k_agg_h(const __half* __restrict__ y, const __half* __restrict__ r,
                        const float* __restrict__ bias, __half* __restrict__ outp) {
    int warp = (blockIdx.x * blockDim.x + threadIdx.x) >> 5;
    int lane = threadIdx.x & 31;
    if (warp >= NN) return;
    const int n = warp;
    const int F = 32 * HL;
    int beg = g_off[n];
    int c = g_cnt[n];
    const int fo = lane * HL;

    float a0[HL], a1[HL];
#pragma unroll
    for (int q = 0; q < HL; q++) { a0[q] = 0.f; a1[q] = 0.f; }

    int i = 0;
    for (; i + 2 <= c; i += 2) {
        int s0 = g_src[beg + i];
        int s1 = g_src[beg + i + 1];
        uint32_t t0[HL / 2], t1[HL / 2];
        if (HL == 8) {
            *reinterpret_cast<uint4*>(t0) = *reinterpret_cast<const uint4*>(&y[(size_t)s0 * F + fo]);
            *reinterpret_cast<uint4*>(t1) = *reinterpret_cast<const uint4*>(&y[(size_t)s1 * F + fo]);
        } else {
            *reinterpret_cast<uint2*>(t0) = *reinterpret_cast<const uint2*>(&y[(size_t)s0 * F + fo]);
            *reinterpret_cast<uint2*>(t1) = *reinterpret_cast<const uint2*>(&y[(size_t)s1 * F + fo]);
        }
#pragma unroll
        for (int q = 0; q < HL / 2; q++) {
            float2 f0 = u2f(t0[q]);
            float2 f1 = u2f(t1[q]);
            a0[2 * q] += f0.x; a0[2 * q + 1] += f0.y;
            a1[2 * q] += f1.x; a1[2 * q + 1] += f1.y;
        }
    }
    if (i < c) {
        int s = g_src[beg + i];
        uint32_t t[HL / 2];
        if (HL == 8)
            *reinterpret_cast<uint4*>(t) = *reinterpret_cast<const uint4*>(&y[(size_t)s * F + fo]);
        else
            *reinterpret_cast<uint2*>(t) = *reinterpret_cast<const uint2*>(&y[(size_t)s * F + fo]);
#pragma unroll
        for (int q = 0; q < HL / 2; q++) {
            float2 f = u2f(t[q]);
            a0[2 * q] += f.x; a0[2 * q + 1] += f.y;
        }
    }

    float inv = 1.f / (float)(c > 0 ? c : 1);
    uint32_t rw[HL / 2], ow[HL / 2];
    if (HL == 8)
        *reinterpret_cast<uint4*>(rw) = *reinterpret_cast<const uint4*>(&r[(size_t)n * F + fo]);
    else
        *reinterpret_cast<uint2*>(rw) = *reinterpret_cast<const uint2*>(&r[(size_t)n * F + fo]);
#pragma unroll
    for (int q = 0; q < HL / 2; q++) {
        float2 rr = u2f(rw[q]);
        float bx = bias[fo + 2 * q];
        float by = bias[fo + 2 * q + 1];
        float ox = (a0[2 * q] + a1[2 * q]) * inv + bx + rr.x;
        float oy = (a0[2 * q + 1] + a1[2 * q + 1]) * inv + by + rr.y;
        if (RELU) { ox = fmaxf(ox, 0.f); oy = fmaxf(oy, 0.f); }
        ow[q] = h2u(ox, oy);
    }
    if (HL == 8)
        *reinterpret_cast<uint4*>(&outp[(size_t)n * F + fo]) = *reinterpret_cast<uint4*>(ow);
    else
        *reinterpret_cast<uint2*>(&outp[(size_t)n * F + fo]) = *reinterpret_cast<uint2*>(ow);
}

// ---------------- edge decoder (CSR-grouped; 4 edges per warp iteration) -----
// 8 lanes per edge, 16 features per lane (fl*16 .. fl*16+15); 3-shuffle reduce.
__global__ void k_edge_csr(const __half* __restrict__ u_, const __half* __restrict__ v_,
                           const float* __restrict__ bd1, const float* __restrict__ wd2,
                           const float* __restrict__ bd2, float* __restrict__ out) {
    int warp = (blockIdx.x * blockDim.x + threadIdx.x) >> 5;
    int lane = threadIdx.x & 31;
    if (warp >= NN) return;
    const int n = warp;
    int beg = g_off[n];
    int c = g_cnt[n];
    if (c == 0) return;

    const int sub = lane >> 3;   // edge slot 0..3
    const int fl = lane & 7;     // feature block: cols fl*16 .. fl*16+15

    float w16[16], vb16[16];
#pragma unroll
    for (int q = 0; q < 4; q++) {
        float4 wv = *reinterpret_cast<const float4*>(&wd2[fl * 16 + q * 4]);
        w16[4 * q + 0] = wv.x; w16[4 * q + 1] = wv.y;
        w16[4 * q + 2] = wv.z; w16[4 * q + 3] = wv.w;
        float4 bv = *reinterpret_cast<const float4*>(&bd1[fl * 16 + q * 4]);
        vb16[4 * q + 0] = bv.x; vb16[4 * q + 1] = bv.y;
        vb16[4 * q + 2] = bv.z; vb16[4 * q + 3] = bv.w;
    }
    {
        uint4 vv0 = *reinterpret_cast<const uint4*>(&v_[(size_t)n * 128 + fl * 16]);
        uint4 vv1 = *reinterpret_cast<const uint4*>(&v_[(size_t)n * 128 + fl * 16 + 8]);
        uint32_t vw[8] = {vv0.x, vv0.y, vv0.z, vv0.w, vv1.x, vv1.y, vv1.z, vv1.w};
#pragma unroll
        for (int q = 0; q < 8; q++) {
            float2 f = u2f(vw[q]);
            vb16[2 * q] += f.x;
            vb16[2 * q + 1] += f.y;
        }
    }
    float b2 = *bd2;

    for (int i = 0; i < c; i += 4) {
        int j = i + sub;
        bool ok = (j < c);
        int idx = beg + (ok ? j : c - 1);
        int s = g_src[idx];
        int eid = g_eid[idx];
        uint4 uu0 = *reinterpret_cast<const uint4*>(&u_[(size_t)s * 128 + fl * 16]);
        uint4 uu1 = *reinterpret_cast<const uint4*>(&u_[(size_t)s * 128 + fl * 16 + 8]);
        uint32_t uw[8] = {uu0.x, uu0.y, uu0.z, uu0.w, uu1.x, uu1.y, uu1.z, uu1.w};
        float sum = 0.f;
#pragma unroll
        for (int q = 0; q < 8; q++) {
            float2 f = u2f(uw[q]);
            float t;
            t = fmaxf(f.x + vb16[2 * q], 0.f);     sum = fmaf(t, w16[2 * q], sum);
            t = fmaxf(f.y + vb16[2 * q + 1], 0.f); sum = fmaf(t, w16[2 * q + 1], sum);
        }
        sum += __shfl_xor_sync(0xFFFFFFFFu, sum, 4);
        sum += __shfl_xor_sync(0xFFFFFFFFu, sum, 2);
        sum += __shfl_xor_sync(0xFFFFFFFFu, sum, 1);
        if (fl == 0 && ok) out[eid] = sum + b2;
    }
}

// ---------------- launch -----------------------------------------------------
extern "C" void kernel_launch(void* const* d_in, const int* in_sizes, int n_in,
                              void* d_out, int out_size) {
    const float* x       = (const float*)d_in[0];
    const void*  ei      = (const void*)d_in[1];
    const float* W1l     = (const float*)d_in[2];
    const float* b1l     = (const float*)d_in[3];
    const float* W1r     = (const float*)d_in[4];
    const float* W2l     = (const float*)d_in[5];
    const float* b2l     = (const float*)d_in[6];
    const float* W2r     = (const float*)d_in[7];
    const float* Wd1     = (const float*)d_in[8];
    const float* bd1     = (const float*)d_in[9];
    const float* Wd2     = (const float*)d_in[10];
    const float* bd2     = (const float*)d_in[11];
    float* out           = (float*)d_out;

    __half *yh, *rh, *hh, *zh;
    cudaGetSymbolAddress((void**)&yh, g_yh);
    cudaGetSymbolAddress((void**)&rh, g_rh);
    cudaGetSymbolAddress((void**)&hh, g_hh);
    cudaGetSymbolAddress((void**)&zh, g_zh);

    const int smemK256 = (128 * (256 / 2 + 4) + 2 * 128 * 20) * 4;  // 88064
    const int smemK128 = (128 * (128 / 2 + 4) + 2 * 128 * 20) * 4;  // 55296
    cudaFuncSetAttribute(k_gemm_mma<256, 4, false>, cudaFuncAttributeMaxDynamicSharedMemorySize, smemK256);
    cudaFuncSetAttribute(k_gemm_mma<256, 2, true>,  cudaFuncAttributeMaxDynamicSharedMemorySize, smemK256);
    cudaFuncSetAttribute(k_gemm_mma<128, 2, true>,  cudaFuncAttributeMaxDynamicSharedMemorySize, smemK128);

    const int MT = (NN + 127) / 128;              // 782
    const int AGG_GRID = (NN * 32 + 255) / 256;   // warp per node

    // ---- fork: CSR build on side stream, GEMM1 on main stream ----
    cudaStream_t s2 = g_ss.s;
    cudaEventRecord(g_ss.fork, 0);
    cudaStreamWaitEvent(s2, g_ss.fork, 0);

    k_detect<<<1, 32, 0, s2>>>((const int*)ei);
    k_zero_cnt<<<(NN + 255) / 256, 256, 0, s2>>>();
    k_cvt_hist<<<(NE + 255) / 256, 256, 0, s2>>>(ei);
    k_scanA<<<SCAN_B, 256, 0, s2>>>();
    k_scanB<<<1, 512, 0, s2>>>();
    k_scanC<<<SCAN_B, 256, 0, s2>>>();
    k_scatter<<<(NE + 255) / 256, 256, 0, s2>>>();
    cudaEventRecord(g_ss.join, s2);

    // main stream: conv1 GEMMs (A = x fp32; outputs y1, r1 fp16)
    k_gemm_mma<256, 4, false><<<MT, 256, smemK256>>>(x, W1l, W1r, 256, yh, rh, NN, 256);

    // join: agg needs CSR + GEMM1
    cudaStreamWaitEvent(0, g_ss.join, 0);

    // conv1 aggregation -> h (fp16)
    k_agg_h<8, true><<<AGG_GRID, 256>>>(yh, rh, b1l, hh);

    // conv2 (A = h fp16; outputs y2, r2 fp16)
    k_gemm_mma<256, 2, true><<<MT, 256, smemK256>>>(hh, W2l, W2r, 256, yh, rh, NN, 128);
    k_agg_h<4, false><<<AGG_GRID, 256>>>(yh, rh, b2l, zh);

    // decoder precompute: u = z@A^T, v = z@B^T (A = z fp16)
    k_gemm_mma<128, 2, true><<<MT, 256, smemK128>>>(zh, Wd1, Wd1 + 128, 256, yh, rh, NN, 128);

    // per-edge (CSR-grouped): out = Wd2 . relu(u[src]+v[dst]+bd1) + bd2
    k_edge_csr<<<AGG_GRID, 256>>>(yh, rh, bd1, Wd2, bd2, out);
}

// round 12
// speedup vs baseline: 3.4283x; 1.1471x over previous
#include <cuda_runtime.h>
#include <cuda_fp16.h>
#include <cstdint>
#include <cstdio>

#define NN 100000
#define NE 1600000
#define SCAN_B 391          // ceil(NN/256)

// ---------------- scratch ----------------------------------------------------
__device__ int    g_is64;
__device__ int    g_esrc[NE];
__device__ int    g_edst[NE];
__device__ int    g_cnt[NN];
__device__ int    g_off[NN];
__device__ int    g_cur[NN];
__device__ int    g_src[NE];
__device__ int    g_eid[NE];
__device__ int    g_bsum[SCAN_B];
__device__ int    g_bpre[SCAN_B];
__device__ __half g_yh[(size_t)NN * 256];   // gathered: y1 / y2 / u
__device__ __half g_rh[(size_t)NN * 256];   // streamed: r1 / r2 / v
__device__ __half g_hh[(size_t)NN * 256];   // h
__device__ __half g_zh[(size_t)NN * 128];   // z
// fp16 weights (pre-converted once per launch)
__device__ __half g_w1[512 * 256];          // [W1l; W1r]
__device__ __half g_w2[256 * 256];          // [W2l; W2r]
__device__ __half g_wd[256 * 128];          // [Wd1_A; Wd1_B]

// ---------------- side stream for CSR/GEMM overlap ---------------------------
struct SideStream {
    cudaStream_t s = nullptr;
    cudaEvent_t fork = nullptr, join = nullptr;
    SideStream() {
        cudaStreamCreateWithFlags(&s, cudaStreamNonBlocking);
        cudaEventCreateWithFlags(&fork, cudaEventDisableTiming);
        cudaEventCreateWithFlags(&join, cudaEventDisableTiming);
    }
};
static SideStream g_ss;

// ---------------- helpers ----------------------------------------------------
__device__ __forceinline__ uint32_t h2u(float x, float y) {
    __half2 h = __floats2half2_rn(x, y);
    return *reinterpret_cast<uint32_t*>(&h);
}
__device__ __forceinline__ float2 u2f(uint32_t u) {
    __half2 h = *reinterpret_cast<__half2*>(&u);
    return __half22float2(h);
}

__device__ __forceinline__ void mma_f16(float4& c, uint32_t a0, uint32_t a1,
                                        uint32_t a2, uint32_t a3,
                                        uint32_t b0, uint32_t b1) {
    asm volatile(
        "mma.sync.aligned.m16n8k16.row.col.f32.f16.f16.f32 "
        "{%0,%1,%2,%3}, {%4,%5,%6,%7}, {%8,%9}, {%0,%1,%2,%3};"
        : "+f"(c.x), "+f"(c.y), "+f"(c.z), "+f"(c.w)
        : "r"(a0), "r"(a1), "r"(a2), "r"(a3), "r"(b0), "r"(b1));
}

__device__ __forceinline__ void ldsm_x4(uint32_t& r0, uint32_t& r1,
                                        uint32_t& r2, uint32_t& r3, uint32_t addr) {
    asm volatile("ldmatrix.sync.aligned.m8n8.x4.shared.b16 {%0,%1,%2,%3}, [%4];"
        : "=r"(r0), "=r"(r1), "=r"(r2), "=r"(r3) : "r"(addr));
}

__device__ __forceinline__ void cp_async16(uint32_t dst, const void* src, bool pred) {
    int sz = pred ? 16 : 0;
    asm volatile("cp.async.cg.shared.global [%0], [%1], 16, %2;"
        :: "r"(dst), "l"(src), "r"(sz) : "memory");
}
#define CP_COMMIT() asm volatile("cp.async.commit_group;" ::: "memory")
#define CP_WAIT(n)  asm volatile("cp.async.wait_group %0;" :: "n"(n) : "memory")

// ---------------- weight pre-conversion to fp16 ------------------------------
__global__ void k_cvtW(const float* __restrict__ W1l, const float* __restrict__ W1r,
                       const float* __restrict__ W2l, const float* __restrict__ W2r,
                       const float* __restrict__ Wd1) {
    int idx = blockIdx.x * blockDim.x + threadIdx.x;
    if (idx < 512 * 256) {
        int row = idx >> 8, col = idx & 255;
        float v = (row < 256) ? W1l[row * 256 + col] : W1r[(row - 256) * 256 + col];
        g_w1[idx] = __float2half_rn(v);
    } else if (idx < 512 * 256 + 256 * 256) {
        int j = idx - 512 * 256;
        int row = j >> 8, col = j & 255;
        float v = (row < 128) ? W2l[row * 256 + col] : W2r[(row - 128) * 256 + col];
        g_w2[j] = __float2half_rn(v);
    } else if (idx < 512 * 256 + 256 * 256 + 256 * 128) {
        int j = idx - 512 * 256 - 256 * 256;
        int row = j >> 7, col = j & 127;
        // rows 0-127: A = Wd1[:,0:128]; rows 128-255: B = Wd1[:,128:256]
        float v = Wd1[(row & 127) * 256 + (row >> 7) * 128 + col];
        g_wd[j] = __float2half_rn(v);
    }
}

// ---------------- edge index dtype detection + normalization ----------------
__global__ void k_detect(const int* __restrict__ p) {
    if (threadIdx.x == 0 && blockIdx.x == 0) {
        int odd_nonzero = 0;
        for (int i = 0; i < 1024; i++) {
            if (p[2 * i + 1] != 0) { odd_nonzero = 1; break; }
        }
        g_is64 = odd_nonzero ? 0 : 1;
    }
}

__global__ void k_cvt_hist(const void* __restrict__ ei) {
    int e = blockIdx.x * blockDim.x + threadIdx.x;
    if (e >= NE) return;
    int s, d;
    if (g_is64) {
        const long long* p = (const long long*)ei;
        s = (int)p[e];
        d = (int)p[NE + e];
    } else {
        const int* p = (const int*)ei;
        s = p[e];
        d = p[NE + e];
    }
    g_esrc[e] = s;
    g_edst[e] = d;
    atomicAdd(&g_cnt[d], 1);
}

__global__ void k_zero_cnt() {
    int i = blockIdx.x * blockDim.x + threadIdx.x;
    if (i < NN) g_cnt[i] = 0;
}

// ---------------- multi-block exclusive scan (3 phases) ----------------------
__global__ void k_scanA() {
    int i = blockIdx.x * 256 + threadIdx.x;
    int v = (i < NN) ? g_cnt[i] : 0;
    int lane = threadIdx.x & 31;
    int wid = threadIdx.x >> 5;
#pragma unroll
    for (int off = 16; off > 0; off >>= 1)
        v += __shfl_xor_sync(0xFFFFFFFFu, v, off);
    __shared__ int ws[8];
    if (lane == 0) ws[wid] = v;
    __syncthreads();
    if (threadIdx.x == 0) {
        int s = 0;
#pragma unroll
        for (int w = 0; w < 8; w++) s += ws[w];
        g_bsum[blockIdx.x] = s;
    }
}

__global__ void k_scanB() {
    __shared__ int ws[16];
    const int t = threadIdx.x;           // 512 threads
    int v = (t < SCAN_B) ? g_bsum[t] : 0;
    int lane = t & 31, wid = t >> 5;
    int x = v;
#pragma unroll
    for (int off = 1; off < 32; off <<= 1) {
        int y = __shfl_up_sync(0xFFFFFFFFu, x, off);
        if (lane >= off) x += y;
    }
    if (lane == 31) ws[wid] = x;
    __syncthreads();
    int base = 0;
    for (int w = 0; w < wid; w++) base += ws[w];
    if (t < SCAN_B) g_bpre[t] = base + x - v;   // exclusive prefix
}

__global__ void k_scanC() {
    __shared__ int ws[8];
    int i = blockIdx.x * 256 + threadIdx.x;
    int v = (i < NN) ? g_cnt[i] : 0;
    int lane = threadIdx.x & 31, wid = threadIdx.x >> 5;
    int x = v;
#pragma unroll
    for (int off = 1; off < 32; off <<= 1) {
        int y = __shfl_up_sync(0xFFFFFFFFu, x, off);
        if (lane >= off) x += y;
    }
    if (lane == 31) ws[wid] = x;
    __syncthreads();
    int base = g_bpre[blockIdx.x];
    for (int w = 0; w < wid; w++) base += ws[w];
    if (i < NN) {
        int off = base + x - v;
        g_off[i] = off;
        g_cur[i] = off;
    }
}

__global__ void k_scatter() {
    int e = blockIdx.x * blockDim.x + threadIdx.x;
    if (e < NE) {
        int pos = atomicAdd(&g_cur[g_edst[e]], 1);
        g_src[pos] = g_esrc[e];
        g_eid[pos] = e;
    }
}

// ---------------- fused dual-GEMM: mma.sync fp16 + ldmatrix + cp.async -------
// C[M, NTOT] = A[M,K] @ W[NTOT,K]^T, NTOT = NBLK*128, W fp16 stacked.
// Cl gets cols [0,NHALF), Cr gets [NHALF, NTOT). A resident in SMEM; W streamed
// in 32-col chunks through a 4-stage cp.async pipeline.
template <int K, int NBLK, bool AF16>
__global__ void __launch_bounds__(256, 2)
k_gemm_mma(const void* __restrict__ A, const __half* __restrict__ W,
           __half* __restrict__ Cl, __half* __restrict__ Cr, int M, int NHALF) {
    constexpr int SA = K / 2 + 4;   // A row stride (32-bit words)
    constexpr int SW = 20;          // W row stride (words; 16 data + 4 pad)
    constexpr int NCHK = K / 32;    // K chunks (32 cols = 2 groups of 16)
    constexpr int WSTAGE_W = 128 * SW;  // words per W stage
    extern __shared__ uint32_t smem[];
    uint32_t* Asm = smem;                        // 128 * SA
    uint32_t* Wsm = smem + 128 * SA;             // 4 * WSTAGE_W

    const int tid = threadIdx.x;
    const int wid = tid >> 5;
    const int lane = tid & 31;
    const int wm = wid >> 2;
    const int wn = wid & 3;
    const int qr = lane >> 2;
    const int tig = lane & 3;
    const int bm = blockIdx.x * 128;

    const uint32_t asm_base = (uint32_t)__cvta_generic_to_shared(Asm);
    const uint32_t wsm_base = (uint32_t)__cvta_generic_to_shared(Wsm);

    // W stage issue: 512 pieces of 16B (128 rows x 4 segs), 2 per thread
    auto issue_w = [&](const __half* Wp, int c, int s) {
#pragma unroll
        for (int r = 0; r < 2; r++) {
            int p = tid + r * 256;
            int row = p >> 2, seg = p & 3;
            cp_async16(wsm_base + (uint32_t)((s * WSTAGE_W + row * SW + seg * 4) << 2),
                       Wp + (size_t)row * K + c * 32 + seg * 8, true);
        }
    };

    // ---- A tile load ----
    if (AF16) {
        const __half* Ah = (const __half*)A;
        constexpr int SEGS = K / 8;     // 16B segs per row
#pragma unroll
        for (int r = 0; r < (128 * SEGS) / 256; r++) {
            int p = tid + r * 256;
            int row = p / SEGS, seg = p % SEGS;
            cp_async16(asm_base + (uint32_t)((row * SA + seg * 4) << 2),
                       Ah + (size_t)(bm + row) * K + seg * 8, bm + row < M);
        }
        CP_COMMIT();   // A group (oldest)
        // W prologue for nb=0: stages 0..2
        for (int s = 0; s < 3; s++) { issue_w(W, s, s); CP_COMMIT(); }
    } else {
        // W prologue first so cp.asyncs fly during the manual A convert
        for (int s = 0; s < 3; s++) { issue_w(W, s, s); CP_COMMIT(); }
        const float* Af = (const float*)A;
        for (int it = tid; it < 128 * (K / 16); it += 256) {
            int row = it / (K / 16);
            int g = it % (K / 16);
            uint32_t w[8];
#pragma unroll
            for (int q = 0; q < 4; q++) {
                float4 f = make_float4(0.f, 0.f, 0.f, 0.f);
                if (bm + row < M)
                    f = *reinterpret_cast<const float4*>(&Af[(size_t)(bm + row) * K + g * 16 + q * 4]);
                w[2 * q]     = h2u(f.x, f.y);
                w[2 * q + 1] = h2u(f.z, f.w);
            }
            uint32_t* dst = &Asm[row * SA + g * 8];
            *reinterpret_cast<uint4*>(dst)     = make_uint4(w[0], w[1], w[2], w[3]);
            *reinterpret_cast<uint4*>(dst + 4) = make_uint4(w[4], w[5], w[6], w[7]);
        }
    }

    // ldmatrix per-lane addresses
    const int rowA = (lane & 7) | (((lane >> 3) & 1) << 3);
    const int kwA = ((lane >> 4) & 1) * 4;
    uint32_t aAddr[4];
#pragma unroll
    for (int mt = 0; mt < 4; mt++)
        aAddr[mt] = asm_base + (((wm * 64 + mt * 16 + rowA) * SA + kwA) << 2);
    const int rowB = (lane & 7) + (((lane >> 4) & 1) << 3);
    const int kwB = ((lane >> 3) & 1) * 4;
    uint32_t bAddr[2];
#pragma unroll
    for (int p = 0; p < 2; p++)
        bAddr[p] = wsm_base + (((wn * 32 + p * 16 + rowB) * SW + kwB) << 2);

    for (int nb = 0; nb < NBLK; nb++) {
        const __half* Wp = W + (size_t)nb * 128 * K;
        const int colbase = (nb * 128 < NHALF) ? nb * 128 : nb * 128 - NHALF;
        __half* Cp = (nb * 128 < NHALF) ? Cl : Cr;

        if (nb > 0) {
            // prologue for this nb (previous nb's stages all consumed; barrier
            // below in iteration 0 protects buffer reuse)
            for (int s = 0; s < 3; s++) { issue_w(Wp, s, s); CP_COMMIT(); }
        }

        float4 acc[4][4];
#pragma unroll
        for (int i = 0; i < 4; i++)
#pragma unroll
            for (int j = 0; j < 4; j++) acc[i][j] = make_float4(0.f, 0.f, 0.f, 0.f);

        for (int c = 0; c < NCHK; c++) {
            CP_WAIT(2);          // stage c complete (<=2 newer W groups pending)
            __syncthreads();     // visibility + buffer-reuse guard
            if (c + 3 < NCHK) issue_w(Wp, c + 3, (c + 3) & 3);
            else if (c + 3 == NCHK && nb + 1 < NBLK) {
                // head-start: stage 0 of next nb into buffer (c+3)&3 == 0? only
                // when (c+3)&3==0; otherwise just empty-commit. Keep simple:
            }
            CP_COMMIT();         // exactly one group per iteration

            const uint32_t wbuf = (uint32_t)(((c & 3) * WSTAGE_W) << 2);
#pragma unroll
            for (int g2 = 0; g2 < 2; g2++) {
                const uint32_t koff = (uint32_t)((c * 16 + g2 * 8) << 2);
                uint32_t a[4][4];
#pragma unroll
                for (int mt = 0; mt < 4; mt++)
                    ldsm_x4(a[mt][0], a[mt][1], a[mt][2], a[mt][3], aAddr[mt] + koff);
                uint32_t b[2][4];
#pragma unroll
                for (int p = 0; p < 2; p++)
                    ldsm_x4(b[p][0], b[p][1], b[p][2], b[p][3],
                            bAddr[p] + wbuf + (uint32_t)((g2 * 8) << 2));
#pragma unroll
                for (int mt = 0; mt < 4; mt++) {
#pragma unroll
                    for (int p = 0; p < 2; p++) {
                        mma_f16(acc[mt][2 * p], a[mt][0], a[mt][1], a[mt][2], a[mt][3],
                                b[p][0], b[p][1]);
                        mma_f16(acc[mt][2 * p + 1], a[mt][0], a[mt][1], a[mt][2], a[mt][3],
                                b[p][2], b[p][3]);
                    }
                }
            }
        }

        // epilogue: fp16 outputs
#pragma unroll
        for (int mt = 0; mt < 4; mt++) {
            int row = bm + wm * 64 + mt * 16 + qr;
#pragma unroll
            for (int nt = 0; nt < 4; nt++) {
                int col = colbase + wn * 32 + nt * 8 + 2 * tig;
                if (row < M)
                    *reinterpret_cast<uint32_t*>(&Cp[(size_t)row * NHALF + col]) =
                        h2u(acc[mt][nt].x, acc[mt][nt].y);
                if (row + 8 < M)
                    *reinterpret_cast<uint32_t*>(&Cp[(size_t)(row + 8) * NHALF + col]) =
                        h2u(acc[mt][nt].z, acc[mt][nt].w);
            }
        }
        __syncthreads();
    }
}

// ---------------- aggregation + epilogue (fp16 in/out, fp32 accumulate) ------
template <int HL, bool RELU>
__global__ void k_agg_h(const __half* __restrict__ y, const __half* __restrict__ r,
                        const float* __restrict__ bias, __half* __restrict__ outp) {
    int warp = (blockIdx.x * blockDim.x + threadIdx.x) >> 5;
    int lane = threadIdx.x & 31;
    if (warp >= NN) return;
    const int n = warp;
    const int F = 32 * HL;
    int beg = g_off[n];
    int c = g_cnt[n];
    const int fo = lane * HL;

    float a0[HL], a1[HL];
#pragma unroll
    for (int q = 0; q < HL; q++) { a0[q] = 0.f; a1[q] = 0.f; }

    auto loadrow = [&](int s, uint32_t* t) {
        if (HL == 8)
            *reinterpret_cast<uint4*>(t) = *reinterpret_cast<const uint4*>(&y[(size_t)s * F + fo]);
        else
            *reinterpret_cast<uint2*>(t) = *reinterpret_cast<const uint2*>(&y[(size_t)s * F + fo]);
    };
    auto accum = [&](const uint32_t* t, float* a) {
#pragma unroll
        for (int q = 0; q < HL / 2; q++) {
            float2 f = u2f(t[q]);
            a[2 * q] += f.x; a[2 * q + 1] += f.y;
        }
    };

    int i = 0;
    for (; i + 4 <= c; i += 4) {
        int s0 = g_src[beg + i],     s1 = g_src[beg + i + 1];
        int s2 = g_src[beg + i + 2], s3 = g_src[beg + i + 3];
        uint32_t t0[HL / 2], t1[HL / 2], t2[HL / 2], t3[HL / 2];
        loadrow(s0, t0); loadrow(s1, t1); loadrow(s2, t2); loadrow(s3, t3);
        accum(t0, a0); accum(t1, a1); accum(t2, a0); accum(t3, a1);
    }
    for (; i < c; i++) {
        int s = g_src[beg + i];
        uint32_t t[HL / 2];
        loadrow(s, t);
        accum(t, a0);
    }

    float inv = 1.f / (float)(c > 0 ? c : 1);
    uint32_t rw[HL / 2], ow[HL / 2];
    if (HL == 8)
        *reinterpret_cast<uint4*>(rw) = *reinterpret_cast<const uint4*>(&r[(size_t)n * F + fo]);
    else
        *reinterpret_cast<uint2*>(rw) = *reinterpret_cast<const uint2*>(&r[(size_t)n * F + fo]);
#pragma unroll
    for (int q = 0; q < HL / 2; q++) {
        float2 rr = u2f(rw[q]);
        float bx = bias[fo + 2 * q];
        float by = bias[fo + 2 * q + 1];
        float ox = (a0[2 * q] + a1[2 * q]) * inv + bx + rr.x;
        float oy = (a0[2 * q + 1] + a1[2 * q + 1]) * inv + by + rr.y;
        if (RELU) { ox = fmaxf(ox, 0.f); oy = fmaxf(oy, 0.f); }
        ow[q] = h2u(ox, oy);
    }
    if (HL == 8)
        *reinterpret_cast<uint4*>(&outp[(size_t)n * F + fo]) = *reinterpret_cast<uint4*>(ow);
    else
        *reinterpret_cast<uint2*>(&outp[(size_t)n * F + fo]) = *reinterpret_cast<uint2*>(ow);
}

// ---------------- edge decoder (CSR-grouped; 4 edges per warp iteration) -----
__global__ void k_edge_csr(const __half* __restrict__ u_, const __half* __restrict__ v_,
                           const float* __restrict__ bd1, const float* __restrict__ wd2,
                           const float* __restrict__ bd2, float* __restrict__ out) {
    int warp = (blockIdx.x * blockDim.x + threadIdx.x) >> 5;
    int lane = threadIdx.x & 31;
    if (warp >= NN) return;
    const int n = warp;
    int beg = g_off[n];
    int c = g_cnt[n];
    if (c == 0) return;

    const int sub = lane >> 3;   // edge slot 0..3
    const int fl = lane & 7;     // feature block: cols fl*16 .. fl*16+15

    float w16[16], vb16[16];
#pragma unroll
    for (int q = 0; q < 4; q++) {
        float4 wv = *reinterpret_cast<const float4*>(&wd2[fl * 16 + q * 4]);
        w16[4 * q + 0] = wv.x; w16[4 * q + 1] = wv.y;
        w16[4 * q + 2] = wv.z; w16[4 * q + 3] = wv.w;
        float4 bv = *reinterpret_cast<const float4*>(&bd1[fl * 16 + q * 4]);
        vb16[4 * q + 0] = bv.x; vb16[4 * q + 1] = bv.y;
        vb16[4 * q + 2] = bv.z; vb16[4 * q + 3] = bv.w;
    }
    {
        uint4 vv0 = *reinterpret_cast<const uint4*>(&v_[(size_t)n * 128 + fl * 16]);
        uint4 vv1 = *reinterpret_cast<const uint4*>(&v_[(size_t)n * 128 + fl * 16 + 8]);
        uint32_t vw[8] = {vv0.x, vv0.y, vv0.z, vv0.w, vv1.x, vv1.y, vv1.z, vv1.w};
#pragma unroll
        for (int q = 0; q < 8; q++) {
            float2 f = u2f(vw[q]);
            vb16[2 * q] += f.x;
            vb16[2 * q + 1] += f.y;
        }
    }
    float b2 = *bd2;

    for (int i = 0; i < c; i += 4) {
        int j = i + sub;
        bool ok = (j < c);
        int idx = beg + (ok ? j : c - 1);
        int s = g_src[idx];
        int eid = g_eid[idx];
        uint4 uu0 = *reinterpret_cast<const uint4*>(&u_[(size_t)s * 128 + fl * 16]);
        uint4 uu1 = *reinterpret_cast<const uint4*>(&u_[(size_t)s * 128 + fl * 16 + 8]);
        uint32_t uw[8] = {uu0.x, uu0.y, uu0.z, uu0.w, uu1.x, uu1.y, uu1.z, uu1.w};
        float sum = 0.f;
#pragma unroll
        for (int q = 0; q < 8; q++) {
            float2 f = u2f(uw[q]);
            float t;
            t = fmaxf(f.x + vb16[2 * q], 0.f);     sum = fmaf(t, w16[2 * q], sum);
            t = fmaxf(f.y + vb16[2 * q + 1], 0.f); sum = fmaf(t, w16[2 * q + 1], sum);
        }
        sum += __shfl_xor_sync(0xFFFFFFFFu, sum, 4);
        sum += __shfl_xor_sync(0xFFFFFFFFu, sum, 2);
        sum += __shfl_xor_sync(0xFFFFFFFFu, sum, 1);
        if (fl == 0 && ok) out[eid] = sum + b2;
    }
}

// ---------------- launch -----------------------------------------------------
extern "C" void kernel_launch(void* const* d_in, const int* in_sizes, int n_in,
                              void* d_out, int out_size) {
    const float* x       = (const float*)d_in[0];
    const void*  ei      = (const void*)d_in[1];
    const float* W1l     = (const float*)d_in[2];
    const float* b1l     = (const float*)d_in[3];
    const float* W1r     = (const float*)d_in[4];
    const float* W2l     = (const float*)d_in[5];
    const float* b2l     = (const float*)d_in[6];
    const float* W2r     = (const float*)d_in[7];
    const float* Wd1     = (const float*)d_in[8];
    const float* bd1     = (const float*)d_in[9];
    const float* Wd2     = (const float*)d_in[10];
    const float* bd2     = (const float*)d_in[11];
    float* out           = (float*)d_out;

    __half *yh, *rh, *hh, *zh, *w1, *w2, *wd;
    cudaGetSymbolAddress((void**)&yh, g_yh);
    cudaGetSymbolAddress((void**)&rh, g_rh);
    cudaGetSymbolAddress((void**)&hh, g_hh);
    cudaGetSymbolAddress((void**)&zh, g_zh);
    cudaGetSymbolAddress((void**)&w1, g_w1);
    cudaGetSymbolAddress((void**)&w2, g_w2);
    cudaGetSymbolAddress((void**)&wd, g_wd);

    const int smemK256 = (128 * (256 / 2 + 4) + 4 * 128 * 20) * 4;  // 108544
    const int smemK128 = (128 * (128 / 2 + 4) + 4 * 128 * 20) * 4;  //  75776
    cudaFuncSetAttribute(k_gemm_mma<256, 4, false>, cudaFuncAttributeMaxDynamicSharedMemorySize, smemK256);
    cudaFuncSetAttribute(k_gemm_mma<256, 2, true>,  cudaFuncAttributeMaxDynamicSharedMemorySize, smemK256);
    cudaFuncSetAttribute(k_gemm_mma<128, 2, true>,  cudaFuncAttributeMaxDynamicSharedMemorySize, smemK128);

    const int MT = (NN + 127) / 128;              // 782
    const int AGG_GRID = (NN * 32 + 255) / 256;   // warp per node

    // ---- fork: CSR build on side stream, weights+GEMM1 on main stream ----
    cudaStream_t s2 = g_ss.s;
    cudaEventRecord(g_ss.fork, 0);
    cudaStreamWaitEvent(s2, g_ss.fork, 0);

    k_detect<<<1, 32, 0, s2>>>((const int*)ei);
    k_zero_cnt<<<(NN + 255) / 256, 256, 0, s2>>>();
    k_cvt_hist<<<(NE + 255) / 256, 256, 0, s2>>>(ei);
    k_scanA<<<SCAN_B, 256, 0, s2>>>();
    k_scanB<<<1, 512, 0, s2>>>();
    k_scanC<<<SCAN_B, 256, 0, s2>>>();
    k_scatter<<<(NE + 255) / 256, 256, 0, s2>>>();
    cudaEventRecord(g_ss.join, s2);

    // main stream: convert weights (tiny), then conv1 GEMMs
    k_cvtW<<<(512 * 256 + 256 * 256 + 256 * 128 + 255) / 256, 256>>>(W1l, W1r, W2l, W2r, Wd1);
    k_gemm_mma<256, 4, false><<<MT, 256, smemK256>>>(x, w1, yh, rh, NN, 256);

    // join: agg needs CSR + GEMM1
    cudaStreamWaitEvent(0, g_ss.join, 0);

    // conv1 aggregation -> h (fp16)
    k_agg_h<8, true><<<AGG_GRID, 256>>>(yh, rh, b1l, hh);

    // conv2 (A = h fp16)
    k_gemm_mma<256, 2, true><<<MT, 256, smemK256>>>(hh, w2, yh, rh, NN, 128);
    k_agg_h<4, false><<<AGG_GRID, 256>>>(yh, rh, b2l, zh);

    // decoder precompute: u = z@A^T, v = z@B^T (A = z fp16)
    k_gemm_mma<128, 2, true><<<MT, 256, smemK128>>>(zh, wd, yh, rh, NN, 128);

    // per-edge (CSR-grouped): out = Wd2 . relu(u[src]+v[dst]+bd1) + bd2
    k_edge_csr<<<AGG_GRID, 256>>>(yh, rh, bd1, Wd2, bd2, out);
}

// round 13
// speedup vs baseline: 3.5282x; 1.0291x over previous
#include <cuda_runtime.h>
#include <cuda_fp16.h>
#include <cstdint>
#include <cstdio>

#define NN 100000
#define NE 1600000
#define SCAN_B 391          // ceil(NN/256)

// ---------------- scratch ----------------------------------------------------
__device__ int    g_is64;
__device__ int    g_esrc[NE];
__device__ int    g_edst[NE];
__device__ int    g_cnt[NN];
__device__ int    g_off[NN];
__device__ int    g_cur[NN];
__device__ int    g_src[NE];
__device__ int    g_eid[NE];
__device__ int    g_bsum[SCAN_B];
__device__ int    g_bpre[SCAN_B];
__device__ __half g_yh[(size_t)NN * 256];   // gathered: y1 / y2 / u  (keep in L2)
__device__ __half g_rh[(size_t)NN * 256];   // streamed: r1 / r2 / v  (evict-first)
__device__ __half g_hh[(size_t)NN * 256];   // h
__device__ __half g_zh[(size_t)NN * 128];   // z
// fp16 weights (pre-converted once per launch)
__device__ __half g_w1[512 * 256];          // [W1l; W1r]
__device__ __half g_w2[256 * 256];          // [W2l; W2r]
__device__ __half g_wd[256 * 128];          // [Wd1_A; Wd1_B]

// ---------------- side stream for CSR/GEMM overlap ---------------------------
struct SideStream {
    cudaStream_t s = nullptr;
    cudaEvent_t fork = nullptr, join = nullptr;
    SideStream() {
        cudaStreamCreateWithFlags(&s, cudaStreamNonBlocking);
        cudaEventCreateWithFlags(&fork, cudaEventDisableTiming);
        cudaEventCreateWithFlags(&join, cudaEventDisableTiming);
    }
};
static SideStream g_ss;

// ---------------- helpers ----------------------------------------------------
__device__ __forceinline__ uint32_t h2u(float x, float y) {
    __half2 h = __floats2half2_rn(x, y);
    return *reinterpret_cast<uint32_t*>(&h);
}
__device__ __forceinline__ float2 u2f(uint32_t u) {
    __half2 h = *reinterpret_cast<__half2*>(&u);
    return __half22float2(h);
}

__device__ __forceinline__ void mma_f16(float4& c, uint32_t a0, uint32_t a1,
                                        uint32_t a2, uint32_t a3,
                                        uint32_t b0, uint32_t b1) {
    asm volatile(
        "mma.sync.aligned.m16n8k16.row.col.f32.f16.f16.f32 "
        "{%0,%1,%2,%3}, {%4,%5,%6,%7}, {%8,%9}, {%0,%1,%2,%3};"
        : "+f"(c.x), "+f"(c.y), "+f"(c.z), "+f"(c.w)
        : "r"(a0), "r"(a1), "r"(a2), "r"(a3), "r"(b0), "r"(b1));
}

__device__ __forceinline__ void ldsm_x4(uint32_t& r0, uint32_t& r1,
                                        uint32_t& r2, uint32_t& r3, uint32_t addr) {
    asm volatile("ldmatrix.sync.aligned.m8n8.x4.shared.b16 {%0,%1,%2,%3}, [%4];"
        : "=r"(r0), "=r"(r1), "=r"(r2), "=r"(r3) : "r"(addr));
}

__device__ __forceinline__ void cp_async16(uint32_t dst, const void* src, bool pred) {
    int sz = pred ? 16 : 0;
    asm volatile("cp.async.cg.shared.global [%0], [%1], 16, %2;"
        :: "r"(dst), "l"(src), "r"(sz) : "memory");
}
#define CP_COMMIT() asm volatile("cp.async.commit_group;" ::: "memory")
#define CP_WAIT(n)  asm volatile("cp.async.wait_group %0;" :: "n"(n) : "memory")

// ---------------- weight pre-conversion to fp16 ------------------------------
__global__ void k_cvtW(const float* __restrict__ W1l, const float* __restrict__ W1r,
                       const float* __restrict__ W2l, const float* __restrict__ W2r,
                       const float* __restrict__ Wd1) {
    int idx = blockIdx.x * blockDim.x + threadIdx.x;
    if (idx < 512 * 256) {
        int row = idx >> 8, col = idx & 255;
        float v = (row < 256) ? W1l[row * 256 + col] : W1r[(row - 256) * 256 + col];
        g_w1[idx] = __float2half_rn(v);
    } else if (idx < 512 * 256 + 256 * 256) {
        int j = idx - 512 * 256;
        int row = j >> 8, col = j & 255;
        float v = (row < 128) ? W2l[row * 256 + col] : W2r[(row - 128) * 256 + col];
        g_w2[j] = __float2half_rn(v);
    } else if (idx < 512 * 256 + 256 * 256 + 256 * 128) {
        int j = idx - 512 * 256 - 256 * 256;
        int row = j >> 7, col = j & 127;
        float v = Wd1[(row & 127) * 256 + (row >> 7) * 128 + col];
        g_wd[j] = __float2half_rn(v);
    }
}

// ---------------- edge index dtype detection + normalization ----------------
__global__ void k_detect(const int* __restrict__ p) {
    if (threadIdx.x == 0 && blockIdx.x == 0) {
        int odd_nonzero = 0;
        for (int i = 0; i < 1024; i++) {
            if (p[2 * i + 1] != 0) { odd_nonzero = 1; break; }
        }
        g_is64 = odd_nonzero ? 0 : 1;
    }
}

__global__ void k_cvt_hist(const void* __restrict__ ei) {
    int e = blockIdx.x * blockDim.x + threadIdx.x;
    if (e >= NE) return;
    int s, d;
    if (g_is64) {
        const long long* p = (const long long*)ei;
        s = (int)p[e];
        d = (int)p[NE + e];
    } else {
        const int* p = (const int*)ei;
        s = p[e];
        d = p[NE + e];
    }
    g_esrc[e] = s;
    g_edst[e] = d;
    atomicAdd(&g_cnt[d], 1);
}

__global__ void k_zero_cnt() {
    int i = blockIdx.x * blockDim.x + threadIdx.x;
    if (i < NN) g_cnt[i] = 0;
}

// ---------------- multi-block exclusive scan (3 phases) ----------------------
__global__ void k_scanA() {
    int i = blockIdx.x * 256 + threadIdx.x;
    int v = (i < NN) ? g_cnt[i] : 0;
    int lane = threadIdx.x & 31;
    int wid = threadIdx.x >> 5;
#pragma unroll
    for (int off = 16; off > 0; off >>= 1)
        v += __shfl_xor_sync(0xFFFFFFFFu, v, off);
    __shared__ int ws[8];
    if (lane == 0) ws[wid] = v;
    __syncthreads();
    if (threadIdx.x == 0) {
        int s = 0;
#pragma unroll
        for (int w = 0; w < 8; w++) s += ws[w];
        g_bsum[blockIdx.x] = s;
    }
}

__global__ void k_scanB() {
    __shared__ int ws[16];
    const int t = threadIdx.x;           // 512 threads
    int v = (t < SCAN_B) ? g_bsum[t] : 0;
    int lane = t & 31, wid = t >> 5;
    int x = v;
#pragma unroll
    for (int off = 1; off < 32; off <<= 1) {
        int y = __shfl_up_sync(0xFFFFFFFFu, x, off);
        if (lane >= off) x += y;
    }
    if (lane == 31) ws[wid] = x;
    __syncthreads();
    int base = 0;
    for (int w = 0; w < wid; w++) base += ws[w];
    if (t < SCAN_B) g_bpre[t] = base + x - v;   // exclusive prefix
}

__global__ void k_scanC() {
    __shared__ int ws[8];
    int i = blockIdx.x * 256 + threadIdx.x;
    int v = (i < NN) ? g_cnt[i] : 0;
    int lane = threadIdx.x & 31, wid = threadIdx.x >> 5;
    int x = v;
#pragma unroll
    for (int off = 1; off < 32; off <<= 1) {
        int y = __shfl_up_sync(0xFFFFFFFFu, x, off);
        if (lane >= off) x += y;
    }
    if (lane == 31) ws[wid] = x;
    __syncthreads();
    int base = g_bpre[blockIdx.x];
    for (int w = 0; w < wid; w++) base += ws[w];
    if (i < NN) {
        int off = base + x - v;
        g_off[i] = off;
        g_cur[i] = off;
    }
}

__global__ void k_scatter() {
    int e = blockIdx.x * blockDim.x + threadIdx.x;
    if (e < NE) {
        int pos = atomicAdd(&g_cur[g_edst[e]], 1);
        g_src[pos] = g_esrc[e];
        g_eid[pos] = e;
    }
}

// ---------------- fused dual-GEMM: mma.sync fp16 + ldmatrix + cp.async -------
// C[M, NTOT] = A[M,K] @ W[NTOT,K]^T, NTOT = NBLK*128, W fp16 stacked.
// Cl gets cols [0,NHALF) [gathered next -> keep in L2],
// Cr gets [NHALF, NTOT)  [streamed next -> evict-first stores].
template <int K, int NBLK, bool AF16>
__global__ void __launch_bounds__(256, 2)
k_gemm_mma(const void* __restrict__ A, const __half* __restrict__ W,
           __half* __restrict__ Cl, __half* __restrict__ Cr, int M, int NHALF) {
    constexpr int SA = K / 2 + 4;   // A row stride (32-bit words)
    constexpr int SW = 20;          // W row stride (words; 16 data + 4 pad)
    constexpr int NCHK = K / 32;    // K chunks
    constexpr int WSTAGE_W = 128 * SW;
    extern __shared__ uint32_t smem[];
    uint32_t* Asm = smem;
    uint32_t* Wsm = smem + 128 * SA;

    const int tid = threadIdx.x;
    const int wid = tid >> 5;
    const int lane = tid & 31;
    const int wm = wid >> 2;
    const int wn = wid & 3;
    const int qr = lane >> 2;
    const int tig = lane & 3;
    const int bm = blockIdx.x * 128;

    const uint32_t asm_base = (uint32_t)__cvta_generic_to_shared(Asm);
    const uint32_t wsm_base = (uint32_t)__cvta_generic_to_shared(Wsm);

    auto issue_w = [&](const __half* Wp, int c, int s) {
#pragma unroll
        for (int r = 0; r < 2; r++) {
            int p = tid + r * 256;
            int row = p >> 2, seg = p & 3;
            cp_async16(wsm_base + (uint32_t)((s * WSTAGE_W + row * SW + seg * 4) << 2),
                       Wp + (size_t)row * K + c * 32 + seg * 8, true);
        }
    };

    // ---- A tile load ----
    if (AF16) {
        const __half* Ah = (const __half*)A;
        constexpr int SEGS = K / 8;
#pragma unroll
        for (int r = 0; r < (128 * SEGS) / 256; r++) {
            int p = tid + r * 256;
            int row = p / SEGS, seg = p % SEGS;
            cp_async16(asm_base + (uint32_t)((row * SA + seg * 4) << 2),
                       Ah + (size_t)(bm + row) * K + seg * 8, bm + row < M);
        }
        CP_COMMIT();
        for (int s = 0; s < 3; s++) { issue_w(W, s, s); CP_COMMIT(); }
    } else {
        for (int s = 0; s < 3; s++) { issue_w(W, s, s); CP_COMMIT(); }
        const float* Af = (const float*)A;
        for (int it = tid; it < 128 * (K / 16); it += 256) {
            int row = it / (K / 16);
            int g = it % (K / 16);
            uint32_t w[8];
#pragma unroll
            for (int q = 0; q < 4; q++) {
                float4 f = make_float4(0.f, 0.f, 0.f, 0.f);
                if (bm + row < M)
                    f = __ldcs(reinterpret_cast<const float4*>(
                        &Af[(size_t)(bm + row) * K + g * 16 + q * 4]));
                w[2 * q]     = h2u(f.x, f.y);
                w[2 * q + 1] = h2u(f.z, f.w);
            }
            uint32_t* dst = &Asm[row * SA + g * 8];
            *reinterpret_cast<uint4*>(dst)     = make_uint4(w[0], w[1], w[2], w[3]);
            *reinterpret_cast<uint4*>(dst + 4) = make_uint4(w[4], w[5], w[6], w[7]);
        }
    }

    // ldmatrix per-lane addresses
    const int rowA = (lane & 7) | (((lane >> 3) & 1) << 3);
    const int kwA = ((lane >> 4) & 1) * 4;
    uint32_t aAddr[4];
#pragma unroll
    for (int mt = 0; mt < 4; mt++)
        aAddr[mt] = asm_base + (((wm * 64 + mt * 16 + rowA) * SA + kwA) << 2);
    const int rowB = (lane & 7) + (((lane >> 4) & 1) << 3);
    const int kwB = ((lane >> 3) & 1) * 4;
    uint32_t bAddr[2];
#pragma unroll
    for (int p = 0; p < 2; p++)
        bAddr[p] = wsm_base + (((wn * 32 + p * 16 + rowB) * SW + kwB) << 2);

    for (int nb = 0; nb < NBLK; nb++) {
        const __half* Wp = W + (size_t)nb * 128 * K;
        const bool isL = (nb * 128 < NHALF);
        const int colbase = isL ? nb * 128 : nb * 128 - NHALF;
        __half* Cp = isL ? Cl : Cr;

        if (nb > 0) {
            for (int s = 0; s < 3; s++) { issue_w(Wp, s, s); CP_COMMIT(); }
        }

        float4 acc[4][4];
#pragma unroll
        for (int i = 0; i < 4; i++)
#pragma unroll
            for (int j = 0; j < 4; j++) acc[i][j] = make_float4(0.f, 0.f, 0.f, 0.f);

        for (int c = 0; c < NCHK; c++) {
            CP_WAIT(2);
            __syncthreads();
            if (c + 3 < NCHK) issue_w(Wp, c + 3, (c + 3) & 3);
            CP_COMMIT();

            const uint32_t wbuf = (uint32_t)(((c & 3) * WSTAGE_W) << 2);
#pragma unroll
            for (int g2 = 0; g2 < 2; g2++) {
                const uint32_t koff = (uint32_t)((c * 16 + g2 * 8) << 2);
                uint32_t a[4][4];
#pragma unroll
                for (int mt = 0; mt < 4; mt++)
                    ldsm_x4(a[mt][0], a[mt][1], a[mt][2], a[mt][3], aAddr[mt] + koff);
                uint32_t b[2][4];
#pragma unroll
                for (int p = 0; p < 2; p++)
                    ldsm_x4(b[p][0], b[p][1], b[p][2], b[p][3],
                            bAddr[p] + wbuf + (uint32_t)((g2 * 8) << 2));
#pragma unroll
                for (int mt = 0; mt < 4; mt++) {
#pragma unroll
                    for (int p = 0; p < 2; p++) {
                        mma_f16(acc[mt][2 * p], a[mt][0], a[mt][1], a[mt][2], a[mt][3],
                                b[p][0], b[p][1]);
                        mma_f16(acc[mt][2 * p + 1], a[mt][0], a[mt][1], a[mt][2], a[mt][3],
                                b[p][2], b[p][3]);
                    }
                }
            }
        }

        // epilogue: Cl normal (gathered next), Cr evict-first (streamed next)
#pragma unroll
        for (int mt = 0; mt < 4; mt++) {
            int row = bm + wm * 64 + mt * 16 + qr;
#pragma unroll
            for (int nt = 0; nt < 4; nt++) {
                int col = colbase + wn * 32 + nt * 8 + 2 * tig;
                uint32_t lo = h2u(acc[mt][nt].x, acc[mt][nt].y);
                uint32_t hi = h2u(acc[mt][nt].z, acc[mt][nt].w);
                if (isL) {
                    if (row < M)
                        *reinterpret_cast<uint32_t*>(&Cp[(size_t)row * NHALF + col]) = lo;
                    if (row + 8 < M)
                        *reinterpret_cast<uint32_t*>(&Cp[(size_t)(row + 8) * NHALF + col]) = hi;
                } else {
                    if (row < M)
                        __stcs(reinterpret_cast<unsigned int*>(&Cp[(size_t)row * NHALF + col]), lo);
                    if (row + 8 < M)
                        __stcs(reinterpret_cast<unsigned int*>(&Cp[(size_t)(row + 8) * NHALF + col]), hi);
                }
            }
        }
        __syncthreads();
    }
}

// ---------------- aggregation + epilogue (fp16 in/out, fp32 accumulate) ------
// Gather y (keep L2); stream r with __ldcs; write out with __stcs.
template <int HL, bool RELU>
__global__ void k_agg_h(const __half* __restrict__ y, const __half* __restrict__ r,
                        const float* __restrict__ bias, __half* __restrict__ outp) {
    int warp = (blockIdx.x * blockDim.x + threadIdx.x) >> 5;
    int lane = threadIdx.x & 31;
    if (warp >= NN) return;
    const int n = warp;
    const int F = 32 * HL;
    int beg = g_off[n];
    int c = g_cnt[n];
    const int fo = lane * HL;

    float a0[HL], a1[HL];
#pragma unroll
    for (int q = 0; q < HL; q++) { a0[q] = 0.f; a1[q] = 0.f; }

    auto loadrow = [&](int s, uint32_t* t) {
        if (HL == 8)
            *reinterpret_cast<uint4*>(t) = *reinterpret_cast<const uint4*>(&y[(size_t)s * F + fo]);
        else
            *reinterpret_cast<uint2*>(t) = *reinterpret_cast<const uint2*>(&y[(size_t)s * F + fo]);
    };
    auto accum = [&](const uint32_t* t, float* a) {
#pragma unroll
        for (int q = 0; q < HL / 2; q++) {
            float2 f = u2f(t[q]);
            a[2 * q] += f.x; a[2 * q + 1] += f.y;
        }
    };

    int i = 0;
    for (; i + 4 <= c; i += 4) {
        int s0 = g_src[beg + i],     s1 = g_src[beg + i + 1];
        int s2 = g_src[beg + i + 2], s3 = g_src[beg + i + 3];
        uint32_t t0[HL / 2], t1[HL / 2], t2[HL / 2], t3[HL / 2];
        loadrow(s0, t0); loadrow(s1, t1); loadrow(s2, t2); loadrow(s3, t3);
        accum(t0, a0); accum(t1, a1); accum(t2, a0); accum(t3, a1);
    }
    for (; i < c; i++) {
        int s = g_src[beg + i];
        uint32_t t[HL / 2];
        loadrow(s, t);
        accum(t, a0);
    }

    float inv = 1.f / (float)(c > 0 ? c : 1);
    uint32_t rw[HL / 2], ow[HL / 2];
    if (HL == 8)
        *reinterpret_cast<uint4*>(rw) = __ldcs(reinterpret_cast<const uint4*>(&r[(size_t)n * F + fo]));
    else
        *reinterpret_cast<uint2*>(rw) = __ldcs(reinterpret_cast<const uint2*>(&r[(size_t)n * F + fo]));
#pragma unroll
    for (int q = 0; q < HL / 2; q++) {
        float2 rr = u2f(rw[q]);
        float bx = bias[fo + 2 * q];
        float by = bias[fo + 2 * q + 1];
        float ox = (a0[2 * q] + a1[2 * q]) * inv + bx + rr.x;
        float oy = (a0[2 * q + 1] + a1[2 * q + 1]) * inv + by + rr.y;
        if (RELU) { ox = fmaxf(ox, 0.f); oy = fmaxf(oy, 0.f); }
        ow[q] = h2u(ox, oy);
    }
    if (HL == 8)
        __stcs(reinterpret_cast<uint4*>(&outp[(size_t)n * F + fo]), *reinterpret_cast<uint4*>(ow));
    else
        __stcs(reinterpret_cast<uint2*>(&outp[(size_t)n * F + fo]), *reinterpret_cast<uint2*>(ow));
}

// ---------------- edge decoder (CSR-grouped; 4 edges per warp iteration) -----
__global__ void k_edge_csr(const __half* __restrict__ u_, const __half* __restrict__ v_,
                           const float* __restrict__ bd1, const float* __restrict__ wd2,
                           const float* __restrict__ bd2, float* __restrict__ out) {
    int warp = (blockIdx.x * blockDim.x + threadIdx.x) >> 5;
    int lane = threadIdx.x & 31;
    if (warp >= NN) return;
    const int n = warp;
    int beg = g_off[n];
    int c = g_cnt[n];
    if (c == 0) return;

    const int sub = lane >> 3;   // edge slot 0..3
    const int fl = lane & 7;     // feature block: cols fl*16 .. fl*16+15

    float w16[16], vb16[16];
#pragma unroll
    for (int q = 0; q < 4; q++) {
        float4 wv = *reinterpret_cast<const float4*>(&wd2[fl * 16 + q * 4]);
        w16[4 * q + 0] = wv.x; w16[4 * q + 1] = wv.y;
        w16[4 * q + 2] = wv.z; w16[4 * q + 3] = wv.w;
        float4 bv = *reinterpret_cast<const float4*>(&bd1[fl * 16 + q * 4]);
        vb16[4 * q + 0] = bv.x; vb16[4 * q + 1] = bv.y;
        vb16[4 * q + 2] = bv.z; vb16[4 * q + 3] = bv.w;
    }
    {
        uint4 vv0 = __ldcs(reinterpret_cast<const uint4*>(&v_[(size_t)n * 128 + fl * 16]));
        uint4 vv1 = __ldcs(reinterpret_cast<const uint4*>(&v_[(size_t)n * 128 + fl * 16 + 8]));
        uint32_t vw[8] = {vv0.x, vv0.y, vv0.z, vv0.w, vv1.x, vv1.y, vv1.z, vv1.w};
#pragma unroll
        for (int q = 0; q < 8; q++) {
            float2 f = u2f(vw[q]);
            vb16[2 * q] += f.x;
            vb16[2 * q + 1] += f.y;
        }
    }
    float b2 = *bd2;

    for (int i = 0; i < c; i += 4) {
        int j = i + sub;
        bool ok = (j < c);
        int idx = beg + (ok ? j : c - 1);
        int s = g_src[idx];
        int eid = g_eid[idx];
        uint4 uu0 = *reinterpret_cast<const uint4*>(&u_[(size_t)s * 128 + fl * 16]);
        uint4 uu1 = *reinterpret_cast<const uint4*>(&u_[(size_t)s * 128 + fl * 16 + 8]);
        uint32_t uw[8] = {uu0.x, uu0.y, uu0.z, uu0.w, uu1.x, uu1.y, uu1.z, uu1.w};
        float sum = 0.f;
#pragma unroll
        for (int q = 0; q < 8; q++) {
            float2 f = u2f(uw[q]);
            float t;
            t = fmaxf(f.x + vb16[2 * q], 0.f);     sum = fmaf(t, w16[2 * q], sum);
            t = fmaxf(f.y + vb16[2 * q + 1], 0.f); sum = fmaf(t, w16[2 * q + 1], sum);
        }
        sum += __shfl_xor_sync(0xFFFFFFFFu, sum, 4);
        sum += __shfl_xor_sync(0xFFFFFFFFu, sum, 2);
        sum += __shfl_xor_sync(0xFFFFFFFFu, sum, 1);
        if (fl == 0 && ok) __stcs(&out[eid], sum + b2);
    }
}

// ---------------- launch -----------------------------------------------------
extern "C" void kernel_launch(void* const* d_in, const int* in_sizes, int n_in,
                              void* d_out, int out_size) {
    const float* x       = (const float*)d_in[0];
    const void*  ei      = (const void*)d_in[1];
    const float* W1l     = (const float*)d_in[2];
    const float* b1l     = (const float*)d_in[3];
    const float* W1r     = (const float*)d_in[4];
    const float* W2l     = (const float*)d_in[5];
    const float* b2l     = (const float*)d_in[6];
    const float* W2r     = (const float*)d_in[7];
    const float* Wd1     = (const float*)d_in[8];
    const float* bd1     = (const float*)d_in[9];
    const float* Wd2     = (const float*)d_in[10];
    const float* bd2     = (const float*)d_in[11];
    float* out           = (float*)d_out;

    __half *yh, *rh, *hh, *zh, *w1, *w2, *wd;
    cudaGetSymbolAddress((void**)&yh, g_yh);
    cudaGetSymbolAddress((void**)&rh, g_rh);
    cudaGetSymbolAddress((void**)&hh, g_hh);
    cudaGetSymbolAddress((void**)&zh, g_zh);
    cudaGetSymbolAddress((void**)&w1, g_w1);
    cudaGetSymbolAddress((void**)&w2, g_w2);
    cudaGetSymbolAddress((void**)&wd, g_wd);

    const int smemK256 = (128 * (256 / 2 + 4) + 4 * 128 * 20) * 4;  // 108544
    const int smemK128 = (128 * (128 / 2 + 4) + 4 * 128 * 20) * 4;  //  75776
    cudaFuncSetAttribute(k_gemm_mma<256, 4, false>, cudaFuncAttributeMaxDynamicSharedMemorySize, smemK256);
    cudaFuncSetAttribute(k_gemm_mma<256, 2, true>,  cudaFuncAttributeMaxDynamicSharedMemorySize, smemK256);
    cudaFuncSetAttribute(k_gemm_mma<128, 2, true>,  cudaFuncAttributeMaxDynamicSharedMemorySize, smemK128);

    const int MT = (NN + 127) / 128;              // 782
    const int AGG_GRID = (NN * 32 + 255) / 256;   // warp per node

    // ---- fork: CSR build on side stream, weights+GEMM1 on main stream ----
    cudaStream_t s2 = g_ss.s;
    cudaEventRecord(g_ss.fork, 0);
    cudaStreamWaitEvent(s2, g_ss.fork, 0);

    k_detect<<<1, 32, 0, s2>>>((const int*)ei);
    k_zero_cnt<<<(NN + 255) / 256, 256, 0, s2>>>();
    k_cvt_hist<<<(NE + 255) / 256, 256, 0, s2>>>(ei);
    k_scanA<<<SCAN_B, 256, 0, s2>>>();
    k_scanB<<<1, 512, 0, s2>>>();
    k_scanC<<<SCAN_B, 256, 0, s2>>>();
    k_scatter<<<(NE + 255) / 256, 256, 0, s2>>>();
    cudaEventRecord(g_ss.join, s2);

    // main stream: convert weights (tiny), then conv1 GEMMs
    k_cvtW<<<(512 * 256 + 256 * 256 + 256 * 128 + 255) / 256, 256>>>(W1l, W1r, W2l, W2r, Wd1);
    k_gemm_mma<256, 4, false><<<MT, 256, smemK256>>>(x, w1, yh, rh, NN, 256);

    // join: agg needs CSR + GEMM1
    cudaStreamWaitEvent(0, g_ss.join, 0);

    // conv1 aggregation -> h (fp16)
    k_agg_h<8, true><<<AGG_GRID, 256>>>(yh, rh, b1l, hh);

    // conv2 (A = h fp16)
    k_gemm_mma<256, 2, true><<<MT, 256, smemK256>>>(hh, w2, yh, rh, NN, 128);
    k_agg_h<4, false><<<AGG_GRID, 256>>>(yh, rh, b2l, zh);

    // decoder precompute: u = z@A^T, v = z@B^T (A = z fp16)
    k_gemm_mma<128, 2, true><<<MT, 256, smemK128>>>(zh, wd, yh, rh, NN, 128);

    // per-edge (CSR-grouped): out = Wd2 . relu(u[src]+v[dst]+bd1) + bd2
    k_edge_csr<<<AGG_GRID, 256>>>(yh, rh, bd1, Wd2, bd2, out);
}